// round 7
// baseline (speedup 1.0000x reference)
#include <cuda_runtime.h>
#include <math.h>

// Problem dims
#define BB   4
#define NN   2048
#define DD   513
#define HH   8
#define DH   64
#define ROWS (BB*NN)       // 8192

#define INV_K   10.0f
#define K_CURV  0.1f
#define EPS_F   1e-9f
#define SCALE_F 0.125f     // 1/sqrt(64)

// ---------------------------------------------------------------------------
// Packed fp32x2 helpers (sm_100+ PTX fma.rn.f32x2 -> FFMA2)
// ---------------------------------------------------------------------------
typedef unsigned long long u64;
__device__ __forceinline__ u64 pk2(float x, float y) {
    u64 r; asm("mov.b64 %0, {%1,%2};" : "=l"(r) : "f"(x), "f"(y)); return r;
}
__device__ __forceinline__ u64 bc2(float x) {
    u64 r; asm("mov.b64 %0, {%1,%1};" : "=l"(r) : "f"(x)); return r;
}
__device__ __forceinline__ void fma2(u64 &d, u64 a, u64 b) {
    asm("fma.rn.f32x2 %0, %1, %2, %0;" : "+l"(d) : "l"(a), "l"(b));
}
__device__ __forceinline__ u64 fma2v(u64 a, u64 b, u64 c) {
    u64 d; asm("fma.rn.f32x2 %0, %1, %2, %3;" : "=l"(d) : "l"(a), "l"(b), "l"(c)); return d;
}
__device__ __forceinline__ float2 up2(u64 v) {
    float lo, hi; asm("mov.b64 {%0,%1}, %2;" : "=f"(lo), "=f"(hi) : "l"(v));
    return make_float2(lo, hi);
}

// Scratch (device globals: allocation-free per harness rules)
__device__ float g_qs[BB*HH*NN*DH];   // q space
__device__ float g_qt[BB*HH*NN];      // q time, NEGATED
__device__ float g_ks[BB*HH*NN*DH];
__device__ float g_kt[BB*HH*NN];
__device__ float g_vs[BB*HH*NN*DH];
__device__ float g_vt[BB*HH*NN];
__device__ float g_cat[ROWS*DD];      // [B*N][513]

// ---------------------------------------------------------------------------
// Kernel 1: QKV projection GEMM, double-buffered, 128x128 tile, 8x8 micro.
// ---------------------------------------------------------------------------
__global__ __launch_bounds__(256, 2) void proj_kernel(
    const float* __restrict__ x,
    const float* __restrict__ Wq, const float* __restrict__ bq,
    const float* __restrict__ Wk, const float* __restrict__ bk,
    const float* __restrict__ Wv, const float* __restrict__ bv)
{
    __shared__ float As[2][16][132];   // [buf][kk][row]
    __shared__ float Bs[2][16][132];   // [buf][kk][col]

    const int tid = threadIdx.x;
    const int ty = tid >> 4;
    const int tx = tid & 15;
    const int row0 = blockIdx.x * 128;
    const int gy = blockIdx.y;
    const int mat = gy >> 2;        // 0=q 1=k 2=v
    const int h0 = (gy & 3) * 2;

    const float* W    = (mat == 0) ? Wq : ((mat == 1) ? Wk : Wv);
    const float* bias = (mat == 0) ? bq : ((mat == 1) ? bk : bv);
    float* outs       = (mat == 0) ? g_qs : ((mat == 1) ? g_ks : g_vs);
    float* outt       = (mat == 0) ? g_qt : ((mat == 1) ? g_kt : g_vt);

    u64 acc2[8][4] = {};

    // prologue: stage k0=0 into buffer 0
    #pragma unroll
    for (int it = 0; it < 8; it++) {
        int lin = tid + it * 256;
        int r = lin >> 4, kk = lin & 15;
        As[0][kk][r] = (kk < DD) ? x[(size_t)(row0 + r) * DD + kk] : 0.0f;
    }
    #pragma unroll
    for (int it = 0; it < 2; it++) {
        int lin = tid + it * 256;
        int kk = lin >> 5, c4 = lin & 31;
        int c = c4 * 4;
        int h = h0 + (c >> 6), m = c & 63;
        float4 v = make_float4(0.f, 0.f, 0.f, 0.f);
        if (kk < DD) v = *(const float4*)&W[((size_t)h * DD + kk) * DH + m];
        *(float4*)&Bs[0][kk][c] = v;
    }
    __syncthreads();

    int buf = 0;
    for (int k0 = 0; k0 < DD; k0 += 16, buf ^= 1) {
        const bool more = (k0 + 16) < DD;
        float ra[8];
        float4 rb[2];
        if (more) {
            #pragma unroll
            for (int it = 0; it < 8; it++) {
                int lin = tid + it * 256;
                int r = lin >> 4, kk = lin & 15;
                int kg = k0 + 16 + kk;
                ra[it] = (kg < DD) ? x[(size_t)(row0 + r) * DD + kg] : 0.0f;
            }
            #pragma unroll
            for (int it = 0; it < 2; it++) {
                int lin = tid + it * 256;
                int kk = lin >> 5, c4 = lin & 31;
                int kg = k0 + 16 + kk;
                int c = c4 * 4;
                int h = h0 + (c >> 6), m = c & 63;
                float4 v = make_float4(0.f, 0.f, 0.f, 0.f);
                if (kg < DD) v = *(const float4*)&W[((size_t)h * DD + kg) * DH + m];
                rb[it] = v;
            }
        }
        #pragma unroll
        for (int kk = 0; kk < 16; kk++) {
            float4 a0 = *(const float4*)&As[buf][kk][ty * 8];
            float4 a1 = *(const float4*)&As[buf][kk][ty * 8 + 4];
            float4 b0 = *(const float4*)&Bs[buf][kk][tx * 8];
            float4 b1 = *(const float4*)&Bs[buf][kk][tx * 8 + 4];
            u64 bp[4] = {pk2(b0.x, b0.y), pk2(b0.z, b0.w),
                         pk2(b1.x, b1.y), pk2(b1.z, b1.w)};
            float av[8] = {a0.x, a0.y, a0.z, a0.w, a1.x, a1.y, a1.z, a1.w};
            #pragma unroll
            for (int i = 0; i < 8; i++) {
                u64 ab = bc2(av[i]);
                #pragma unroll
                for (int p = 0; p < 4; p++) fma2(acc2[i][p], ab, bp[p]);
            }
        }
        if (more) {
            #pragma unroll
            for (int it = 0; it < 8; it++) {
                int lin = tid + it * 256;
                int r = lin >> 4, kk = lin & 15;
                As[buf ^ 1][kk][r] = ra[it];
            }
            #pragma unroll
            for (int it = 0; it < 2; it++) {
                int lin = tid + it * 256;
                int kk = lin >> 5, c4 = lin & 31;
                *(float4*)&Bs[buf ^ 1][kk][c4 * 4] = rb[it];
            }
        }
        __syncthreads();
    }

    // Epilogue: bias, per-head row sumsq via shuffles, time attach.
    const int h = h0 + (tx >> 3);
    const int m0 = (tx & 7) * 8;
    float4 bb0 = *(const float4*)&bias[h * DH + m0];
    float4 bb1 = *(const float4*)&bias[h * DH + m0 + 4];
    const float bbv[8] = {bb0.x, bb0.y, bb0.z, bb0.w, bb1.x, bb1.y, bb1.z, bb1.w};
    const float tsign = (mat == 0) ? -1.0f : 1.0f;

    #pragma unroll
    for (int i = 0; i < 8; i++) {
        float c[8];
        float2 u;
        u = up2(acc2[i][0]); c[0] = u.x + bbv[0]; c[1] = u.y + bbv[1];
        u = up2(acc2[i][1]); c[2] = u.x + bbv[2]; c[3] = u.y + bbv[3];
        u = up2(acc2[i][2]); c[4] = u.x + bbv[4]; c[5] = u.y + bbv[5];
        u = up2(acc2[i][3]); c[6] = u.x + bbv[6]; c[7] = u.y + bbv[7];
        float ss = 0.f;
        #pragma unroll
        for (int j = 0; j < 8; j++) ss += c[j] * c[j];
        ss += __shfl_xor_sync(0xffffffffu, ss, 1);
        ss += __shfl_xor_sync(0xffffffffu, ss, 2);
        ss += __shfl_xor_sync(0xffffffffu, ss, 4);
        int g = row0 + ty * 8 + i;
        int b = g >> 11, n = g & 2047;
        size_t bhn = (size_t)(b * HH + h) * NN + n;
        float* dst = &outs[bhn * DH + m0];
        #pragma unroll
        for (int j = 0; j < 8; j++) dst[j] = c[j];
        if ((tx & 7) == 0)
            outt[bhn] = tsign * sqrtf(fmaxf(INV_K + ss, EPS_F));
    }
}

// ---------------------------------------------------------------------------
// Kernel 2: flash attention, 128q x 128k tiles, float4 operand reads.
// Qs/Ks/Vs [128][68] (space 0..63, time at 64; Q pre-scaled by SCALE).
// Pt [128][132]: key kk at column kk + 4*(kk>=64) (mid-pad for softmax banks).
// ---------------------------------------------------------------------------
#define AT_QS   0
#define AT_KS   (128*68)
#define AT_VS   (2*128*68)
#define AT_PT   (3*128*68)
#define AT_MR   (AT_PT + 128*132)
#define ATT_SMEM_FLOATS (AT_MR + 4*128)
#define ATT_SMEM_BYTES  (ATT_SMEM_FLOATS * 4)

__global__ __launch_bounds__(256, 1) void attn_kernel()
{
    extern __shared__ float sm[];
    float* Qs   = sm + AT_QS;
    float* Ks   = sm + AT_KS;
    float* Vs   = sm + AT_VS;
    float* Pt   = sm + AT_PT;
    float* mrow = sm + AT_MR;
    float* lrow = mrow + 128;
    float* arow = lrow + 128;
    float* otc  = arow + 128;

    const int tid = threadIdx.x;
    const int ty = tid >> 4;      // queries ty+16i
    const int tx = tid & 15;      // S: keys tx+16j ; PV/epilogue: cols tx*4
    const int bh = blockIdx.y;
    const int q0 = blockIdx.x * 128;
    const int h = bh & 7, b = bh >> 3;

    // stage Q (once), pre-scaled by SCALE (time negated upstream)
    const float* qsb = g_qs + ((size_t)bh * NN + q0) * DH;
    const float* qtb = g_qt + (size_t)bh * NN + q0;
    #pragma unroll
    for (int it = 0; it < 8; it++) {
        int lin = tid + it * 256;
        int r = lin >> 4, c4 = lin & 15;
        float4 v = *(const float4*)&qsb[r * DH + c4 * 4];
        *(float4*)&Qs[r * 68 + c4 * 4] = make_float4(
            v.x * SCALE_F, v.y * SCALE_F, v.z * SCALE_F, v.w * SCALE_F);
    }
    if (tid < 128) {
        Qs[tid * 68 + 64] = qtb[tid] * SCALE_F;
        mrow[tid] = -1e30f; lrow[tid] = 0.0f; otc[tid] = 0.0f;
    }

    u64 o2[8][2] = {};

    const float* ksb = g_ks + (size_t)bh * NN * DH;
    const float* ktb = g_kt + (size_t)bh * NN;
    const float* vsb = g_vs + (size_t)bh * NN * DH;
    const float* vtb = g_vt + (size_t)bh * NN;

    #pragma unroll 1
    for (int kt = 0; kt < NN / 128; kt++) {
        __syncthreads();
        const float* kp_ = ksb + (size_t)kt * 128 * DH;
        const float* vp_ = vsb + (size_t)kt * 128 * DH;
        #pragma unroll
        for (int it = 0; it < 8; it++) {
            int lin = tid + it * 256;
            int r = lin >> 4, c4 = lin & 15;
            float4 kv = *(const float4*)&kp_[r * DH + c4 * 4];
            *(float4*)&Ks[r * 68 + c4 * 4] = kv;
            float4 vv = *(const float4*)&vp_[r * DH + c4 * 4];
            *(float4*)&Vs[r * 68 + c4 * 4] = vv;
        }
        if (tid < 128) {
            Ks[tid * 68 + 64] = ktb[kt * 128 + tid];
            Vs[tid * 68 + 64] = vtb[kt * 128 + tid];
        }
        __syncthreads();

        // ---- S = (SCALE*Q~) . K over 65 dims ----
        {
            u64 s2[8][4] = {};
            #pragma unroll 2
            for (int d4 = 0; d4 < 64; d4 += 4) {
                float4 qv4[8], kv4[8];
                #pragma unroll
                for (int i = 0; i < 8; i++)
                    qv4[i] = *(const float4*)&Qs[(ty + 16 * i) * 68 + d4];
                #pragma unroll
                for (int j = 0; j < 8; j++)
                    kv4[j] = *(const float4*)&Ks[(tx + 16 * j) * 68 + d4];
                #pragma unroll
                for (int dd = 0; dd < 4; dd++) {
                    u64 kp2[4];
                    #pragma unroll
                    for (int p = 0; p < 4; p++)
                        kp2[p] = pk2(((const float*)&kv4[2 * p])[dd],
                                     ((const float*)&kv4[2 * p + 1])[dd]);
                    #pragma unroll
                    for (int i = 0; i < 8; i++) {
                        u64 qb = bc2(((const float*)&qv4[i])[dd]);
                        #pragma unroll
                        for (int p = 0; p < 4; p++) fma2(s2[i][p], qb, kp2[p]);
                    }
                }
            }
            {   // time dim (d=64)
                u64 kp2[4];
                float kvt[8];
                #pragma unroll
                for (int j = 0; j < 8; j++) kvt[j] = Ks[(tx + 16 * j) * 68 + 64];
                #pragma unroll
                for (int p = 0; p < 4; p++) kp2[p] = pk2(kvt[2 * p], kvt[2 * p + 1]);
                #pragma unroll
                for (int i = 0; i < 8; i++) {
                    u64 qb = bc2(Qs[(ty + 16 * i) * 68 + 64]);
                    #pragma unroll
                    for (int p = 0; p < 4; p++) fma2(s2[i][p], qb, kp2[p]);
                }
            }
            #pragma unroll
            for (int i = 0; i < 8; i++) {
                float* pr = &Pt[(ty + 16 * i) * 132];
                #pragma unroll
                for (int p = 0; p < 4; p++) {
                    float2 v = up2(s2[i][p]);
                    int pad = (p >= 2) ? 4 : 0;
                    pr[tx + 32 * p + pad]      = v.x;
                    pr[tx + 32 * p + 16 + pad] = v.y;
                }
            }
        }
        __syncthreads();

        // ---- online softmax (2 threads/row; half-rows 68 apart) ----
        {
            int r = tid >> 1, part = tid & 1;
            float* prow = &Pt[r * 132 + part * 68];
            float mo = mrow[r];
            float mx = -1e30f;
            #pragma unroll
            for (int jf = 0; jf < 16; jf++) {
                float4 p = *(const float4*)&prow[jf * 4];
                mx = fmaxf(mx, fmaxf(fmaxf(p.x, p.y), fmaxf(p.z, p.w)));
            }
            mx = fmaxf(mx, __shfl_xor_sync(0xffffffffu, mx, 1));
            float mn = fmaxf(mo, mx);
            float sum = 0.f, tsum = 0.f;
            #pragma unroll
            for (int jf = 0; jf < 16; jf++) {
                float4 p = *(float4*)&prow[jf * 4];
                float e0 = __expf(p.x - mn), e1 = __expf(p.y - mn);
                float e2 = __expf(p.z - mn), e3 = __expf(p.w - mn);
                *(float4*)&prow[jf * 4] = make_float4(e0, e1, e2, e3);
                sum += (e0 + e1) + (e2 + e3);
                int kk = part * 64 + jf * 4;
                tsum += e0 * Vs[(kk + 0) * 68 + 64] + e1 * Vs[(kk + 1) * 68 + 64]
                      + e2 * Vs[(kk + 2) * 68 + 64] + e3 * Vs[(kk + 3) * 68 + 64];
            }
            sum  += __shfl_xor_sync(0xffffffffu, sum, 1);
            tsum += __shfl_xor_sync(0xffffffffu, tsum, 1);
            if (part == 0) {
                float al = __expf(mo - mn);
                arow[r] = al;
                lrow[r] = lrow[r] * al + sum;
                otc[r]  = otc[r] * al + tsum;
                mrow[r] = mn;
            }
        }
        __syncthreads();

        // ---- O = O*alpha + P @ V (float4 P reads per 4-key block) ----
        {
            u64 pacc[8][2] = {};
            #pragma unroll 2
            for (int kb = 0; kb < 32; kb++) {
                int off = kb * 4 + ((kb >= 16) ? 4 : 0);
                float4 pv4[8];
                #pragma unroll
                for (int i = 0; i < 8; i++)
                    pv4[i] = *(const float4*)&Pt[(ty + 16 * i) * 132 + off];
                #pragma unroll
                for (int dd = 0; dd < 4; dd++) {
                    int kk = kb * 4 + dd;
                    float4 v4 = *(const float4*)&Vs[kk * 68 + tx * 4];
                    u64 vp0 = pk2(v4.x, v4.y), vp1 = pk2(v4.z, v4.w);
                    #pragma unroll
                    for (int i = 0; i < 8; i++) {
                        u64 pb = bc2(((const float*)&pv4[i])[dd]);
                        fma2(pacc[i][0], pb, vp0);
                        fma2(pacc[i][1], pb, vp1);
                    }
                }
            }
            #pragma unroll
            for (int i = 0; i < 8; i++) {
                u64 al = bc2(arow[ty + 16 * i]);
                o2[i][0] = fma2v(o2[i][0], al, pacc[i][0]);
                o2[i][1] = fma2v(o2[i][1], al, pacc[i][1]);
            }
        }
    }

    // ---- epilogue: normalize, Lorentz midpoint factor, head-concat write ----
    #pragma unroll
    for (int i = 0; i < 8; i++) {
        int q = ty + 16 * i;
        float invl = 1.0f / lrow[q];
        float2 c01 = up2(o2[i][0]);
        float2 c23 = up2(o2[i][1]);
        float c0 = c01.x * invl, c1 = c01.y * invl;
        float c2 = c23.x * invl, c3 = c23.y * invl;
        float t = otc[q] * invl;
        float ss = c0 * c0 + c1 * c1 + c2 * c2 + c3 * c3;
        ss += __shfl_xor_sync(0xffffffffu, ss, 1);
        ss += __shfl_xor_sync(0xffffffffu, ss, 2);
        ss += __shfl_xor_sync(0xffffffffu, ss, 4);
        ss += __shfl_xor_sync(0xffffffffu, ss, 8);
        float fac = rsqrtf(fmaxf(-K_CURV * (ss - t * t), EPS_F));
        float* dst = &g_cat[(size_t)(b * NN + q0 + q) * DD + 1 + h * DH + tx * 4];
        dst[0] = c0 * fac; dst[1] = c1 * fac; dst[2] = c2 * fac; dst[3] = c3 * fac;
    }
}

// ---------------------------------------------------------------------------
// Kernel 3/5: per-row time attach
// ---------------------------------------------------------------------------
__global__ void rowtime_kernel(float* outp, int which)
{
    float* buf = which ? g_cat : outp;
    int warp = (blockIdx.x * blockDim.x + threadIdx.x) >> 5;
    int lane = threadIdx.x & 31;
    if (warp >= ROWS) return;
    const float* row = buf + (size_t)warp * DD + 1;
    float s = 0.0f;
    #pragma unroll
    for (int c = lane; c < 512; c += 32) {
        float v = row[c];
        s += v * v;
    }
    #pragma unroll
    for (int off = 16; off; off >>= 1)
        s += __shfl_xor_sync(0xffffffffu, s, off);
    if (lane == 0) buf[(size_t)warp * DD] = sqrtf(fmaxf(INV_K + s, EPS_F));
}

// ---------------------------------------------------------------------------
// Kernel 4: output GEMM, double-buffered, 128x128 tile, 8x8 micro.
// ---------------------------------------------------------------------------
__global__ __launch_bounds__(256, 2) void outproj_kernel(
    const float* __restrict__ Wo, const float* __restrict__ bo,
    float* __restrict__ outp)
{
    __shared__ float As[2][16][132];
    __shared__ float Bs[2][16][132];

    const int tid = threadIdx.x;
    const int ty = tid >> 4;
    const int tx = tid & 15;
    const int row0 = blockIdx.x * 128;
    const int col0 = blockIdx.y * 128;

    u64 acc2[8][4] = {};

    #pragma unroll
    for (int it = 0; it < 8; it++) {
        int lin = tid + it * 256;
        int r = lin >> 4, kk = lin & 15;
        As[0][kk][r] = (kk < DD) ? g_cat[(size_t)(row0 + r) * DD + kk] : 0.0f;
    }
    #pragma unroll
    for (int it = 0; it < 2; it++) {
        int lin = tid + it * 256;
        int kk = lin >> 5, c4 = lin & 31;
        float4 v = make_float4(0.f, 0.f, 0.f, 0.f);
        if (kk < DD) v = *(const float4*)&Wo[(size_t)kk * 512 + col0 + c4 * 4];
        *(float4*)&Bs[0][kk][c4 * 4] = v;
    }
    __syncthreads();

    int buf = 0;
    for (int k0 = 0; k0 < DD; k0 += 16, buf ^= 1) {
        const bool more = (k0 + 16) < DD;
        float ra[8];
        float4 rb[2];
        if (more) {
            #pragma unroll
            for (int it = 0; it < 8; it++) {
                int lin = tid + it * 256;
                int r = lin >> 4, kk = lin & 15;
                int kg = k0 + 16 + kk;
                ra[it] = (kg < DD) ? g_cat[(size_t)(row0 + r) * DD + kg] : 0.0f;
            }
            #pragma unroll
            for (int it = 0; it < 2; it++) {
                int lin = tid + it * 256;
                int kk = lin >> 5, c4 = lin & 31;
                int kg = k0 + 16 + kk;
                float4 v = make_float4(0.f, 0.f, 0.f, 0.f);
                if (kg < DD) v = *(const float4*)&Wo[(size_t)kg * 512 + col0 + c4 * 4];
                rb[it] = v;
            }
        }
        #pragma unroll
        for (int kk = 0; kk < 16; kk++) {
            float4 a0 = *(const float4*)&As[buf][kk][ty * 8];
            float4 a1 = *(const float4*)&As[buf][kk][ty * 8 + 4];
            float4 b0 = *(const float4*)&Bs[buf][kk][tx * 8];
            float4 b1 = *(const float4*)&Bs[buf][kk][tx * 8 + 4];
            u64 bp[4] = {pk2(b0.x, b0.y), pk2(b0.z, b0.w),
                         pk2(b1.x, b1.y), pk2(b1.z, b1.w)};
            float av[8] = {a0.x, a0.y, a0.z, a0.w, a1.x, a1.y, a1.z, a1.w};
            #pragma unroll
            for (int i = 0; i < 8; i++) {
                u64 ab = bc2(av[i]);
                #pragma unroll
                for (int p = 0; p < 4; p++) fma2(acc2[i][p], ab, bp[p]);
            }
        }
        if (more) {
            #pragma unroll
            for (int it = 0; it < 8; it++) {
                int lin = tid + it * 256;
                int r = lin >> 4, kk = lin & 15;
                As[buf ^ 1][kk][r] = ra[it];
            }
            #pragma unroll
            for (int it = 0; it < 2; it++) {
                int lin = tid + it * 256;
                int kk = lin >> 5, c4 = lin & 31;
                *(float4*)&Bs[buf ^ 1][kk][c4 * 4] = rb[it];
            }
        }
        __syncthreads();
    }

    float4 bb0 = *(const float4*)&bo[col0 + tx * 8];
    float4 bb1 = *(const float4*)&bo[col0 + tx * 8 + 4];
    const float bbv[8] = {bb0.x, bb0.y, bb0.z, bb0.w, bb1.x, bb1.y, bb1.z, bb1.w};
    #pragma unroll
    for (int i = 0; i < 8; i++) {
        float c[8];
        float2 u;
        u = up2(acc2[i][0]); c[0] = u.x; c[1] = u.y;
        u = up2(acc2[i][1]); c[2] = u.x; c[3] = u.y;
        u = up2(acc2[i][2]); c[4] = u.x; c[5] = u.y;
        u = up2(acc2[i][3]); c[6] = u.x; c[7] = u.y;
        float* dst = &outp[(size_t)(row0 + ty * 8 + i) * DD + 1 + col0 + tx * 8];
        #pragma unroll
        for (int j = 0; j < 8; j++) dst[j] = c[j] + bbv[j];
    }
}

// ---------------------------------------------------------------------------
extern "C" void kernel_launch(void* const* d_in, const int* in_sizes, int n_in,
                              void* d_out, int out_size)
{
    const float* x  = (const float*)d_in[0];
    const float* Wq = (const float*)d_in[1];
    const float* bq = (const float*)d_in[2];
    const float* Wk = (const float*)d_in[3];
    const float* bk = (const float*)d_in[4];
    const float* Wv = (const float*)d_in[5];
    const float* bv = (const float*)d_in[6];
    const float* Wo = (const float*)d_in[7];
    const float* bo = (const float*)d_in[8];
    float* outp = (float*)d_out;

    cudaFuncSetAttribute(attn_kernel,
                         cudaFuncAttributeMaxDynamicSharedMemorySize,
                         ATT_SMEM_BYTES);

    proj_kernel<<<dim3(ROWS / 128, 12), 256>>>(x, Wq, bq, Wk, bk, Wv, bv);
    attn_kernel<<<dim3(NN / 128, BB * HH), 256, ATT_SMEM_BYTES>>>();
    rowtime_kernel<<<ROWS / 8, 256>>>(nullptr, 1);
    outproj_kernel<<<dim3(ROWS / 128, 4), 256>>>(Wo, bo, outp);
    rowtime_kernel<<<ROWS / 8, 256>>>(outp, 0);
}

// round 8
// speedup vs baseline: 1.1416x; 1.1416x over previous
#include <cuda_runtime.h>
#include <math.h>

// Problem dims
#define BB   4
#define NN   2048
#define DD   513
#define HH   8
#define DH   64
#define ROWS (BB*NN)       // 8192

#define INV_K   10.0f
#define K_CURV  0.1f
#define EPS_F   1e-9f
#define SCALE_F 0.125f     // 1/sqrt(64)

// ---------------------------------------------------------------------------
// Packed fp32x2 helpers (sm_100+ PTX fma.rn.f32x2 -> FFMA2)
// ---------------------------------------------------------------------------
typedef unsigned long long u64;
__device__ __forceinline__ u64 pk2(float x, float y) {
    u64 r; asm("mov.b64 %0, {%1,%2};" : "=l"(r) : "f"(x), "f"(y)); return r;
}
__device__ __forceinline__ u64 bc2(float x) {
    u64 r; asm("mov.b64 %0, {%1,%1};" : "=l"(r) : "f"(x)); return r;
}
__device__ __forceinline__ void fma2(u64 &d, u64 a, u64 b) {
    asm("fma.rn.f32x2 %0, %1, %2, %0;" : "+l"(d) : "l"(a), "l"(b));
}
__device__ __forceinline__ u64 fma2v(u64 a, u64 b, u64 c) {
    u64 d; asm("fma.rn.f32x2 %0, %1, %2, %3;" : "=l"(d) : "l"(a), "l"(b), "l"(c)); return d;
}
__device__ __forceinline__ float2 up2(u64 v) {
    float lo, hi; asm("mov.b64 {%0,%1}, %2;" : "=f"(lo), "=f"(hi) : "l"(v));
    return make_float2(lo, hi);
}

// Scratch (device globals: allocation-free per harness rules)
__device__ float g_qs[BB*HH*NN*DH];   // q space
__device__ float g_qt[BB*HH*NN];      // q time, NEGATED
__device__ float g_ks[BB*HH*NN*DH];
__device__ float g_kt[BB*HH*NN];
__device__ float g_vs[BB*HH*NN*DH];
__device__ float g_vt[BB*HH*NN];
__device__ float g_cat[ROWS*DD];      // [B*N][513]

// ---------------------------------------------------------------------------
// Kernel 1: QKV projection GEMM (128x128 tile, 8x8 micro, FFMA2) + time attach
// (single-buffered: the R6-measured best variant)
// ---------------------------------------------------------------------------
__global__ __launch_bounds__(256) void proj_kernel(
    const float* __restrict__ x,
    const float* __restrict__ Wq, const float* __restrict__ bq,
    const float* __restrict__ Wk, const float* __restrict__ bk,
    const float* __restrict__ Wv, const float* __restrict__ bv)
{
    __shared__ float As[16][132];   // [kk][row]
    __shared__ float Bs[16][132];   // [kk][col]

    const int tid = threadIdx.x;
    const int ty = tid >> 4;
    const int tx = tid & 15;
    const int row0 = blockIdx.x * 128;
    const int gy = blockIdx.y;
    const int mat = gy >> 2;        // 0=q 1=k 2=v
    const int h0 = (gy & 3) * 2;

    const float* W    = (mat == 0) ? Wq : ((mat == 1) ? Wk : Wv);
    const float* bias = (mat == 0) ? bq : ((mat == 1) ? bk : bv);
    float* outs       = (mat == 0) ? g_qs : ((mat == 1) ? g_ks : g_vs);
    float* outt       = (mat == 0) ? g_qt : ((mat == 1) ? g_kt : g_vt);

    u64 acc2[8][4] = {};

    for (int k0 = 0; k0 < DD; k0 += 16) {
        #pragma unroll
        for (int it = 0; it < 8; it++) {
            int lin = tid + it * 256;
            int r = lin >> 4, kk = lin & 15;
            int kg = k0 + kk;
            As[kk][r] = (kg < DD) ? x[(size_t)(row0 + r) * DD + kg] : 0.0f;
        }
        #pragma unroll
        for (int it = 0; it < 2; it++) {
            int lin = tid + it * 256;
            int kk = lin >> 5, c4 = lin & 31;
            int kg = k0 + kk;
            int c = c4 * 4;
            int h = h0 + (c >> 6), m = c & 63;
            float4 v = make_float4(0.f, 0.f, 0.f, 0.f);
            if (kg < DD) v = *(const float4*)&W[((size_t)h * DD + kg) * DH + m];
            *(float4*)&Bs[kk][c] = v;
        }
        __syncthreads();
        #pragma unroll
        for (int kk = 0; kk < 16; kk++) {
            float4 a0 = *(const float4*)&As[kk][ty * 8];
            float4 a1 = *(const float4*)&As[kk][ty * 8 + 4];
            float4 b0 = *(const float4*)&Bs[kk][tx * 8];
            float4 b1 = *(const float4*)&Bs[kk][tx * 8 + 4];
            u64 bp[4] = {pk2(b0.x, b0.y), pk2(b0.z, b0.w),
                         pk2(b1.x, b1.y), pk2(b1.z, b1.w)};
            float av[8] = {a0.x, a0.y, a0.z, a0.w, a1.x, a1.y, a1.z, a1.w};
            #pragma unroll
            for (int i = 0; i < 8; i++) {
                u64 ab = bc2(av[i]);
                #pragma unroll
                for (int p = 0; p < 4; p++) fma2(acc2[i][p], ab, bp[p]);
            }
        }
        __syncthreads();
    }

    // Epilogue: bias, per-head row sumsq via shuffles, time attach.
    const int h = h0 + (tx >> 3);
    const int m0 = (tx & 7) * 8;
    float4 bb0 = *(const float4*)&bias[h * DH + m0];
    float4 bb1 = *(const float4*)&bias[h * DH + m0 + 4];
    const float bbv[8] = {bb0.x, bb0.y, bb0.z, bb0.w, bb1.x, bb1.y, bb1.z, bb1.w};
    const float tsign = (mat == 0) ? -1.0f : 1.0f;

    #pragma unroll
    for (int i = 0; i < 8; i++) {
        float c[8];
        float2 u;
        u = up2(acc2[i][0]); c[0] = u.x + bbv[0]; c[1] = u.y + bbv[1];
        u = up2(acc2[i][1]); c[2] = u.x + bbv[2]; c[3] = u.y + bbv[3];
        u = up2(acc2[i][2]); c[4] = u.x + bbv[4]; c[5] = u.y + bbv[5];
        u = up2(acc2[i][3]); c[6] = u.x + bbv[6]; c[7] = u.y + bbv[7];
        float ss = 0.f;
        #pragma unroll
        for (int j = 0; j < 8; j++) ss += c[j] * c[j];
        ss += __shfl_xor_sync(0xffffffffu, ss, 1);
        ss += __shfl_xor_sync(0xffffffffu, ss, 2);
        ss += __shfl_xor_sync(0xffffffffu, ss, 4);
        int g = row0 + ty * 8 + i;
        int b = g >> 11, n = g & 2047;
        size_t bhn = (size_t)(b * HH + h) * NN + n;
        float* dst = &outs[bhn * DH + m0];
        #pragma unroll
        for (int j = 0; j < 8; j++) dst[j] = c[j];
        if ((tx & 7) == 0)
            outt[bhn] = tsign * sqrtf(fmaxf(INV_K + ss, EPS_F));
    }
}

// ---------------------------------------------------------------------------
// Kernel 2: flash attention, 128q x 128k tiles, 256 threads, 8x8 micro.
// Qs stride 72 (float4-aligned reads, broadcast in S-phase), Ks stride 69
// (odd stride -> conflict-free 16-lane scalar column reads), Vs stride 68,
// Pt [query][key] stride 132 (float4-aligned at any 4-key offset).
// PV-phase reads P as float4 per 4-key block (was 8 scalar broadcasts/key).
// ---------------------------------------------------------------------------
#define AT_QS   0
#define AT_KS   (128*72)
#define AT_VS   (AT_KS + 128*69)
#define AT_PT   (AT_VS + 128*68)
#define AT_MR   (AT_PT + 128*132)
#define ATT_SMEM_FLOATS (AT_MR + 4*128)
#define ATT_SMEM_BYTES  (ATT_SMEM_FLOATS * 4)

__global__ __launch_bounds__(256, 1) void attn_kernel()
{
    extern __shared__ float sm[];
    float* Qs   = sm + AT_QS;     // [128][72], time at col 64 (negated upstream)
    float* Ks   = sm + AT_KS;     // [128][69], time at col 64
    float* Vs   = sm + AT_VS;     // [128][68], space 0..63, time at 64
    float* Pt   = sm + AT_PT;     // [128 query][132]
    float* mrow = sm + AT_MR;     // [128]
    float* lrow = mrow + 128;
    float* arow = lrow + 128;
    float* otc  = arow + 128;

    const int tid = threadIdx.x;
    const int ty = tid >> 4;      // queries ty+16i
    const int tx = tid & 15;      // S: keys tx+16j ; PV/epilogue: cols tx*4
    const int bh = blockIdx.y;
    const int q0 = blockIdx.x * 128;
    const int h = bh & 7, b = bh >> 3;

    // stage Q (once)
    const float* qsb = g_qs + ((size_t)bh * NN + q0) * DH;
    const float* qtb = g_qt + (size_t)bh * NN + q0;
    #pragma unroll
    for (int it = 0; it < 8; it++) {
        int lin = tid + it * 256;
        int r = lin >> 4, c4 = lin & 15;
        float4 v = *(const float4*)&qsb[r * DH + c4 * 4];
        *(float4*)&Qs[r * 72 + c4 * 4] = v;
    }
    if (tid < 128) {
        Qs[tid * 72 + 64] = qtb[tid];
        mrow[tid] = -1e30f; lrow[tid] = 0.0f; otc[tid] = 0.0f;
    }

    u64 o2[8][2] = {};            // persistent O: [row i][col-pair]

    const float* ksb = g_ks + (size_t)bh * NN * DH;
    const float* ktb = g_kt + (size_t)bh * NN;
    const float* vsb = g_vs + (size_t)bh * NN * DH;
    const float* vtb = g_vt + (size_t)bh * NN;

    #pragma unroll 1
    for (int kt = 0; kt < NN / 128; kt++) {
        __syncthreads();
        const float* kp_ = ksb + (size_t)kt * 128 * DH;
        const float* vp_ = vsb + (size_t)kt * 128 * DH;
        #pragma unroll
        for (int it = 0; it < 8; it++) {
            int lin = tid + it * 256;
            int r = lin >> 4, c4 = lin & 15;
            float4 kv = *(const float4*)&kp_[r * DH + c4 * 4];
            float* kd = &Ks[r * 69 + c4 * 4];
            kd[0] = kv.x; kd[1] = kv.y; kd[2] = kv.z; kd[3] = kv.w;
            float4 vv = *(const float4*)&vp_[r * DH + c4 * 4];
            *(float4*)&Vs[r * 68 + c4 * 4] = vv;
        }
        if (tid < 128) {
            Ks[tid * 69 + 64] = ktb[kt * 128 + tid];
            Vs[tid * 68 + 64] = vtb[kt * 128 + tid];
        }
        __syncthreads();

        // ---- S = Q~ K^T over 65 dims (time folded via negated q-time) ----
        {
            u64 s2[8][4] = {};    // [query i][key-pair]
            #pragma unroll 1
            for (int d4 = 0; d4 < 64; d4 += 4) {
                float4 qv4[8];    // Q block: 2 unique rows/warp -> broadcast reads
                #pragma unroll
                for (int i = 0; i < 8; i++)
                    qv4[i] = *(const float4*)&Qs[(ty + 16 * i) * 72 + d4];
                #pragma unroll
                for (int dd = 0; dd < 4; dd++) {
                    float kv[8];  // K scalar reads, stride 69: conflict-free
                    #pragma unroll
                    for (int j = 0; j < 8; j++)
                        kv[j] = Ks[(tx + 16 * j) * 69 + d4 + dd];
                    u64 kp2[4];
                    #pragma unroll
                    for (int p = 0; p < 4; p++)
                        kp2[p] = pk2(kv[2 * p], kv[2 * p + 1]);
                    #pragma unroll
                    for (int i = 0; i < 8; i++) {
                        u64 qb = bc2(((const float*)&qv4[i])[dd]);
                        #pragma unroll
                        for (int p = 0; p < 4; p++) fma2(s2[i][p], qb, kp2[p]);
                    }
                }
            }
            {   // time dim (d=64)
                float kv[8];
                #pragma unroll
                for (int j = 0; j < 8; j++) kv[j] = Ks[(tx + 16 * j) * 69 + 64];
                u64 kp2[4];
                #pragma unroll
                for (int p = 0; p < 4; p++) kp2[p] = pk2(kv[2 * p], kv[2 * p + 1]);
                #pragma unroll
                for (int i = 0; i < 8; i++) {
                    u64 qb = bc2(Qs[(ty + 16 * i) * 72 + 64]);
                    #pragma unroll
                    for (int p = 0; p < 4; p++) fma2(s2[i][p], qb, kp2[p]);
                }
            }
            #pragma unroll
            for (int i = 0; i < 8; i++) {
                float* pr = &Pt[(ty + 16 * i) * 132];
                #pragma unroll
                for (int p = 0; p < 4; p++) {
                    float2 v = up2(s2[i][p]);
                    pr[tx + 16 * (2 * p)]     = v.x * SCALE_F;
                    pr[tx + 16 * (2 * p + 1)] = v.y * SCALE_F;
                }
            }
        }
        __syncthreads();

        // ---- online softmax over 128 keys (2 threads/row) + time PV fold ----
        {
            int r = tid >> 1, part = tid & 1;
            float* prow = &Pt[r * 132 + part * 64];
            float mo = mrow[r];
            float mx = -1e30f;
            #pragma unroll
            for (int jf = 0; jf < 16; jf++) {
                float4 p = *(const float4*)&prow[jf * 4];
                mx = fmaxf(mx, fmaxf(fmaxf(p.x, p.y), fmaxf(p.z, p.w)));
            }
            mx = fmaxf(mx, __shfl_xor_sync(0xffffffffu, mx, 1));
            float mn = fmaxf(mo, mx);
            float sum = 0.f, tsum = 0.f;
            #pragma unroll
            for (int jf = 0; jf < 16; jf++) {
                float4 p = *(float4*)&prow[jf * 4];
                float e0 = __expf(p.x - mn), e1 = __expf(p.y - mn);
                float e2 = __expf(p.z - mn), e3 = __expf(p.w - mn);
                *(float4*)&prow[jf * 4] = make_float4(e0, e1, e2, e3);
                sum += (e0 + e1) + (e2 + e3);
                int kk = part * 64 + jf * 4;
                tsum += e0 * Vs[(kk + 0) * 68 + 64] + e1 * Vs[(kk + 1) * 68 + 64]
                      + e2 * Vs[(kk + 2) * 68 + 64] + e3 * Vs[(kk + 3) * 68 + 64];
            }
            sum  += __shfl_xor_sync(0xffffffffu, sum, 1);
            tsum += __shfl_xor_sync(0xffffffffu, tsum, 1);
            if (part == 0) {
                float al = __expf(mo - mn);
                arow[r] = al;
                lrow[r] = lrow[r] * al + sum;
                otc[r]  = otc[r] * al + tsum;
                mrow[r] = mn;
            }
        }
        __syncthreads();

        // ---- O = O*alpha + P @ V : float4 P reads per 4-key block ----
        {
            u64 pacc[8][2] = {};
            #pragma unroll 2
            for (int kb = 0; kb < 32; kb++) {
                float4 pv4[8];    // 2 unique rows/warp -> broadcast reads
                #pragma unroll
                for (int i = 0; i < 8; i++)
                    pv4[i] = *(const float4*)&Pt[(ty + 16 * i) * 132 + kb * 4];
                #pragma unroll
                for (int dd = 0; dd < 4; dd++) {
                    int kk = kb * 4 + dd;
                    float4 v4 = *(const float4*)&Vs[kk * 68 + tx * 4];
                    u64 vp0 = pk2(v4.x, v4.y), vp1 = pk2(v4.z, v4.w);
                    #pragma unroll
                    for (int i = 0; i < 8; i++) {
                        u64 pb = bc2(((const float*)&pv4[i])[dd]);
                        fma2(pacc[i][0], pb, vp0);
                        fma2(pacc[i][1], pb, vp1);
                    }
                }
            }
            #pragma unroll
            for (int i = 0; i < 8; i++) {
                u64 al = bc2(arow[ty + 16 * i]);
                o2[i][0] = fma2v(o2[i][0], al, pacc[i][0]);
                o2[i][1] = fma2v(o2[i][1], al, pacc[i][1]);
            }
        }
    }

    // ---- epilogue: normalize, Lorentz midpoint factor, head-concat write ----
    #pragma unroll
    for (int i = 0; i < 8; i++) {
        int q = ty + 16 * i;
        float invl = 1.0f / lrow[q];
        float2 c01 = up2(o2[i][0]);
        float2 c23 = up2(o2[i][1]);
        float c0 = c01.x * invl, c1 = c01.y * invl;
        float c2 = c23.x * invl, c3 = c23.y * invl;
        float t = otc[q] * invl;
        float ss = c0 * c0 + c1 * c1 + c2 * c2 + c3 * c3;
        ss += __shfl_xor_sync(0xffffffffu, ss, 1);
        ss += __shfl_xor_sync(0xffffffffu, ss, 2);
        ss += __shfl_xor_sync(0xffffffffu, ss, 4);
        ss += __shfl_xor_sync(0xffffffffu, ss, 8);
        float fac = rsqrtf(fmaxf(-K_CURV * (ss - t * t), EPS_F));
        float* dst = &g_cat[(size_t)(b * NN + q0 + q) * DD + 1 + h * DH + tx * 4];
        dst[0] = c0 * fac; dst[1] = c1 * fac; dst[2] = c2 * fac; dst[3] = c3 * fac;
    }
}

// ---------------------------------------------------------------------------
// Kernel 3/5: per-row time attach
// ---------------------------------------------------------------------------
__global__ void rowtime_kernel(float* outp, int which)
{
    float* buf = which ? g_cat : outp;
    int warp = (blockIdx.x * blockDim.x + threadIdx.x) >> 5;
    int lane = threadIdx.x & 31;
    if (warp >= ROWS) return;
    const float* row = buf + (size_t)warp * DD + 1;
    float s = 0.0f;
    #pragma unroll
    for (int c = lane; c < 512; c += 32) {
        float v = row[c];
        s += v * v;
    }
    #pragma unroll
    for (int off = 16; off; off >>= 1)
        s += __shfl_xor_sync(0xffffffffu, s, off);
    if (lane == 0) buf[(size_t)warp * DD] = sqrtf(fmaxf(INV_K + s, EPS_F));
}

// ---------------------------------------------------------------------------
// Kernel 4: output GEMM, double-buffered, 128x128 tile, 8x8 micro.
// ---------------------------------------------------------------------------
__global__ __launch_bounds__(256, 2) void outproj_kernel(
    const float* __restrict__ Wo, const float* __restrict__ bo,
    float* __restrict__ outp)
{
    __shared__ float As[2][16][132];
    __shared__ float Bs[2][16][132];

    const int tid = threadIdx.x;
    const int ty = tid >> 4;
    const int tx = tid & 15;
    const int row0 = blockIdx.x * 128;
    const int col0 = blockIdx.y * 128;

    u64 acc2[8][4] = {};

    #pragma unroll
    for (int it = 0; it < 8; it++) {
        int lin = tid + it * 256;
        int r = lin >> 4, kk = lin & 15;
        As[0][kk][r] = g_cat[(size_t)(row0 + r) * DD + kk];
    }
    #pragma unroll
    for (int it = 0; it < 2; it++) {
        int lin = tid + it * 256;
        int kk = lin >> 5, c4 = lin & 31;
        float4 v = *(const float4*)&Wo[(size_t)kk * 512 + col0 + c4 * 4];
        *(float4*)&Bs[0][kk][c4 * 4] = v;
    }
    __syncthreads();

    int buf = 0;
    for (int k0 = 0; k0 < DD; k0 += 16, buf ^= 1) {
        const bool more = (k0 + 16) < DD;
        float ra[8];
        float4 rb[2];
        if (more) {
            #pragma unroll
            for (int it = 0; it < 8; it++) {
                int lin = tid + it * 256;
                int r = lin >> 4, kk = lin & 15;
                int kg = k0 + 16 + kk;
                ra[it] = (kg < DD) ? g_cat[(size_t)(row0 + r) * DD + kg] : 0.0f;
            }
            #pragma unroll
            for (int it = 0; it < 2; it++) {
                int lin = tid + it * 256;
                int kk = lin >> 5, c4 = lin & 31;
                int kg = k0 + 16 + kk;
                float4 v = make_float4(0.f, 0.f, 0.f, 0.f);
                if (kg < DD) v = *(const float4*)&Wo[(size_t)kg * 512 + col0 + c4 * 4];
                rb[it] = v;
            }
        }
        #pragma unroll
        for (int kk = 0; kk < 16; kk++) {
            float4 a0 = *(const float4*)&As[buf][kk][ty * 8];
            float4 a1 = *(const float4*)&As[buf][kk][ty * 8 + 4];
            float4 b0 = *(const float4*)&Bs[buf][kk][tx * 8];
            float4 b1 = *(const float4*)&Bs[buf][kk][tx * 8 + 4];
            u64 bp[4] = {pk2(b0.x, b0.y), pk2(b0.z, b0.w),
                         pk2(b1.x, b1.y), pk2(b1.z, b1.w)};
            float av[8] = {a0.x, a0.y, a0.z, a0.w, a1.x, a1.y, a1.z, a1.w};
            #pragma unroll
            for (int i = 0; i < 8; i++) {
                u64 ab = bc2(av[i]);
                #pragma unroll
                for (int p = 0; p < 4; p++) fma2(acc2[i][p], ab, bp[p]);
            }
        }
        if (more) {
            #pragma unroll
            for (int it = 0; it < 8; it++) {
                int lin = tid + it * 256;
                int r = lin >> 4, kk = lin & 15;
                As[buf ^ 1][kk][r] = ra[it];
            }
            #pragma unroll
            for (int it = 0; it < 2; it++) {
                int lin = tid + it * 256;
                int kk = lin >> 5, c4 = lin & 31;
                *(float4*)&Bs[buf ^ 1][kk][c4 * 4] = rb[it];
            }
        }
        __syncthreads();
    }

    float4 bb0 = *(const float4*)&bo[col0 + tx * 8];
    float4 bb1 = *(const float4*)&bo[col0 + tx * 8 + 4];
    const float bbv[8] = {bb0.x, bb0.y, bb0.z, bb0.w, bb1.x, bb1.y, bb1.z, bb1.w};
    #pragma unroll
    for (int i = 0; i < 8; i++) {
        float c[8];
        float2 u;
        u = up2(acc2[i][0]); c[0] = u.x; c[1] = u.y;
        u = up2(acc2[i][1]); c[2] = u.x; c[3] = u.y;
        u = up2(acc2[i][2]); c[4] = u.x; c[5] = u.y;
        u = up2(acc2[i][3]); c[6] = u.x; c[7] = u.y;
        float* dst = &outp[(size_t)(row0 + ty * 8 + i) * DD + 1 + col0 + tx * 8];
        #pragma unroll
        for (int j = 0; j < 8; j++) dst[j] = c[j] + bbv[j];
    }
}

// ---------------------------------------------------------------------------
extern "C" void kernel_launch(void* const* d_in, const int* in_sizes, int n_in,
                              void* d_out, int out_size)
{
    const float* x  = (const float*)d_in[0];
    const float* Wq = (const float*)d_in[1];
    const float* bq = (const float*)d_in[2];
    const float* Wk = (const float*)d_in[3];
    const float* bk = (const float*)d_in[4];
    const float* Wv = (const float*)d_in[5];
    const float* bv = (const float*)d_in[6];
    const float* Wo = (const float*)d_in[7];
    const float* bo = (const float*)d_in[8];
    float* outp = (float*)d_out;

    cudaFuncSetAttribute(attn_kernel,
                         cudaFuncAttributeMaxDynamicSharedMemorySize,
                         ATT_SMEM_BYTES);

    proj_kernel<<<dim3(ROWS / 128, 12), 256>>>(x, Wq, bq, Wk, bk, Wv, bv);
    attn_kernel<<<dim3(NN / 128, BB * HH), 256, ATT_SMEM_BYTES>>>();
    rowtime_kernel<<<ROWS / 8, 256>>>(nullptr, 1);
    outproj_kernel<<<dim3(ROWS / 128, 4), 256>>>(Wo, bo, outp);
    rowtime_kernel<<<ROWS / 8, 256>>>(outp, 0);
}

// round 10
// speedup vs baseline: 1.8187x; 1.5931x over previous
#include <cuda_runtime.h>
#include <math.h>

// Problem dims
#define BB   4
#define NN   2048
#define DD   513
#define HH   8
#define DH   64
#define ROWS (BB*NN)       // 8192

#define INV_K   10.0f
#define K_CURV  0.1f
#define EPS_F   1e-9f
#define SCALE_F 0.125f     // 1/sqrt(64)

// ---------------------------------------------------------------------------
// Packed fp32x2 helpers (FFMA2) — used by the GEMM kernels
// ---------------------------------------------------------------------------
typedef unsigned long long u64;
__device__ __forceinline__ u64 pk2(float x, float y) {
    u64 r; asm("mov.b64 %0, {%1,%2};" : "=l"(r) : "f"(x), "f"(y)); return r;
}
__device__ __forceinline__ u64 bc2(float x) {
    u64 r; asm("mov.b64 %0, {%1,%1};" : "=l"(r) : "f"(x)); return r;
}
__device__ __forceinline__ void fma2(u64 &d, u64 a, u64 b) {
    asm("fma.rn.f32x2 %0, %1, %2, %0;" : "+l"(d) : "l"(a), "l"(b));
}
__device__ __forceinline__ float2 up2(u64 v) {
    float lo, hi; asm("mov.b64 {%0,%1}, %2;" : "=f"(lo), "=f"(hi) : "l"(v));
    return make_float2(lo, hi);
}

// ---------------------------------------------------------------------------
// tf32 mma helpers
// ---------------------------------------------------------------------------
__device__ __forceinline__ float tf32r(float x) {
    unsigned u; asm("cvt.rna.tf32.f32 %0, %1;" : "=r"(u) : "f"(x));
    return __uint_as_float(u);
}
__device__ __forceinline__ void mma_tf32(float c[4],
    unsigned a0, unsigned a1, unsigned a2, unsigned a3,
    unsigned b0, unsigned b1)
{
    asm("mma.sync.aligned.m16n8k8.row.col.f32.tf32.tf32.f32 "
        "{%0,%1,%2,%3},{%4,%5,%6,%7},{%8,%9},{%0,%1,%2,%3};"
        : "+f"(c[0]), "+f"(c[1]), "+f"(c[2]), "+f"(c[3])
        : "r"(a0), "r"(a1), "r"(a2), "r"(a3), "r"(b0), "r"(b1));
}
__device__ __forceinline__ unsigned fu(float x) { return __float_as_uint(x); }

// Scratch (device globals: allocation-free per harness rules)
__device__ float g_qs[BB*HH*NN*DH];   // q space
__device__ float g_qt[BB*HH*NN];      // q time, NEGATED
__device__ float g_ks[BB*HH*NN*DH];
__device__ float g_kt[BB*HH*NN];
__device__ float g_vs[BB*HH*NN*DH];
__device__ float g_vt[BB*HH*NN];
__device__ float g_cat[ROWS*DD];      // [B*N][513]

// ---------------------------------------------------------------------------
// Kernel 1: QKV projection GEMM (128x128 tile, 8x8 micro, FFMA2) + time attach
// ---------------------------------------------------------------------------
__global__ __launch_bounds__(256) void proj_kernel(
    const float* __restrict__ x,
    const float* __restrict__ Wq, const float* __restrict__ bq,
    const float* __restrict__ Wk, const float* __restrict__ bk,
    const float* __restrict__ Wv, const float* __restrict__ bv)
{
    __shared__ float As[16][132];
    __shared__ float Bs[16][132];

    const int tid = threadIdx.x;
    const int ty = tid >> 4;
    const int tx = tid & 15;
    const int row0 = blockIdx.x * 128;
    const int gy = blockIdx.y;
    const int mat = gy >> 2;
    const int h0 = (gy & 3) * 2;

    const float* W    = (mat == 0) ? Wq : ((mat == 1) ? Wk : Wv);
    const float* bias = (mat == 0) ? bq : ((mat == 1) ? bk : bv);
    float* outs       = (mat == 0) ? g_qs : ((mat == 1) ? g_ks : g_vs);
    float* outt       = (mat == 0) ? g_qt : ((mat == 1) ? g_kt : g_vt);

    u64 acc2[8][4] = {};

    for (int k0 = 0; k0 < DD; k0 += 16) {
        #pragma unroll
        for (int it = 0; it < 8; it++) {
            int lin = tid + it * 256;
            int r = lin >> 4, kk = lin & 15;
            int kg = k0 + kk;
            As[kk][r] = (kg < DD) ? x[(size_t)(row0 + r) * DD + kg] : 0.0f;
        }
        #pragma unroll
        for (int it = 0; it < 2; it++) {
            int lin = tid + it * 256;
            int kk = lin >> 5, c4 = lin & 31;
            int kg = k0 + kk;
            int c = c4 * 4;
            int h = h0 + (c >> 6), m = c & 63;
            float4 v = make_float4(0.f, 0.f, 0.f, 0.f);
            if (kg < DD) v = *(const float4*)&W[((size_t)h * DD + kg) * DH + m];
            *(float4*)&Bs[kk][c] = v;
        }
        __syncthreads();
        #pragma unroll
        for (int kk = 0; kk < 16; kk++) {
            float4 a0 = *(const float4*)&As[kk][ty * 8];
            float4 a1 = *(const float4*)&As[kk][ty * 8 + 4];
            float4 b0 = *(const float4*)&Bs[kk][tx * 8];
            float4 b1 = *(const float4*)&Bs[kk][tx * 8 + 4];
            u64 bp[4] = {pk2(b0.x, b0.y), pk2(b0.z, b0.w),
                         pk2(b1.x, b1.y), pk2(b1.z, b1.w)};
            float av[8] = {a0.x, a0.y, a0.z, a0.w, a1.x, a1.y, a1.z, a1.w};
            #pragma unroll
            for (int i = 0; i < 8; i++) {
                u64 ab = bc2(av[i]);
                #pragma unroll
                for (int p = 0; p < 4; p++) fma2(acc2[i][p], ab, bp[p]);
            }
        }
        __syncthreads();
    }

    const int h = h0 + (tx >> 3);
    const int m0 = (tx & 7) * 8;
    float4 bb0 = *(const float4*)&bias[h * DH + m0];
    float4 bb1 = *(const float4*)&bias[h * DH + m0 + 4];
    const float bbv[8] = {bb0.x, bb0.y, bb0.z, bb0.w, bb1.x, bb1.y, bb1.z, bb1.w};
    const float tsign = (mat == 0) ? -1.0f : 1.0f;

    #pragma unroll
    for (int i = 0; i < 8; i++) {
        float c[8];
        float2 u;
        u = up2(acc2[i][0]); c[0] = u.x + bbv[0]; c[1] = u.y + bbv[1];
        u = up2(acc2[i][1]); c[2] = u.x + bbv[2]; c[3] = u.y + bbv[3];
        u = up2(acc2[i][2]); c[4] = u.x + bbv[4]; c[5] = u.y + bbv[5];
        u = up2(acc2[i][3]); c[6] = u.x + bbv[6]; c[7] = u.y + bbv[7];
        float ss = 0.f;
        #pragma unroll
        for (int j = 0; j < 8; j++) ss += c[j] * c[j];
        ss += __shfl_xor_sync(0xffffffffu, ss, 1);
        ss += __shfl_xor_sync(0xffffffffu, ss, 2);
        ss += __shfl_xor_sync(0xffffffffu, ss, 4);
        int g = row0 + ty * 8 + i;
        int b = g >> 11, n = g & 2047;
        size_t bhn = (size_t)(b * HH + h) * NN + n;
        float* dst = &outs[bhn * DH + m0];
        #pragma unroll
        for (int j = 0; j < 8; j++) dst[j] = c[j];
        if ((tx & 7) == 0)
            outt[bhn] = tsign * sqrtf(fmaxf(INV_K + ss, EPS_F));
    }
}

// ---------------------------------------------------------------------------
// Kernel 2: flash attention on tensor cores (mma.sync m16n8k8 tf32).
// 128q x 128k tiles, 8 warps.
//   S phase:  S = (SCALE*Qs_tf32) . Ks_tf32 over 64 space dims via mma
//             + EXACT rank-1 time term (SCALE*qt)*kt folded at C-store.
//   PV phase: O^T = Vs_tf32^T . P^T via mma (V in natural [key][dim] layout).
// ---------------------------------------------------------------------------
#define AT_QS   0
#define AT_KS   (128*68)
#define AT_VS   (2*128*68)
#define AT_PT   (3*128*68)
#define AT_QT   (AT_PT + 128*132)
#define ATT_SMEM_FLOATS (AT_QT + 7*128)
#define ATT_SMEM_BYTES  (ATT_SMEM_FLOATS * 4)

__global__ __launch_bounds__(256, 1) void attn_kernel()
{
    extern __shared__ float sm[];
    float* Qs    = sm + AT_QS;    // [128][68] tf32(SCALE*q_space)
    float* Ks    = sm + AT_KS;    // [128][68] tf32(k_space)
    float* Vs    = sm + AT_VS;    // [128][68] tf32(v_space)
    float* Pt    = sm + AT_PT;    // [128 q][132]: scores/P; O^T at the end
    float* qts   = sm + AT_QT;    // [128] SCALE * (negated q time), fp32 exact
    float* kts   = qts + 128;     // [128] k time
    float* vtime = kts + 128;     // [128] v time
    float* mrow  = vtime + 128;   // [128]
    float* lrow  = mrow + 128;
    float* arow  = lrow + 128;
    float* otc   = arow + 128;

    const int tid  = threadIdx.x;
    const int lane = tid & 31;
    const int wid  = tid >> 5;
    const int lg   = lane >> 2;     // group id (0..7)
    const int lt   = lane & 3;      // thread-in-group (0..3)
    const int bh = blockIdx.y;
    const int q0 = blockIdx.x * 128;
    const int h = bh & 7, b = bh >> 3;

    // S-phase warp tiling: 2 (m=q) x 4 (n=key)
    const int s_qb = (wid >> 2) * 64;
    const int s_kb = (wid & 3) * 32;
    // PV-phase warp tiling: 2 (m=dim) x 4 (n=q)
    const int p_mb = (wid >> 2) * 32;   // dim base
    const int p_qb = (wid & 3) * 32;    // q base

    // ---- stage Q (once): tf32-rounded, pre-scaled ----
    const float* qsb = g_qs + ((size_t)bh * NN + q0) * DH;
    const float* qtb = g_qt + (size_t)bh * NN + q0;
    #pragma unroll
    for (int it = 0; it < 8; it++) {
        int lin = tid + it * 256;
        int r = lin >> 4, c4 = lin & 15;
        float4 v = *(const float4*)&qsb[r * DH + c4 * 4];
        float* d = &Qs[r * 68 + c4 * 4];
        d[0] = tf32r(v.x * SCALE_F); d[1] = tf32r(v.y * SCALE_F);
        d[2] = tf32r(v.z * SCALE_F); d[3] = tf32r(v.w * SCALE_F);
    }
    if (tid < 128) {
        qts[tid] = qtb[tid] * SCALE_F;       // exact (fp32), already negated
        mrow[tid] = -1e30f; lrow[tid] = 0.0f; otc[tid] = 0.0f;
    }

    float o[2][4][4] = {};   // persistent O^T frags: [m-tile][n-tile][reg]

    const float* ksb = g_ks + (size_t)bh * NN * DH;
    const float* ktb = g_kt + (size_t)bh * NN;
    const float* vsb = g_vs + (size_t)bh * NN * DH;
    const float* vtb = g_vt + (size_t)bh * NN;

    #pragma unroll 1
    for (int kt = 0; kt < NN / 128; kt++) {
        __syncthreads();
        const float* kp_ = ksb + (size_t)kt * 128 * DH;
        const float* vp_ = vsb + (size_t)kt * 128 * DH;
        #pragma unroll
        for (int it = 0; it < 8; it++) {
            int lin = tid + it * 256;
            int r = lin >> 4, c4 = lin & 15;
            float4 kv = *(const float4*)&kp_[r * DH + c4 * 4];
            float* kd = &Ks[r * 68 + c4 * 4];
            kd[0] = tf32r(kv.x); kd[1] = tf32r(kv.y);
            kd[2] = tf32r(kv.z); kd[3] = tf32r(kv.w);
            float4 vv = *(const float4*)&vp_[r * DH + c4 * 4];
            float* vd = &Vs[r * 68 + c4 * 4];
            vd[0] = tf32r(vv.x); vd[1] = tf32r(vv.y);
            vd[2] = tf32r(vv.z); vd[3] = tf32r(vv.w);
        }
        if (tid < 128) {
            kts[tid]   = ktb[kt * 128 + tid];
            vtime[tid] = vtb[kt * 128 + tid];
        }
        __syncthreads();

        // ======== S phase: mma over 64 space dims ========
        {
            float sc[4][4][4];
            #pragma unroll
            for (int mi = 0; mi < 4; mi++)
                #pragma unroll
                for (int ni = 0; ni < 4; ni++)
                    #pragma unroll
                    for (int r = 0; r < 4; r++) sc[mi][ni][r] = 0.0f;

            #pragma unroll
            for (int ks = 0; ks < 8; ks++) {
                unsigned a[4][4];
                #pragma unroll
                for (int mi = 0; mi < 4; mi++) {
                    const float* ap = &Qs[(s_qb + 16 * mi + lg) * 68 + ks * 8 + lt];
                    a[mi][0] = fu(ap[0]);
                    a[mi][1] = fu(ap[8 * 68]);
                    a[mi][2] = fu(ap[4]);
                    a[mi][3] = fu(ap[8 * 68 + 4]);
                }
                unsigned bf[4][2];
                #pragma unroll
                for (int ni = 0; ni < 4; ni++) {
                    const float* bp = &Ks[(s_kb + 8 * ni + lg) * 68 + ks * 8 + lt];
                    bf[ni][0] = fu(bp[0]);
                    bf[ni][1] = fu(bp[4]);
                }
                #pragma unroll
                for (int mi = 0; mi < 4; mi++)
                    #pragma unroll
                    for (int ni = 0; ni < 4; ni++)
                        mma_tf32(sc[mi][ni], a[mi][0], a[mi][1], a[mi][2], a[mi][3],
                                 bf[ni][0], bf[ni][1]);
            }

            // exact time-term fold + store to Pt
            #pragma unroll
            for (int mi = 0; mi < 4; mi++) {
                int qr = s_qb + 16 * mi + lg;
                float qt0 = qts[qr], qt8 = qts[qr + 8];
                #pragma unroll
                for (int ni = 0; ni < 4; ni++) {
                    int kc = s_kb + 8 * ni + 2 * lt;
                    float kt0 = kts[kc], kt1 = kts[kc + 1];
                    float c0 = sc[mi][ni][0] + qt0 * kt0;
                    float c1 = sc[mi][ni][1] + qt0 * kt1;
                    float c2 = sc[mi][ni][2] + qt8 * kt0;
                    float c3 = sc[mi][ni][3] + qt8 * kt1;
                    *(float2*)&Pt[qr * 132 + kc]       = make_float2(c0, c1);
                    *(float2*)&Pt[(qr + 8) * 132 + kc] = make_float2(c2, c3);
                }
            }
        }
        __syncthreads();

        // ======== online softmax over 128 keys (2 threads/row) ========
        {
            int r = tid >> 1, part = tid & 1;
            float* prow = &Pt[r * 132 + part * 64];
            float mo = mrow[r];
            float mx = -1e30f;
            #pragma unroll
            for (int jf = 0; jf < 16; jf++) {
                float4 p = *(const float4*)&prow[jf * 4];
                mx = fmaxf(mx, fmaxf(fmaxf(p.x, p.y), fmaxf(p.z, p.w)));
            }
            mx = fmaxf(mx, __shfl_xor_sync(0xffffffffu, mx, 1));
            float mn = fmaxf(mo, mx);
            float sum = 0.f, tsum = 0.f;
            #pragma unroll
            for (int jf = 0; jf < 16; jf++) {
                float4 p = *(float4*)&prow[jf * 4];
                float e0 = __expf(p.x - mn), e1 = __expf(p.y - mn);
                float e2 = __expf(p.z - mn), e3 = __expf(p.w - mn);
                *(float4*)&prow[jf * 4] = make_float4(e0, e1, e2, e3);
                sum += (e0 + e1) + (e2 + e3);
                int kk = part * 64 + jf * 4;
                tsum += e0 * vtime[kk] + e1 * vtime[kk + 1]
                      + e2 * vtime[kk + 2] + e3 * vtime[kk + 3];
            }
            sum  += __shfl_xor_sync(0xffffffffu, sum, 1);
            tsum += __shfl_xor_sync(0xffffffffu, tsum, 1);
            if (part == 0) {
                float al = __expf(mo - mn);
                arow[r] = al;
                lrow[r] = lrow[r] * al + sum;
                otc[r]  = otc[r] * al + tsum;
                mrow[r] = mn;
            }
        }
        __syncthreads();

        // ======== PV phase: O^T = O^T*alpha + V^T . P^T via mma ========
        {
            #pragma unroll
            for (int ni = 0; ni < 4; ni++) {
                int qc = p_qb + 8 * ni + 2 * lt;
                float a0 = arow[qc], a1 = arow[qc + 1];
                #pragma unroll
                for (int fi = 0; fi < 2; fi++) {
                    o[fi][ni][0] *= a0; o[fi][ni][1] *= a1;
                    o[fi][ni][2] *= a0; o[fi][ni][3] *= a1;
                }
            }
            #pragma unroll
            for (int ks = 0; ks < 16; ks++) {
                unsigned a[2][4];
                #pragma unroll
                for (int fi = 0; fi < 2; fi++) {
                    const float* ap = &Vs[(ks * 8 + lt) * 68 + p_mb + 16 * fi + lg];
                    a[fi][0] = fu(ap[0]);
                    a[fi][1] = fu(ap[8]);
                    a[fi][2] = fu(ap[4 * 68]);
                    a[fi][3] = fu(ap[4 * 68 + 8]);
                }
                unsigned bf[4][2];
                #pragma unroll
                for (int ni = 0; ni < 4; ni++) {
                    const float* bp = &Pt[(p_qb + 8 * ni + lg) * 132 + ks * 8 + lt];
                    bf[ni][0] = fu(bp[0]);
                    bf[ni][1] = fu(bp[4]);
                }
                #pragma unroll
                for (int fi = 0; fi < 2; fi++)
                    #pragma unroll
                    for (int ni = 0; ni < 4; ni++)
                        mma_tf32(o[fi][ni], a[fi][0], a[fi][1], a[fi][2], a[fi][3],
                                 bf[ni][0], bf[ni][1]);
            }
        }
    }
    __syncthreads();   // all PV reads of Pt done before overwriting with O^T

    // ---- stage O^T into Pt as [q][dim] ----
    #pragma unroll
    for (int fi = 0; fi < 2; fi++) {
        #pragma unroll
        for (int ni = 0; ni < 4; ni++) {
            int mr = p_mb + 16 * fi + lg;
            int qc = p_qb + 8 * ni + 2 * lt;
            Pt[qc * 132 + mr]           = o[fi][ni][0];
            Pt[(qc + 1) * 132 + mr]     = o[fi][ni][1];
            Pt[qc * 132 + mr + 8]       = o[fi][ni][2];
            Pt[(qc + 1) * 132 + mr + 8] = o[fi][ni][3];
        }
    }
    __syncthreads();

    // ---- epilogue: normalize, Lorentz midpoint factor, head-concat write ----
    // (g_cat stores are SCALAR: row stride 513 floats is odd -> not 16B aligned)
    {
        int q = tid >> 1, half = tid & 1;
        float invl = 1.0f / lrow[q];
        const float* orow = &Pt[q * 132 + half * 32];
        float c[32];
        float ss = 0.f;
        #pragma unroll
        for (int jf = 0; jf < 8; jf++) {
            float4 p = *(const float4*)&orow[jf * 4];
            c[jf * 4 + 0] = p.x * invl; c[jf * 4 + 1] = p.y * invl;
            c[jf * 4 + 2] = p.z * invl; c[jf * 4 + 3] = p.w * invl;
            ss += c[jf*4]*c[jf*4] + c[jf*4+1]*c[jf*4+1]
                + c[jf*4+2]*c[jf*4+2] + c[jf*4+3]*c[jf*4+3];
        }
        ss += __shfl_xor_sync(0xffffffffu, ss, 1);   // combine halves
        float t = otc[q] * invl;
        float fac = rsqrtf(fmaxf(-K_CURV * (ss - t * t), EPS_F));
        float* dst = &g_cat[(size_t)(b * NN + q0 + q) * DD + 1 + h * DH + half * 32];
        #pragma unroll
        for (int j = 0; j < 32; j++) dst[j] = c[j] * fac;
    }
}

// ---------------------------------------------------------------------------
// Kernel 3/5: per-row time attach
// ---------------------------------------------------------------------------
__global__ void rowtime_kernel(float* outp, int which)
{
    float* buf = which ? g_cat : outp;
    int warp = (blockIdx.x * blockDim.x + threadIdx.x) >> 5;
    int lane = threadIdx.x & 31;
    if (warp >= ROWS) return;
    const float* row = buf + (size_t)warp * DD + 1;
    float s = 0.0f;
    #pragma unroll
    for (int c = lane; c < 512; c += 32) {
        float v = row[c];
        s += v * v;
    }
    #pragma unroll
    for (int off = 16; off; off >>= 1)
        s += __shfl_xor_sync(0xffffffffu, s, off);
    if (lane == 0) buf[(size_t)warp * DD] = sqrtf(fmaxf(INV_K + s, EPS_F));
}

// ---------------------------------------------------------------------------
// Kernel 4: output GEMM, double-buffered, 128x128 tile, 8x8 micro
// ---------------------------------------------------------------------------
__global__ __launch_bounds__(256, 2) void outproj_kernel(
    const float* __restrict__ Wo, const float* __restrict__ bo,
    float* __restrict__ outp)
{
    __shared__ float As[2][16][132];
    __shared__ float Bs[2][16][132];

    const int tid = threadIdx.x;
    const int ty = tid >> 4;
    const int tx = tid & 15;
    const int row0 = blockIdx.x * 128;
    const int col0 = blockIdx.y * 128;

    u64 acc2[8][4] = {};

    #pragma unroll
    for (int it = 0; it < 8; it++) {
        int lin = tid + it * 256;
        int r = lin >> 4, kk = lin & 15;
        As[0][kk][r] = g_cat[(size_t)(row0 + r) * DD + kk];
    }
    #pragma unroll
    for (int it = 0; it < 2; it++) {
        int lin = tid + it * 256;
        int kk = lin >> 5, c4 = lin & 31;
        float4 v = *(const float4*)&Wo[(size_t)kk * 512 + col0 + c4 * 4];
        *(float4*)&Bs[0][kk][c4 * 4] = v;
    }
    __syncthreads();

    int buf = 0;
    for (int k0 = 0; k0 < DD; k0 += 16, buf ^= 1) {
        const bool more = (k0 + 16) < DD;
        float ra[8];
        float4 rb[2];
        if (more) {
            #pragma unroll
            for (int it = 0; it < 8; it++) {
                int lin = tid + it * 256;
                int r = lin >> 4, kk = lin & 15;
                int kg = k0 + 16 + kk;
                ra[it] = (kg < DD) ? g_cat[(size_t)(row0 + r) * DD + kg] : 0.0f;
            }
            #pragma unroll
            for (int it = 0; it < 2; it++) {
                int lin = tid + it * 256;
                int kk = lin >> 5, c4 = lin & 31;
                int kg = k0 + 16 + kk;
                float4 v = make_float4(0.f, 0.f, 0.f, 0.f);
                if (kg < DD) v = *(const float4*)&Wo[(size_t)kg * 512 + col0 + c4 * 4];
                rb[it] = v;
            }
        }
        #pragma unroll
        for (int kk = 0; kk < 16; kk++) {
            float4 a0 = *(const float4*)&As[buf][kk][ty * 8];
            float4 a1 = *(const float4*)&As[buf][kk][ty * 8 + 4];
            float4 b0 = *(const float4*)&Bs[buf][kk][tx * 8];
            float4 b1 = *(const float4*)&Bs[buf][kk][tx * 8 + 4];
            u64 bp[4] = {pk2(b0.x, b0.y), pk2(b0.z, b0.w),
                         pk2(b1.x, b1.y), pk2(b1.z, b1.w)};
            float av[8] = {a0.x, a0.y, a0.z, a0.w, a1.x, a1.y, a1.z, a1.w};
            #pragma unroll
            for (int i = 0; i < 8; i++) {
                u64 ab = bc2(av[i]);
                #pragma unroll
                for (int p = 0; p < 4; p++) fma2(acc2[i][p], ab, bp[p]);
            }
        }
        if (more) {
            #pragma unroll
            for (int it = 0; it < 8; it++) {
                int lin = tid + it * 256;
                int r = lin >> 4, kk = lin & 15;
                As[buf ^ 1][kk][r] = ra[it];
            }
            #pragma unroll
            for (int it = 0; it < 2; it++) {
                int lin = tid + it * 256;
                int kk = lin >> 5, c4 = lin & 31;
                *(float4*)&Bs[buf ^ 1][kk][c4 * 4] = rb[it];
            }
        }
        __syncthreads();
    }

    float4 bb0 = *(const float4*)&bo[col0 + tx * 8];
    float4 bb1 = *(const float4*)&bo[col0 + tx * 8 + 4];
    const float bbv[8] = {bb0.x, bb0.y, bb0.z, bb0.w, bb1.x, bb1.y, bb1.z, bb1.w};
    #pragma unroll
    for (int i = 0; i < 8; i++) {
        float c[8];
        float2 u;
        u = up2(acc2[i][0]); c[0] = u.x; c[1] = u.y;
        u = up2(acc2[i][1]); c[2] = u.x; c[3] = u.y;
        u = up2(acc2[i][2]); c[4] = u.x; c[5] = u.y;
        u = up2(acc2[i][3]); c[6] = u.x; c[7] = u.y;
        float* dst = &outp[(size_t)(row0 + ty * 8 + i) * DD + 1 + col0 + tx * 8];
        #pragma unroll
        for (int j = 0; j < 8; j++) dst[j] = c[j] + bbv[j];
    }
}

// ---------------------------------------------------------------------------
extern "C" void kernel_launch(void* const* d_in, const int* in_sizes, int n_in,
                              void* d_out, int out_size)
{
    const float* x  = (const float*)d_in[0];
    const float* Wq = (const float*)d_in[1];
    const float* bq = (const float*)d_in[2];
    const float* Wk = (const float*)d_in[3];
    const float* bk = (const float*)d_in[4];
    const float* Wv = (const float*)d_in[5];
    const float* bv = (const float*)d_in[6];
    const float* Wo = (const float*)d_in[7];
    const float* bo = (const float*)d_in[8];
    float* outp = (float*)d_out;

    cudaFuncSetAttribute(attn_kernel,
                         cudaFuncAttributeMaxDynamicSharedMemorySize,
                         ATT_SMEM_BYTES);

    proj_kernel<<<dim3(ROWS / 128, 12), 256>>>(x, Wq, bq, Wk, bk, Wv, bv);
    attn_kernel<<<dim3(NN / 128, BB * HH), 256, ATT_SMEM_BYTES>>>();
    rowtime_kernel<<<ROWS / 8, 256>>>(nullptr, 1);
    outproj_kernel<<<dim3(ROWS / 128, 4), 256>>>(Wo, bo, outp);
    rowtime_kernel<<<ROWS / 8, 256>>>(outp, 0);
}

// round 11
// speedup vs baseline: 2.0237x; 1.1127x over previous
#include <cuda_runtime.h>
#include <math.h>

// Problem dims
#define BB   4
#define NN   2048
#define DD   513
#define HH   8
#define DH   64
#define ROWS (BB*NN)       // 8192

#define INV_K   10.0f
#define K_CURV  0.1f
#define EPS_F   1e-9f
#define SCALE_F 0.125f     // 1/sqrt(64)

// ---------------------------------------------------------------------------
// tf32 mma helpers
// ---------------------------------------------------------------------------
__device__ __forceinline__ float tf32r(float x) {
    unsigned u; asm("cvt.rna.tf32.f32 %0, %1;" : "=r"(u) : "f"(x));
    return __uint_as_float(u);
}
__device__ __forceinline__ void mma_tf32(float c[4],
    unsigned a0, unsigned a1, unsigned a2, unsigned a3,
    unsigned b0, unsigned b1)
{
    asm("mma.sync.aligned.m16n8k8.row.col.f32.tf32.tf32.f32 "
        "{%0,%1,%2,%3},{%4,%5,%6,%7},{%8,%9},{%0,%1,%2,%3};"
        : "+f"(c[0]), "+f"(c[1]), "+f"(c[2]), "+f"(c[3])
        : "r"(a0), "r"(a1), "r"(a2), "r"(a3), "r"(b0), "r"(b1));
}
__device__ __forceinline__ unsigned fu(float x) { return __float_as_uint(x); }

// Scratch (device globals: allocation-free per harness rules)
__device__ float g_qs[BB*HH*NN*DH];   // q space
__device__ float g_qt[BB*HH*NN];      // q time, NEGATED
__device__ float g_ks[BB*HH*NN*DH];
__device__ float g_kt[BB*HH*NN];
__device__ float g_vs[BB*HH*NN*DH];
__device__ float g_vt[BB*HH*NN];
__device__ float g_cat[ROWS*DD];      // [B*N][513]

// ---------------------------------------------------------------------------
// Shared GEMM-on-tensor-core layout constants (proj & outproj)
// A (inputs) staged [row][k16] hi/lo at stride 20  -> (20*lg+lt)%32 perfect
// B (weights) staged [k16][col128] hi/lo at stride 136 (=8 mod 32) -> perfect
// ---------------------------------------------------------------------------
#define GA_STRIDE 20
#define GB_STRIDE 136
#define G_ASH 0
#define G_ASL (128*GA_STRIDE)
#define G_BSH (2*128*GA_STRIDE)
#define G_BSL (2*128*GA_STRIDE + 16*GB_STRIDE)
#define G_SMEM_FLOATS (2*128*GA_STRIDE + 2*16*GB_STRIDE)   // 9472
#define PJ_SMEM_FLOATS (128*132 > G_SMEM_FLOATS ? 128*132 : G_SMEM_FLOATS)
#define PJ_SMEM_BYTES  (PJ_SMEM_FLOATS * 4)                // 67584 (Cs reuse)

// ---------------------------------------------------------------------------
// Kernel 1: QKV projection on tensor cores, 3-pass tf32 split (≈fp32 exact).
// C tile 128 rows x 128 cols (2 heads). 8 warps = 2(m64) x 4(n32).
// Epilogue: stage C to smem, per-(row,head) bias + sumsq + time attach.
// ---------------------------------------------------------------------------
__global__ __launch_bounds__(256) void proj_kernel(
    const float* __restrict__ x,
    const float* __restrict__ Wq, const float* __restrict__ bq,
    const float* __restrict__ Wk, const float* __restrict__ bk,
    const float* __restrict__ Wv, const float* __restrict__ bv)
{
    extern __shared__ float psm[];
    float* Ash = psm + G_ASH;
    float* Asl = psm + G_ASL;
    float* Bsh = psm + G_BSH;
    float* Bsl = psm + G_BSL;

    const int tid  = threadIdx.x;
    const int lane = tid & 31;
    const int wid  = tid >> 5;
    const int lg   = lane >> 2;
    const int lt   = lane & 3;
    const int row0 = blockIdx.x * 128;
    const int gy = blockIdx.y;
    const int mat = gy >> 2;
    const int h0 = (gy & 3) * 2;

    const float* W    = (mat == 0) ? Wq : ((mat == 1) ? Wk : Wv);
    const float* bias = (mat == 0) ? bq : ((mat == 1) ? bk : bv);
    float* outs       = (mat == 0) ? g_qs : ((mat == 1) ? g_ks : g_vs);
    float* outt       = (mat == 0) ? g_qt : ((mat == 1) ? g_kt : g_vt);

    const int mb = (wid >> 2) * 64;
    const int nb = (wid & 3) * 32;

    float acc[4][4][4] = {};

    #pragma unroll 1
    for (int k0 = 0; k0 < DD; k0 += 16) {
        __syncthreads();
        // stage A hi/lo: x[128 rows][16 k]
        #pragma unroll
        for (int it = 0; it < 8; it++) {
            int lin = tid + it * 256;
            int r = lin >> 4, kk = lin & 15;
            int kg = k0 + kk;
            float v = (kg < DD) ? x[(size_t)(row0 + r) * DD + kg] : 0.0f;
            float hi = tf32r(v);
            Ash[r * GA_STRIDE + kk] = hi;
            Asl[r * GA_STRIDE + kk] = tf32r(v - hi);
        }
        // stage B hi/lo: W[16 k][128 cols] (2 heads)
        #pragma unroll
        for (int it = 0; it < 2; it++) {
            int lin = tid + it * 256;
            int kk = lin >> 5, c4 = lin & 31;
            int kg = k0 + kk;
            int c = c4 * 4;
            int h = h0 + (c >> 6), m = c & 63;
            float4 v = make_float4(0.f, 0.f, 0.f, 0.f);
            if (kg < DD) v = *(const float4*)&W[((size_t)h * DD + kg) * DH + m];
            float4 hi = make_float4(tf32r(v.x), tf32r(v.y), tf32r(v.z), tf32r(v.w));
            float4 lo = make_float4(tf32r(v.x - hi.x), tf32r(v.y - hi.y),
                                    tf32r(v.z - hi.z), tf32r(v.w - hi.w));
            *(float4*)&Bsh[kk * GB_STRIDE + c] = hi;
            *(float4*)&Bsl[kk * GB_STRIDE + c] = lo;
        }
        __syncthreads();

        #pragma unroll
        for (int ks = 0; ks < 2; ks++) {
            unsigned bh_[4][2], bl_[4][2];
            #pragma unroll
            for (int ni = 0; ni < 4; ni++) {
                const float* bp = &Bsh[(ks * 8 + lt) * GB_STRIDE + nb + 8 * ni + lg];
                bh_[ni][0] = fu(bp[0]);
                bh_[ni][1] = fu(bp[4 * GB_STRIDE]);
                const float* bq_ = &Bsl[(ks * 8 + lt) * GB_STRIDE + nb + 8 * ni + lg];
                bl_[ni][0] = fu(bq_[0]);
                bl_[ni][1] = fu(bq_[4 * GB_STRIDE]);
            }
            #pragma unroll
            for (int mi = 0; mi < 4; mi++) {
                const float* ap = &Ash[(mb + 16 * mi + lg) * GA_STRIDE + ks * 8 + lt];
                unsigned ah0 = fu(ap[0]), ah1 = fu(ap[8 * GA_STRIDE]);
                unsigned ah2 = fu(ap[4]), ah3 = fu(ap[8 * GA_STRIDE + 4]);
                const float* aq = &Asl[(mb + 16 * mi + lg) * GA_STRIDE + ks * 8 + lt];
                unsigned al0 = fu(aq[0]), al1 = fu(aq[8 * GA_STRIDE]);
                unsigned al2 = fu(aq[4]), al3 = fu(aq[8 * GA_STRIDE + 4]);
                #pragma unroll
                for (int ni = 0; ni < 4; ni++) {
                    mma_tf32(acc[mi][ni], ah0, ah1, ah2, ah3, bh_[ni][0], bh_[ni][1]);
                    mma_tf32(acc[mi][ni], ah0, ah1, ah2, ah3, bl_[ni][0], bl_[ni][1]);
                    mma_tf32(acc[mi][ni], al0, al1, al2, al3, bh_[ni][0], bh_[ni][1]);
                }
            }
        }
    }
    __syncthreads();

    // stage C (raw, no bias yet) to Cs[128][132]
    float* Cs = psm;
    #pragma unroll
    for (int mi = 0; mi < 4; mi++) {
        #pragma unroll
        for (int ni = 0; ni < 4; ni++) {
            int row = mb + 16 * mi + lg;
            int col = nb + 8 * ni + 2 * lt;
            *(float2*)&Cs[row * 132 + col]       = make_float2(acc[mi][ni][0], acc[mi][ni][1]);
            *(float2*)&Cs[(row + 8) * 132 + col] = make_float2(acc[mi][ni][2], acc[mi][ni][3]);
        }
    }
    __syncthreads();

    // epilogue: one thread per (row, head): bias, sumsq, time attach, write
    {
        int r = tid >> 1, hh = tid & 1;
        int h = h0 + hh;
        const float tsign = (mat == 0) ? -1.0f : 1.0f;
        float c[64];
        float ss = 0.f;
        #pragma unroll
        for (int j4 = 0; j4 < 16; j4++) {
            float4 cv = *(const float4*)&Cs[r * 132 + hh * 64 + j4 * 4];
            float4 bb = *(const float4*)&bias[h * DH + j4 * 4];
            float v0 = cv.x + bb.x, v1 = cv.y + bb.y;
            float v2 = cv.z + bb.z, v3 = cv.w + bb.w;
            c[j4 * 4 + 0] = v0; c[j4 * 4 + 1] = v1;
            c[j4 * 4 + 2] = v2; c[j4 * 4 + 3] = v3;
            ss += v0 * v0 + v1 * v1 + v2 * v2 + v3 * v3;
        }
        int g = row0 + r;
        int b = g >> 11, n = g & 2047;
        size_t bhn = (size_t)(b * HH + h) * NN + n;
        float* dst = &outs[bhn * DH];
        #pragma unroll
        for (int j4 = 0; j4 < 16; j4++)
            *(float4*)&dst[j4 * 4] = make_float4(c[j4*4], c[j4*4+1], c[j4*4+2], c[j4*4+3]);
        outt[bhn] = tsign * sqrtf(fmaxf(INV_K + ss, EPS_F));
    }
}

// ---------------------------------------------------------------------------
// Kernel 2: flash attention on tensor cores (UNCHANGED from R10 passing best)
// ---------------------------------------------------------------------------
#define AT_QS   0
#define AT_KS   (128*68)
#define AT_VS   (2*128*68)
#define AT_PT   (3*128*68)
#define AT_QT   (AT_PT + 128*132)
#define ATT_SMEM_FLOATS (AT_QT + 7*128)
#define ATT_SMEM_BYTES  (ATT_SMEM_FLOATS * 4)

__global__ __launch_bounds__(256, 1) void attn_kernel()
{
    extern __shared__ float sm[];
    float* Qs    = sm + AT_QS;
    float* Ks    = sm + AT_KS;
    float* Vs    = sm + AT_VS;
    float* Pt    = sm + AT_PT;
    float* qts   = sm + AT_QT;
    float* kts   = qts + 128;
    float* vtime = kts + 128;
    float* mrow  = vtime + 128;
    float* lrow  = mrow + 128;
    float* arow  = lrow + 128;
    float* otc   = arow + 128;

    const int tid  = threadIdx.x;
    const int lane = tid & 31;
    const int wid  = tid >> 5;
    const int lg   = lane >> 2;
    const int lt   = lane & 3;
    const int bh = blockIdx.y;
    const int q0 = blockIdx.x * 128;
    const int h = bh & 7, b = bh >> 3;

    const int s_qb = (wid >> 2) * 64;
    const int s_kb = (wid & 3) * 32;
    const int p_mb = (wid >> 2) * 32;
    const int p_qb = (wid & 3) * 32;

    const float* qsb = g_qs + ((size_t)bh * NN + q0) * DH;
    const float* qtb = g_qt + (size_t)bh * NN + q0;
    #pragma unroll
    for (int it = 0; it < 8; it++) {
        int lin = tid + it * 256;
        int r = lin >> 4, c4 = lin & 15;
        float4 v = *(const float4*)&qsb[r * DH + c4 * 4];
        float* d = &Qs[r * 68 + c4 * 4];
        d[0] = tf32r(v.x * SCALE_F); d[1] = tf32r(v.y * SCALE_F);
        d[2] = tf32r(v.z * SCALE_F); d[3] = tf32r(v.w * SCALE_F);
    }
    if (tid < 128) {
        qts[tid] = qtb[tid] * SCALE_F;
        mrow[tid] = -1e30f; lrow[tid] = 0.0f; otc[tid] = 0.0f;
    }

    float o[2][4][4] = {};

    const float* ksb = g_ks + (size_t)bh * NN * DH;
    const float* ktb = g_kt + (size_t)bh * NN;
    const float* vsb = g_vs + (size_t)bh * NN * DH;
    const float* vtb = g_vt + (size_t)bh * NN;

    #pragma unroll 1
    for (int kt = 0; kt < NN / 128; kt++) {
        __syncthreads();
        const float* kp_ = ksb + (size_t)kt * 128 * DH;
        const float* vp_ = vsb + (size_t)kt * 128 * DH;
        #pragma unroll
        for (int it = 0; it < 8; it++) {
            int lin = tid + it * 256;
            int r = lin >> 4, c4 = lin & 15;
            float4 kv = *(const float4*)&kp_[r * DH + c4 * 4];
            float* kd = &Ks[r * 68 + c4 * 4];
            kd[0] = tf32r(kv.x); kd[1] = tf32r(kv.y);
            kd[2] = tf32r(kv.z); kd[3] = tf32r(kv.w);
            float4 vv = *(const float4*)&vp_[r * DH + c4 * 4];
            float* vd = &Vs[r * 68 + c4 * 4];
            vd[0] = tf32r(vv.x); vd[1] = tf32r(vv.y);
            vd[2] = tf32r(vv.z); vd[3] = tf32r(vv.w);
        }
        if (tid < 128) {
            kts[tid]   = ktb[kt * 128 + tid];
            vtime[tid] = vtb[kt * 128 + tid];
        }
        __syncthreads();

        {
            float sc[4][4][4];
            #pragma unroll
            for (int mi = 0; mi < 4; mi++)
                #pragma unroll
                for (int ni = 0; ni < 4; ni++)
                    #pragma unroll
                    for (int r = 0; r < 4; r++) sc[mi][ni][r] = 0.0f;

            #pragma unroll
            for (int ks = 0; ks < 8; ks++) {
                unsigned a[4][4];
                #pragma unroll
                for (int mi = 0; mi < 4; mi++) {
                    const float* ap = &Qs[(s_qb + 16 * mi + lg) * 68 + ks * 8 + lt];
                    a[mi][0] = fu(ap[0]);
                    a[mi][1] = fu(ap[8 * 68]);
                    a[mi][2] = fu(ap[4]);
                    a[mi][3] = fu(ap[8 * 68 + 4]);
                }
                unsigned bf[4][2];
                #pragma unroll
                for (int ni = 0; ni < 4; ni++) {
                    const float* bp = &Ks[(s_kb + 8 * ni + lg) * 68 + ks * 8 + lt];
                    bf[ni][0] = fu(bp[0]);
                    bf[ni][1] = fu(bp[4]);
                }
                #pragma unroll
                for (int mi = 0; mi < 4; mi++)
                    #pragma unroll
                    for (int ni = 0; ni < 4; ni++)
                        mma_tf32(sc[mi][ni], a[mi][0], a[mi][1], a[mi][2], a[mi][3],
                                 bf[ni][0], bf[ni][1]);
            }

            #pragma unroll
            for (int mi = 0; mi < 4; mi++) {
                int qr = s_qb + 16 * mi + lg;
                float qt0 = qts[qr], qt8 = qts[qr + 8];
                #pragma unroll
                for (int ni = 0; ni < 4; ni++) {
                    int kc = s_kb + 8 * ni + 2 * lt;
                    float kt0 = kts[kc], kt1 = kts[kc + 1];
                    float c0 = sc[mi][ni][0] + qt0 * kt0;
                    float c1 = sc[mi][ni][1] + qt0 * kt1;
                    float c2 = sc[mi][ni][2] + qt8 * kt0;
                    float c3 = sc[mi][ni][3] + qt8 * kt1;
                    *(float2*)&Pt[qr * 132 + kc]       = make_float2(c0, c1);
                    *(float2*)&Pt[(qr + 8) * 132 + kc] = make_float2(c2, c3);
                }
            }
        }
        __syncthreads();

        {
            int r = tid >> 1, part = tid & 1;
            float* prow = &Pt[r * 132 + part * 64];
            float mo = mrow[r];
            float mx = -1e30f;
            #pragma unroll
            for (int jf = 0; jf < 16; jf++) {
                float4 p = *(const float4*)&prow[jf * 4];
                mx = fmaxf(mx, fmaxf(fmaxf(p.x, p.y), fmaxf(p.z, p.w)));
            }
            mx = fmaxf(mx, __shfl_xor_sync(0xffffffffu, mx, 1));
            float mn = fmaxf(mo, mx);
            float sum = 0.f, tsum = 0.f;
            #pragma unroll
            for (int jf = 0; jf < 16; jf++) {
                float4 p = *(float4*)&prow[jf * 4];
                float e0 = __expf(p.x - mn), e1 = __expf(p.y - mn);
                float e2 = __expf(p.z - mn), e3 = __expf(p.w - mn);
                *(float4*)&prow[jf * 4] = make_float4(e0, e1, e2, e3);
                sum += (e0 + e1) + (e2 + e3);
                int kk = part * 64 + jf * 4;
                tsum += e0 * vtime[kk] + e1 * vtime[kk + 1]
                      + e2 * vtime[kk + 2] + e3 * vtime[kk + 3];
            }
            sum  += __shfl_xor_sync(0xffffffffu, sum, 1);
            tsum += __shfl_xor_sync(0xffffffffu, tsum, 1);
            if (part == 0) {
                float al = __expf(mo - mn);
                arow[r] = al;
                lrow[r] = lrow[r] * al + sum;
                otc[r]  = otc[r] * al + tsum;
                mrow[r] = mn;
            }
        }
        __syncthreads();

        {
            #pragma unroll
            for (int ni = 0; ni < 4; ni++) {
                int qc = p_qb + 8 * ni + 2 * lt;
                float a0 = arow[qc], a1 = arow[qc + 1];
                #pragma unroll
                for (int fi = 0; fi < 2; fi++) {
                    o[fi][ni][0] *= a0; o[fi][ni][1] *= a1;
                    o[fi][ni][2] *= a0; o[fi][ni][3] *= a1;
                }
            }
            #pragma unroll
            for (int ks = 0; ks < 16; ks++) {
                unsigned a[2][4];
                #pragma unroll
                for (int fi = 0; fi < 2; fi++) {
                    const float* ap = &Vs[(ks * 8 + lt) * 68 + p_mb + 16 * fi + lg];
                    a[fi][0] = fu(ap[0]);
                    a[fi][1] = fu(ap[8]);
                    a[fi][2] = fu(ap[4 * 68]);
                    a[fi][3] = fu(ap[4 * 68 + 8]);
                }
                unsigned bf[4][2];
                #pragma unroll
                for (int ni = 0; ni < 4; ni++) {
                    const float* bp = &Pt[(p_qb + 8 * ni + lg) * 132 + ks * 8 + lt];
                    bf[ni][0] = fu(bp[0]);
                    bf[ni][1] = fu(bp[4]);
                }
                #pragma unroll
                for (int fi = 0; fi < 2; fi++)
                    #pragma unroll
                    for (int ni = 0; ni < 4; ni++)
                        mma_tf32(o[fi][ni], a[fi][0], a[fi][1], a[fi][2], a[fi][3],
                                 bf[ni][0], bf[ni][1]);
            }
        }
    }
    __syncthreads();

    #pragma unroll
    for (int fi = 0; fi < 2; fi++) {
        #pragma unroll
        for (int ni = 0; ni < 4; ni++) {
            int mr = p_mb + 16 * fi + lg;
            int qc = p_qb + 8 * ni + 2 * lt;
            Pt[qc * 132 + mr]           = o[fi][ni][0];
            Pt[(qc + 1) * 132 + mr]     = o[fi][ni][1];
            Pt[qc * 132 + mr + 8]       = o[fi][ni][2];
            Pt[(qc + 1) * 132 + mr + 8] = o[fi][ni][3];
        }
    }
    __syncthreads();

    {
        int q = tid >> 1, half = tid & 1;
        float invl = 1.0f / lrow[q];
        const float* orow = &Pt[q * 132 + half * 32];
        float c[32];
        float ss = 0.f;
        #pragma unroll
        for (int jf = 0; jf < 8; jf++) {
            float4 p = *(const float4*)&orow[jf * 4];
            c[jf * 4 + 0] = p.x * invl; c[jf * 4 + 1] = p.y * invl;
            c[jf * 4 + 2] = p.z * invl; c[jf * 4 + 3] = p.w * invl;
            ss += c[jf*4]*c[jf*4] + c[jf*4+1]*c[jf*4+1]
                + c[jf*4+2]*c[jf*4+2] + c[jf*4+3]*c[jf*4+3];
        }
        ss += __shfl_xor_sync(0xffffffffu, ss, 1);
        float t = otc[q] * invl;
        float fac = rsqrtf(fmaxf(-K_CURV * (ss - t * t), EPS_F));
        float* dst = &g_cat[(size_t)(b * NN + q0 + q) * DD + 1 + h * DH + half * 32];
        #pragma unroll
        for (int j = 0; j < 32; j++) dst[j] = c[j] * fac;   // scalar: DD odd
    }
}

// ---------------------------------------------------------------------------
// Kernel 3/5: per-row time attach
// ---------------------------------------------------------------------------
__global__ void rowtime_kernel(float* outp, int which)
{
    float* buf = which ? g_cat : outp;
    int warp = (blockIdx.x * blockDim.x + threadIdx.x) >> 5;
    int lane = threadIdx.x & 31;
    if (warp >= ROWS) return;
    const float* row = buf + (size_t)warp * DD + 1;
    float s = 0.0f;
    #pragma unroll
    for (int c = lane; c < 512; c += 32) {
        float v = row[c];
        s += v * v;
    }
    #pragma unroll
    for (int off = 16; off; off >>= 1)
        s += __shfl_xor_sync(0xffffffffu, s, off);
    if (lane == 0) buf[(size_t)warp * DD] = sqrtf(fmaxf(INV_K + s, EPS_F));
}

// ---------------------------------------------------------------------------
// Kernel 4: output GEMM on tensor cores, 3-pass tf32 split (≈fp32 exact).
// C tile 128x128; epilogue writes straight from fragments (scalar: DD odd).
// ---------------------------------------------------------------------------
__global__ __launch_bounds__(256) void outproj_kernel(
    const float* __restrict__ Wo, const float* __restrict__ bo,
    float* __restrict__ outp)
{
    __shared__ float osm[G_SMEM_FLOATS];
    float* Ash = osm + G_ASH;
    float* Asl = osm + G_ASL;
    float* Bsh = osm + G_BSH;
    float* Bsl = osm + G_BSL;

    const int tid  = threadIdx.x;
    const int lane = tid & 31;
    const int wid  = tid >> 5;
    const int lg   = lane >> 2;
    const int lt   = lane & 3;
    const int row0 = blockIdx.x * 128;
    const int col0 = blockIdx.y * 128;

    const int mb = (wid >> 2) * 64;
    const int nb = (wid & 3) * 32;

    float acc[4][4][4] = {};

    #pragma unroll 1
    for (int k0 = 0; k0 < DD; k0 += 16) {
        __syncthreads();
        #pragma unroll
        for (int it = 0; it < 8; it++) {
            int lin = tid + it * 256;
            int r = lin >> 4, kk = lin & 15;
            int kg = k0 + kk;
            float v = (kg < DD) ? g_cat[(size_t)(row0 + r) * DD + kg] : 0.0f;
            float hi = tf32r(v);
            Ash[r * GA_STRIDE + kk] = hi;
            Asl[r * GA_STRIDE + kk] = tf32r(v - hi);
        }
        #pragma unroll
        for (int it = 0; it < 2; it++) {
            int lin = tid + it * 256;
            int kk = lin >> 5, c4 = lin & 31;
            int kg = k0 + kk;
            int c = c4 * 4;
            float4 v = make_float4(0.f, 0.f, 0.f, 0.f);
            if (kg < DD) v = *(const float4*)&Wo[(size_t)kg * 512 + col0 + c];
            float4 hi = make_float4(tf32r(v.x), tf32r(v.y), tf32r(v.z), tf32r(v.w));
            float4 lo = make_float4(tf32r(v.x - hi.x), tf32r(v.y - hi.y),
                                    tf32r(v.z - hi.z), tf32r(v.w - hi.w));
            *(float4*)&Bsh[kk * GB_STRIDE + c] = hi;
            *(float4*)&Bsl[kk * GB_STRIDE + c] = lo;
        }
        __syncthreads();

        #pragma unroll
        for (int ks = 0; ks < 2; ks++) {
            unsigned bh_[4][2], bl_[4][2];
            #pragma unroll
            for (int ni = 0; ni < 4; ni++) {
                const float* bp = &Bsh[(ks * 8 + lt) * GB_STRIDE + nb + 8 * ni + lg];
                bh_[ni][0] = fu(bp[0]);
                bh_[ni][1] = fu(bp[4 * GB_STRIDE]);
                const float* bq_ = &Bsl[(ks * 8 + lt) * GB_STRIDE + nb + 8 * ni + lg];
                bl_[ni][0] = fu(bq_[0]);
                bl_[ni][1] = fu(bq_[4 * GB_STRIDE]);
            }
            #pragma unroll
            for (int mi = 0; mi < 4; mi++) {
                const float* ap = &Ash[(mb + 16 * mi + lg) * GA_STRIDE + ks * 8 + lt];
                unsigned ah0 = fu(ap[0]), ah1 = fu(ap[8 * GA_STRIDE]);
                unsigned ah2 = fu(ap[4]), ah3 = fu(ap[8 * GA_STRIDE + 4]);
                const float* aq = &Asl[(mb + 16 * mi + lg) * GA_STRIDE + ks * 8 + lt];
                unsigned al0 = fu(aq[0]), al1 = fu(aq[8 * GA_STRIDE]);
                unsigned al2 = fu(aq[4]), al3 = fu(aq[8 * GA_STRIDE + 4]);
                #pragma unroll
                for (int ni = 0; ni < 4; ni++) {
                    mma_tf32(acc[mi][ni], ah0, ah1, ah2, ah3, bh_[ni][0], bh_[ni][1]);
                    mma_tf32(acc[mi][ni], ah0, ah1, ah2, ah3, bl_[ni][0], bl_[ni][1]);
                    mma_tf32(acc[mi][ni], al0, al1, al2, al3, bh_[ni][0], bh_[ni][1]);
                }
            }
        }
    }

    // epilogue: bias + scalar stores (output row stride 513 floats is odd)
    #pragma unroll
    for (int ni = 0; ni < 4; ni++) {
        int col = col0 + nb + 8 * ni + 2 * lt;
        float b0_ = bo[col], b1_ = bo[col + 1];
        #pragma unroll
        for (int mi = 0; mi < 4; mi++) {
            int row = row0 + mb + 16 * mi + lg;
            float* d0 = &outp[(size_t)row * DD + 1 + col];
            d0[0] = acc[mi][ni][0] + b0_;
            d0[1] = acc[mi][ni][1] + b1_;
            float* d1 = &outp[(size_t)(row + 8) * DD + 1 + col];
            d1[0] = acc[mi][ni][2] + b0_;
            d1[1] = acc[mi][ni][3] + b1_;
        }
    }
}

// ---------------------------------------------------------------------------
extern "C" void kernel_launch(void* const* d_in, const int* in_sizes, int n_in,
                              void* d_out, int out_size)
{
    const float* x  = (const float*)d_in[0];
    const float* Wq = (const float*)d_in[1];
    const float* bq = (const float*)d_in[2];
    const float* Wk = (const float*)d_in[3];
    const float* bk = (const float*)d_in[4];
    const float* Wv = (const float*)d_in[5];
    const float* bv = (const float*)d_in[6];
    const float* Wo = (const float*)d_in[7];
    const float* bo = (const float*)d_in[8];
    float* outp = (float*)d_out;

    cudaFuncSetAttribute(attn_kernel,
                         cudaFuncAttributeMaxDynamicSharedMemorySize,
                         ATT_SMEM_BYTES);
    cudaFuncSetAttribute(proj_kernel,
                         cudaFuncAttributeMaxDynamicSharedMemorySize,
                         PJ_SMEM_BYTES);

    proj_kernel<<<dim3(ROWS / 128, 12), 256, PJ_SMEM_BYTES>>>(x, Wq, bq, Wk, bk, Wv, bv);
    attn_kernel<<<dim3(NN / 128, BB * HH), 256, ATT_SMEM_BYTES>>>();
    rowtime_kernel<<<ROWS / 8, 256>>>(nullptr, 1);
    outproj_kernel<<<dim3(ROWS / 128, 4), 256>>>(Wo, bo, outp);
    rowtime_kernel<<<ROWS / 8, 256>>>(outp, 0);
}

// round 14
// speedup vs baseline: 2.1092x; 1.0423x over previous
#include <cuda_runtime.h>
#include <math.h>

// Problem dims
#define BB   4
#define NN   2048
#define DD   513
#define HH   8
#define DH   64
#define ROWS (BB*NN)       // 8192

#define INV_K   10.0f
#define K_CURV  0.1f
#define EPS_F   1e-9f
#define SCALE_F 0.125f     // 1/sqrt(64)
#define QSC     (0.125f * 1.44269504088896f)   // SCALE * log2(e)

// ---------------------------------------------------------------------------
// tf32 mma helpers
// ---------------------------------------------------------------------------
__device__ __forceinline__ float tf32r(float x) {
    unsigned u; asm("cvt.rna.tf32.f32 %0, %1;" : "=r"(u) : "f"(x));
    return __uint_as_float(u);
}
__device__ __forceinline__ void mma_tf32(float c[4],
    unsigned a0, unsigned a1, unsigned a2, unsigned a3,
    unsigned b0, unsigned b1)
{
    asm("mma.sync.aligned.m16n8k8.row.col.f32.tf32.tf32.f32 "
        "{%0,%1,%2,%3},{%4,%5,%6,%7},{%8,%9},{%0,%1,%2,%3};"
        : "+f"(c[0]), "+f"(c[1]), "+f"(c[2]), "+f"(c[3])
        : "r"(a0), "r"(a1), "r"(a2), "r"(a3), "r"(b0), "r"(b1));
}
__device__ __forceinline__ unsigned fu(float x) { return __float_as_uint(x); }
__device__ __forceinline__ float ex2(float x) {
    float r; asm("ex2.approx.f32 %0, %1;" : "=f"(r) : "f"(x)); return r;
}

// Scratch (device globals: allocation-free per harness rules)
__device__ float g_qs[BB*HH*NN*DH];
__device__ float g_qt[BB*HH*NN];      // q time, NEGATED
__device__ float g_ks[BB*HH*NN*DH];
__device__ float g_kt[BB*HH*NN];
__device__ float g_vs[BB*HH*NN*DH];
__device__ float g_vt[BB*HH*NN];
__device__ float g_cat[ROWS*DD];      // [B*N][513]

// ---------------------------------------------------------------------------
// GEMM layout: A [row][k16] hi/lo stride 20, B [k16][col128] hi/lo stride 136.
// Double-buffered: buffer stride G_BUF floats.
// ---------------------------------------------------------------------------
#define GA_STRIDE 20
#define GB_STRIDE 136
#define G_AH 0
#define G_AL (128*GA_STRIDE)
#define G_BH (2*128*GA_STRIDE)
#define G_BL (2*128*GA_STRIDE + 16*GB_STRIDE)
#define G_BUF (2*128*GA_STRIDE + 2*16*GB_STRIDE)   // 9472 floats / buffer
#define G_SMEM_FLOATS (2*G_BUF)                    // 18944
#define G_SMEM_BYTES  (G_SMEM_FLOATS*4)            // 75776 (Cs 16896 fits inside)

// ---------------------------------------------------------------------------
// Kernel 1: QKV projection, tensor-core 3-pass tf32 split, double-buffered.
// ---------------------------------------------------------------------------
__global__ __launch_bounds__(256, 2) void proj_kernel(
    const float* __restrict__ x,
    const float* __restrict__ Wq, const float* __restrict__ bq,
    const float* __restrict__ Wk, const float* __restrict__ bk,
    const float* __restrict__ Wv, const float* __restrict__ bv)
{
    extern __shared__ float psm[];

    const int tid  = threadIdx.x;
    const int lane = tid & 31;
    const int wid  = tid >> 5;
    const int lg   = lane >> 2;
    const int lt   = lane & 3;
    const int row0 = blockIdx.x * 128;
    const int gy = blockIdx.y;
    const int mat = gy >> 2;
    const int h0 = (gy & 3) * 2;

    const float* W    = (mat == 0) ? Wq : ((mat == 1) ? Wk : Wv);
    const float* bias = (mat == 0) ? bq : ((mat == 1) ? bk : bv);
    float* outs       = (mat == 0) ? g_qs : ((mat == 1) ? g_ks : g_vs);
    float* outt       = (mat == 0) ? g_qt : ((mat == 1) ? g_kt : g_vt);

    const int mb = (wid >> 2) * 64;
    const int nb = (wid & 3) * 32;

    // per-thread staging coordinates
    const int a_r[8] = { (tid+0*256)>>4, (tid+1*256)>>4, (tid+2*256)>>4, (tid+3*256)>>4,
                         (tid+4*256)>>4, (tid+5*256)>>4, (tid+6*256)>>4, (tid+7*256)>>4 };
    const int a_k = tid & 15;
    const int b_kk0 = tid >> 5,        b_c0 = (tid & 31) * 4;
    const int b_kk1 = (tid+256) >> 5;

    float acc[4][4][4] = {};
    float pa[8];
    float4 pb[2];

    // prologue: stage k0 = 0 into buffer 0
    #pragma unroll
    for (int it = 0; it < 8; it++)
        pa[it] = x[(size_t)(row0 + a_r[it]) * DD + a_k];
    {
        int h = h0 + (b_c0 >> 6), m = b_c0 & 63;
        pb[0] = *(const float4*)&W[((size_t)h * DD + b_kk0) * DH + m];
        pb[1] = *(const float4*)&W[((size_t)h * DD + b_kk1) * DH + m];
    }
    {
        float* Ash = psm + G_AH; float* Asl = psm + G_AL;
        float* Bsh = psm + G_BH; float* Bsl = psm + G_BL;
        #pragma unroll
        for (int it = 0; it < 8; it++) {
            float hi = tf32r(pa[it]);
            Ash[a_r[it] * GA_STRIDE + a_k] = hi;
            Asl[a_r[it] * GA_STRIDE + a_k] = tf32r(pa[it] - hi);
        }
        #pragma unroll
        for (int it = 0; it < 2; it++) {
            int kk = it ? b_kk1 : b_kk0;
            float4 v = pb[it];
            float4 hi = make_float4(tf32r(v.x), tf32r(v.y), tf32r(v.z), tf32r(v.w));
            float4 lo = make_float4(tf32r(v.x-hi.x), tf32r(v.y-hi.y),
                                    tf32r(v.z-hi.z), tf32r(v.w-hi.w));
            *(float4*)&Bsh[kk * GB_STRIDE + b_c0] = hi;
            *(float4*)&Bsl[kk * GB_STRIDE + b_c0] = lo;
        }
    }
    __syncthreads();

    int buf = 0;
    #pragma unroll 1
    for (int k0 = 0; k0 < DD; k0 += 16, buf ^= 1) {
        const bool more = (k0 + 16) < DD;
        if (more) {
            #pragma unroll
            for (int it = 0; it < 8; it++) {
                int kg = k0 + 16 + a_k;
                pa[it] = (kg < DD) ? x[(size_t)(row0 + a_r[it]) * DD + kg] : 0.0f;
            }
            int h = h0 + (b_c0 >> 6), m = b_c0 & 63;
            int kg0 = k0 + 16 + b_kk0, kg1 = k0 + 16 + b_kk1;
            pb[0] = (kg0 < DD) ? *(const float4*)&W[((size_t)h * DD + kg0) * DH + m]
                               : make_float4(0.f,0.f,0.f,0.f);
            pb[1] = (kg1 < DD) ? *(const float4*)&W[((size_t)h * DD + kg1) * DH + m]
                               : make_float4(0.f,0.f,0.f,0.f);
        }

        const float* Ash = psm + buf * G_BUF + G_AH;
        const float* Asl = psm + buf * G_BUF + G_AL;
        const float* Bsh = psm + buf * G_BUF + G_BH;
        const float* Bsl = psm + buf * G_BUF + G_BL;

        #pragma unroll
        for (int ks = 0; ks < 2; ks++) {
            unsigned bh_[4][2], bl_[4][2];
            #pragma unroll
            for (int ni = 0; ni < 4; ni++) {
                const float* bp = &Bsh[(ks * 8 + lt) * GB_STRIDE + nb + 8 * ni + lg];
                bh_[ni][0] = fu(bp[0]);
                bh_[ni][1] = fu(bp[4 * GB_STRIDE]);
                const float* bq_ = &Bsl[(ks * 8 + lt) * GB_STRIDE + nb + 8 * ni + lg];
                bl_[ni][0] = fu(bq_[0]);
                bl_[ni][1] = fu(bq_[4 * GB_STRIDE]);
            }
            #pragma unroll
            for (int mi = 0; mi < 4; mi++) {
                const float* ap = &Ash[(mb + 16 * mi + lg) * GA_STRIDE + ks * 8 + lt];
                unsigned ah0 = fu(ap[0]), ah1 = fu(ap[8 * GA_STRIDE]);
                unsigned ah2 = fu(ap[4]), ah3 = fu(ap[8 * GA_STRIDE + 4]);
                const float* aq = &Asl[(mb + 16 * mi + lg) * GA_STRIDE + ks * 8 + lt];
                unsigned al0 = fu(aq[0]), al1 = fu(aq[8 * GA_STRIDE]);
                unsigned al2 = fu(aq[4]), al3 = fu(aq[8 * GA_STRIDE + 4]);
                #pragma unroll
                for (int ni = 0; ni < 4; ni++) {
                    mma_tf32(acc[mi][ni], ah0, ah1, ah2, ah3, bh_[ni][0], bh_[ni][1]);
                    mma_tf32(acc[mi][ni], ah0, ah1, ah2, ah3, bl_[ni][0], bl_[ni][1]);
                    mma_tf32(acc[mi][ni], al0, al1, al2, al3, bh_[ni][0], bh_[ni][1]);
                }
            }
        }

        if (more) {
            float* Ash2 = psm + (buf ^ 1) * G_BUF + G_AH;
            float* Asl2 = psm + (buf ^ 1) * G_BUF + G_AL;
            float* Bsh2 = psm + (buf ^ 1) * G_BUF + G_BH;
            float* Bsl2 = psm + (buf ^ 1) * G_BUF + G_BL;
            #pragma unroll
            for (int it = 0; it < 8; it++) {
                float hi = tf32r(pa[it]);
                Ash2[a_r[it] * GA_STRIDE + a_k] = hi;
                Asl2[a_r[it] * GA_STRIDE + a_k] = tf32r(pa[it] - hi);
            }
            #pragma unroll
            for (int it = 0; it < 2; it++) {
                int kk = it ? b_kk1 : b_kk0;
                float4 v = pb[it];
                float4 hi = make_float4(tf32r(v.x), tf32r(v.y), tf32r(v.z), tf32r(v.w));
                float4 lo = make_float4(tf32r(v.x-hi.x), tf32r(v.y-hi.y),
                                        tf32r(v.z-hi.z), tf32r(v.w-hi.w));
                *(float4*)&Bsh2[kk * GB_STRIDE + b_c0] = hi;
                *(float4*)&Bsl2[kk * GB_STRIDE + b_c0] = lo;
            }
        }
        __syncthreads();
    }

    // stage C to Cs[128][132] (reuses buffer smem)
    float* Cs = psm;
    #pragma unroll
    for (int mi = 0; mi < 4; mi++) {
        #pragma unroll
        for (int ni = 0; ni < 4; ni++) {
            int row = mb + 16 * mi + lg;
            int col = nb + 8 * ni + 2 * lt;
            *(float2*)&Cs[row * 132 + col]       = make_float2(acc[mi][ni][0], acc[mi][ni][1]);
            *(float2*)&Cs[(row + 8) * 132 + col] = make_float2(acc[mi][ni][2], acc[mi][ni][3]);
        }
    }
    __syncthreads();

    // epilogue: one thread per (row, head)
    {
        int r = tid >> 1, hh = tid & 1;
        int h = h0 + hh;
        const float tsign = (mat == 0) ? -1.0f : 1.0f;
        float c[64];
        float ss = 0.f;
        #pragma unroll
        for (int j4 = 0; j4 < 16; j4++) {
            float4 cv = *(const float4*)&Cs[r * 132 + hh * 64 + j4 * 4];
            float4 bb = *(const float4*)&bias[h * DH + j4 * 4];
            float v0 = cv.x + bb.x, v1 = cv.y + bb.y;
            float v2 = cv.z + bb.z, v3 = cv.w + bb.w;
            c[j4 * 4 + 0] = v0; c[j4 * 4 + 1] = v1;
            c[j4 * 4 + 2] = v2; c[j4 * 4 + 3] = v3;
            ss += v0 * v0 + v1 * v1 + v2 * v2 + v3 * v3;
        }
        int g = row0 + r;
        int b = g >> 11, n = g & 2047;
        size_t bhn = (size_t)(b * HH + h) * NN + n;
        float* dst = &outs[bhn * DH];
        #pragma unroll
        for (int j4 = 0; j4 < 16; j4++)
            *(float4*)&dst[j4 * 4] = make_float4(c[j4*4], c[j4*4+1], c[j4*4+2], c[j4*4+3]);
        outt[bhn] = tsign * sqrtf(fmaxf(INV_K + ss, EPS_F));
    }
}

// ---------------------------------------------------------------------------
// Kernel 2: flash attention, tensor cores, NO online softmax:
// Lorentz inner products of hyperboloid points are <= -1/k, so every logit
// <= -1.25 < 0: exp never overflows, max-tracking/alpha-rescale unnecessary.
// Q pre-scaled by SCALE*log2e; ex2.approx applied directly at S-fragment store.
// ---------------------------------------------------------------------------
#define AT_QS   0
#define AT_KS   (128*68)
#define AT_VS   (2*128*68)
#define AT_PT   (3*128*68)
#define AT_QT   (AT_PT + 128*132)
#define ATT_SMEM_FLOATS (AT_QT + 5*128)
#define ATT_SMEM_BYTES  (ATT_SMEM_FLOATS * 4)

__global__ __launch_bounds__(256, 1) void attn_kernel()
{
    extern __shared__ float sm[];
    float* Qs    = sm + AT_QS;    // [128][68] tf32(QSC * q_space)
    float* Ks    = sm + AT_KS;    // [128][68] tf32(k_space)
    float* Vs    = sm + AT_VS;    // [128][68] tf32(v_space)
    float* Pt    = sm + AT_PT;    // [128 q][132] exp'd P; O^T at the end
    float* qts   = sm + AT_QT;    // [128] QSC * (negated q time), fp32 exact
    float* kts   = qts + 128;     // [128] k time
    float* vtime = kts + 128;     // [128] v time
    float* lrow  = vtime + 128;   // [128] running sum of exp
    float* otc   = lrow + 128;    // [128] running time-component sum

    const int tid  = threadIdx.x;
    const int lane = tid & 31;
    const int wid  = tid >> 5;
    const int lg   = lane >> 2;
    const int lt   = lane & 3;
    const int bh = blockIdx.y;
    const int q0 = blockIdx.x * 128;
    const int h = bh & 7, b = bh >> 3;

    const int s_qb = (wid >> 2) * 64;
    const int s_kb = (wid & 3) * 32;
    const int p_mb = (wid >> 2) * 32;
    const int p_qb = (wid & 3) * 32;

    const float* qsb = g_qs + ((size_t)bh * NN + q0) * DH;
    const float* qtb = g_qt + (size_t)bh * NN + q0;
    #pragma unroll
    for (int it = 0; it < 8; it++) {
        int lin = tid + it * 256;
        int r = lin >> 4, c4 = lin & 15;
        float4 v = *(const float4*)&qsb[r * DH + c4 * 4];
        float* d = &Qs[r * 68 + c4 * 4];
        d[0] = tf32r(v.x * QSC); d[1] = tf32r(v.y * QSC);
        d[2] = tf32r(v.z * QSC); d[3] = tf32r(v.w * QSC);
    }
    if (tid < 128) {
        qts[tid] = qtb[tid] * QSC;
        lrow[tid] = 0.0f; otc[tid] = 0.0f;
    }

    float o[2][4][4] = {};

    const float* ksb = g_ks + (size_t)bh * NN * DH;
    const float* ktb = g_kt + (size_t)bh * NN;
    const float* vsb = g_vs + (size_t)bh * NN * DH;
    const float* vtb = g_vt + (size_t)bh * NN;

    #pragma unroll 1
    for (int kt = 0; kt < NN / 128; kt++) {
        __syncthreads();   // prior PV reads of Vs/Pt done
        const float* kp_ = ksb + (size_t)kt * 128 * DH;
        const float* vp_ = vsb + (size_t)kt * 128 * DH;
        #pragma unroll
        for (int it = 0; it < 8; it++) {
            int lin = tid + it * 256;
            int r = lin >> 4, c4 = lin & 15;
            float4 kv = *(const float4*)&kp_[r * DH + c4 * 4];
            float* kd = &Ks[r * 68 + c4 * 4];
            kd[0] = tf32r(kv.x); kd[1] = tf32r(kv.y);
            kd[2] = tf32r(kv.z); kd[3] = tf32r(kv.w);
            float4 vv = *(const float4*)&vp_[r * DH + c4 * 4];
            float* vd = &Vs[r * 68 + c4 * 4];
            vd[0] = tf32r(vv.x); vd[1] = tf32r(vv.y);
            vd[2] = tf32r(vv.z); vd[3] = tf32r(vv.w);
        }
        if (tid < 128) {
            kts[tid]   = ktb[kt * 128 + tid];
            vtime[tid] = vtb[kt * 128 + tid];
        }
        __syncthreads();

        // ---- S phase: mma (log2 domain) + exact time fold + exp2 at store ----
        {
            float sc[4][4][4];
            #pragma unroll
            for (int mi = 0; mi < 4; mi++)
                #pragma unroll
                for (int ni = 0; ni < 4; ni++)
                    #pragma unroll
                    for (int r = 0; r < 4; r++) sc[mi][ni][r] = 0.0f;

            #pragma unroll
            for (int ks = 0; ks < 8; ks++) {
                unsigned a[4][4];
                #pragma unroll
                for (int mi = 0; mi < 4; mi++) {
                    const float* ap = &Qs[(s_qb + 16 * mi + lg) * 68 + ks * 8 + lt];
                    a[mi][0] = fu(ap[0]);
                    a[mi][1] = fu(ap[8 * 68]);
                    a[mi][2] = fu(ap[4]);
                    a[mi][3] = fu(ap[8 * 68 + 4]);
                }
                unsigned bf[4][2];
                #pragma unroll
                for (int ni = 0; ni < 4; ni++) {
                    const float* bp = &Ks[(s_kb + 8 * ni + lg) * 68 + ks * 8 + lt];
                    bf[ni][0] = fu(bp[0]);
                    bf[ni][1] = fu(bp[4]);
                }
                #pragma unroll
                for (int mi = 0; mi < 4; mi++)
                    #pragma unroll
                    for (int ni = 0; ni < 4; ni++)
                        mma_tf32(sc[mi][ni], a[mi][0], a[mi][1], a[mi][2], a[mi][3],
                                 bf[ni][0], bf[ni][1]);
            }

            #pragma unroll
            for (int mi = 0; mi < 4; mi++) {
                int qr = s_qb + 16 * mi + lg;
                float qt0 = qts[qr], qt8 = qts[qr + 8];
                #pragma unroll
                for (int ni = 0; ni < 4; ni++) {
                    int kc = s_kb + 8 * ni + 2 * lt;
                    float kt0 = kts[kc], kt1 = kts[kc + 1];
                    float p0 = ex2(fmaf(qt0, kt0, sc[mi][ni][0]));
                    float p1 = ex2(fmaf(qt0, kt1, sc[mi][ni][1]));
                    float p2 = ex2(fmaf(qt8, kt0, sc[mi][ni][2]));
                    float p3 = ex2(fmaf(qt8, kt1, sc[mi][ni][3]));
                    *(float2*)&Pt[qr * 132 + kc]       = make_float2(p0, p1);
                    *(float2*)&Pt[(qr + 8) * 132 + kc] = make_float2(p2, p3);
                }
            }
        }
        __syncthreads();

        // ---- row sums (l, time-component) in exact fp32; 2 threads/row ----
        {
            int r = tid >> 1, part = tid & 1;
            const float* prow = &Pt[r * 132 + part * 64];
            float sum = 0.f, tsum = 0.f;
            #pragma unroll
            for (int jf = 0; jf < 16; jf++) {
                float4 p = *(const float4*)&prow[jf * 4];
                sum += (p.x + p.y) + (p.z + p.w);
                int kk = part * 64 + jf * 4;
                tsum += p.x * vtime[kk] + p.y * vtime[kk + 1]
                      + p.z * vtime[kk + 2] + p.w * vtime[kk + 3];
            }
            sum  += __shfl_xor_sync(0xffffffffu, sum, 1);
            tsum += __shfl_xor_sync(0xffffffffu, tsum, 1);
            if (part == 0) {
                lrow[r] += sum;
                otc[r]  += tsum;
            }
        }
        // (no sync needed: PV below also only READS Pt/Vs)

        // ---- PV phase: O^T += V^T . P^T via mma (no rescale needed) ----
        {
            #pragma unroll
            for (int ks = 0; ks < 16; ks++) {
                unsigned a[2][4];
                #pragma unroll
                for (int fi = 0; fi < 2; fi++) {
                    const float* ap = &Vs[(ks * 8 + lt) * 68 + p_mb + 16 * fi + lg];
                    a[fi][0] = fu(ap[0]);
                    a[fi][1] = fu(ap[8]);
                    a[fi][2] = fu(ap[4 * 68]);
                    a[fi][3] = fu(ap[4 * 68 + 8]);
                }
                unsigned bf[4][2];
                #pragma unroll
                for (int ni = 0; ni < 4; ni++) {
                    const float* bp = &Pt[(p_qb + 8 * ni + lg) * 132 + ks * 8 + lt];
                    bf[ni][0] = fu(bp[0]);
                    bf[ni][1] = fu(bp[4]);
                }
                #pragma unroll
                for (int fi = 0; fi < 2; fi++)
                    #pragma unroll
                    for (int ni = 0; ni < 4; ni++)
                        mma_tf32(o[fi][ni], a[fi][0], a[fi][1], a[fi][2], a[fi][3],
                                 bf[ni][0], bf[ni][1]);
            }
        }
    }
    __syncthreads();

    // ---- stage O^T into Pt as [q][dim] ----
    #pragma unroll
    for (int fi = 0; fi < 2; fi++) {
        #pragma unroll
        for (int ni = 0; ni < 4; ni++) {
            int mr = p_mb + 16 * fi + lg;
            int qc = p_qb + 8 * ni + 2 * lt;
            Pt[qc * 132 + mr]           = o[fi][ni][0];
            Pt[(qc + 1) * 132 + mr]     = o[fi][ni][1];
            Pt[qc * 132 + mr + 8]       = o[fi][ni][2];
            Pt[(qc + 1) * 132 + mr + 8] = o[fi][ni][3];
        }
    }
    __syncthreads();

    // ---- epilogue: normalize, Lorentz midpoint, head-concat (scalar stores) ----
    {
        int q = tid >> 1, half = tid & 1;
        float invl = 1.0f / lrow[q];
        const float* orow = &Pt[q * 132 + half * 32];
        float c[32];
        float ss = 0.f;
        #pragma unroll
        for (int jf = 0; jf < 8; jf++) {
            float4 p = *(const float4*)&orow[jf * 4];
            c[jf * 4 + 0] = p.x * invl; c[jf * 4 + 1] = p.y * invl;
            c[jf * 4 + 2] = p.z * invl; c[jf * 4 + 3] = p.w * invl;
            ss += c[jf*4]*c[jf*4] + c[jf*4+1]*c[jf*4+1]
                + c[jf*4+2]*c[jf*4+2] + c[jf*4+3]*c[jf*4+3];
        }
        ss += __shfl_xor_sync(0xffffffffu, ss, 1);
        float t = otc[q] * invl;
        float fac = rsqrtf(fmaxf(-K_CURV * (ss - t * t), EPS_F));
        float* dst = &g_cat[(size_t)(b * NN + q0 + q) * DD + 1 + h * DH + half * 32];
        #pragma unroll
        for (int j = 0; j < 32; j++) dst[j] = c[j] * fac;
    }
}

// ---------------------------------------------------------------------------
// Kernel 3/5: per-row time attach
// ---------------------------------------------------------------------------
__global__ void rowtime_kernel(float* outp, int which)
{
    float* buf = which ? g_cat : outp;
    int warp = (blockIdx.x * blockDim.x + threadIdx.x) >> 5;
    int lane = threadIdx.x & 31;
    if (warp >= ROWS) return;
    const float* row = buf + (size_t)warp * DD + 1;
    float s = 0.0f;
    #pragma unroll
    for (int c = lane; c < 512; c += 32) {
        float v = row[c];
        s += v * v;
    }
    #pragma unroll
    for (int off = 16; off; off >>= 1)
        s += __shfl_xor_sync(0xffffffffu, s, off);
    if (lane == 0) buf[(size_t)warp * DD] = sqrtf(fmaxf(INV_K + s, EPS_F));
}

// ---------------------------------------------------------------------------
// Kernel 4: output GEMM, tensor-core 3-pass split, double-buffered.
// ---------------------------------------------------------------------------
__global__ __launch_bounds__(256, 2) void outproj_kernel(
    const float* __restrict__ Wo, const float* __restrict__ bo,
    float* __restrict__ outp)
{
    extern __shared__ float osm[];

    const int tid  = threadIdx.x;
    const int lane = tid & 31;
    const int wid  = tid >> 5;
    const int lg   = lane >> 2;
    const int lt   = lane & 3;
    const int row0 = blockIdx.x * 128;
    const int col0 = blockIdx.y * 128;

    const int mb = (wid >> 2) * 64;
    const int nb = (wid & 3) * 32;

    const int a_r[8] = { (tid+0*256)>>4, (tid+1*256)>>4, (tid+2*256)>>4, (tid+3*256)>>4,
                         (tid+4*256)>>4, (tid+5*256)>>4, (tid+6*256)>>4, (tid+7*256)>>4 };
    const int a_k = tid & 15;
    const int b_kk0 = tid >> 5,       b_c0 = (tid & 31) * 4;
    const int b_kk1 = (tid+256) >> 5;

    float acc[4][4][4] = {};
    float pa[8];
    float4 pb[2];

    // prologue: k0 = 0
    #pragma unroll
    for (int it = 0; it < 8; it++)
        pa[it] = g_cat[(size_t)(row0 + a_r[it]) * DD + a_k];
    pb[0] = *(const float4*)&Wo[(size_t)b_kk0 * 512 + col0 + b_c0];
    pb[1] = *(const float4*)&Wo[(size_t)b_kk1 * 512 + col0 + b_c0];
    {
        float* Ash = osm + G_AH; float* Asl = osm + G_AL;
        float* Bsh = osm + G_BH; float* Bsl = osm + G_BL;
        #pragma unroll
        for (int it = 0; it < 8; it++) {
            float hi = tf32r(pa[it]);
            Ash[a_r[it] * GA_STRIDE + a_k] = hi;
            Asl[a_r[it] * GA_STRIDE + a_k] = tf32r(pa[it] - hi);
        }
        #pragma unroll
        for (int it = 0; it < 2; it++) {
            int kk = it ? b_kk1 : b_kk0;
            float4 v = pb[it];
            float4 hi = make_float4(tf32r(v.x), tf32r(v.y), tf32r(v.z), tf32r(v.w));
            float4 lo = make_float4(tf32r(v.x-hi.x), tf32r(v.y-hi.y),
                                    tf32r(v.z-hi.z), tf32r(v.w-hi.w));
            *(float4*)&Bsh[kk * GB_STRIDE + b_c0] = hi;
            *(float4*)&Bsl[kk * GB_STRIDE + b_c0] = lo;
        }
    }
    __syncthreads();

    int buf = 0;
    #pragma unroll 1
    for (int k0 = 0; k0 < DD; k0 += 16, buf ^= 1) {
        const bool more = (k0 + 16) < DD;
        if (more) {
            #pragma unroll
            for (int it = 0; it < 8; it++) {
                int kg = k0 + 16 + a_k;
                pa[it] = (kg < DD) ? g_cat[(size_t)(row0 + a_r[it]) * DD + kg] : 0.0f;
            }
            int kg0 = k0 + 16 + b_kk0, kg1 = k0 + 16 + b_kk1;
            pb[0] = (kg0 < DD) ? *(const float4*)&Wo[(size_t)kg0 * 512 + col0 + b_c0]
                               : make_float4(0.f,0.f,0.f,0.f);
            pb[1] = (kg1 < DD) ? *(const float4*)&Wo[(size_t)kg1 * 512 + col0 + b_c0]
                               : make_float4(0.f,0.f,0.f,0.f);
        }

        const float* Ash = osm + buf * G_BUF + G_AH;
        const float* Asl = osm + buf * G_BUF + G_AL;
        const float* Bsh = osm + buf * G_BUF + G_BH;
        const float* Bsl = osm + buf * G_BUF + G_BL;

        #pragma unroll
        for (int ks = 0; ks < 2; ks++) {
            unsigned bh_[4][2], bl_[4][2];
            #pragma unroll
            for (int ni = 0; ni < 4; ni++) {
                const float* bp = &Bsh[(ks * 8 + lt) * GB_STRIDE + nb + 8 * ni + lg];
                bh_[ni][0] = fu(bp[0]);
                bh_[ni][1] = fu(bp[4 * GB_STRIDE]);
                const float* bq_ = &Bsl[(ks * 8 + lt) * GB_STRIDE + nb + 8 * ni + lg];
                bl_[ni][0] = fu(bq_[0]);
                bl_[ni][1] = fu(bq_[4 * GB_STRIDE]);
            }
            #pragma unroll
            for (int mi = 0; mi < 4; mi++) {
                const float* ap = &Ash[(mb + 16 * mi + lg) * GA_STRIDE + ks * 8 + lt];
                unsigned ah0 = fu(ap[0]), ah1 = fu(ap[8 * GA_STRIDE]);
                unsigned ah2 = fu(ap[4]), ah3 = fu(ap[8 * GA_STRIDE + 4]);
                const float* aq = &Asl[(mb + 16 * mi + lg) * GA_STRIDE + ks * 8 + lt];
                unsigned al0 = fu(aq[0]), al1 = fu(aq[8 * GA_STRIDE]);
                unsigned al2 = fu(aq[4]), al3 = fu(aq[8 * GA_STRIDE + 4]);
                #pragma unroll
                for (int ni = 0; ni < 4; ni++) {
                    mma_tf32(acc[mi][ni], ah0, ah1, ah2, ah3, bh_[ni][0], bh_[ni][1]);
                    mma_tf32(acc[mi][ni], ah0, ah1, ah2, ah3, bl_[ni][0], bl_[ni][1]);
                    mma_tf32(acc[mi][ni], al0, al1, al2, al3, bh_[ni][0], bh_[ni][1]);
                }
            }
        }

        if (more) {
            float* Ash2 = osm + (buf ^ 1) * G_BUF + G_AH;
            float* Asl2 = osm + (buf ^ 1) * G_BUF + G_AL;
            float* Bsh2 = osm + (buf ^ 1) * G_BUF + G_BH;
            float* Bsl2 = osm + (buf ^ 1) * G_BUF + G_BL;
            #pragma unroll
            for (int it = 0; it < 8; it++) {
                float hi = tf32r(pa[it]);
                Ash2[a_r[it] * GA_STRIDE + a_k] = hi;
                Asl2[a_r[it] * GA_STRIDE + a_k] = tf32r(pa[it] - hi);
            }
            #pragma unroll
            for (int it = 0; it < 2; it++) {
                int kk = it ? b_kk1 : b_kk0;
                float4 v = pb[it];
                float4 hi = make_float4(tf32r(v.x), tf32r(v.y), tf32r(v.z), tf32r(v.w));
                float4 lo = make_float4(tf32r(v.x-hi.x), tf32r(v.y-hi.y),
                                        tf32r(v.z-hi.z), tf32r(v.w-hi.w));
                *(float4*)&Bsh2[kk * GB_STRIDE + b_c0] = hi;
                *(float4*)&Bsl2[kk * GB_STRIDE + b_c0] = lo;
            }
        }
        __syncthreads();
    }

    // epilogue: bias + scalar stores (output row stride 513 floats is odd)
    #pragma unroll
    for (int ni = 0; ni < 4; ni++) {
        int col = col0 + nb + 8 * ni + 2 * lt;
        float b0_ = bo[col], b1_ = bo[col + 1];
        #pragma unroll
        for (int mi = 0; mi < 4; mi++) {
            int row = row0 + mb + 16 * mi + lg;
            float* d0 = &outp[(size_t)row * DD + 1 + col];
            d0[0] = acc[mi][ni][0] + b0_;
            d0[1] = acc[mi][ni][1] + b1_;
            float* d1 = &outp[(size_t)(row + 8) * DD + 1 + col];
            d1[0] = acc[mi][ni][2] + b0_;
            d1[1] = acc[mi][ni][3] + b1_;
        }
    }
}

// ---------------------------------------------------------------------------
extern "C" void kernel_launch(void* const* d_in, const int* in_sizes, int n_in,
                              void* d_out, int out_size)
{
    const float* x  = (const float*)d_in[0];
    const float* Wq = (const float*)d_in[1];
    const float* bq = (const float*)d_in[2];
    const float* Wk = (const float*)d_in[3];
    const float* bk = (const float*)d_in[4];
    const float* Wv = (const float*)d_in[5];
    const float* bv = (const float*)d_in[6];
    const float* Wo = (const float*)d_in[7];
    const float* bo = (const float*)d_in[8];
    float* outp = (float*)d_out;

    cudaFuncSetAttribute(attn_kernel,
                         cudaFuncAttributeMaxDynamicSharedMemorySize,
                         ATT_SMEM_BYTES);
    cudaFuncSetAttribute(proj_kernel,
                         cudaFuncAttributeMaxDynamicSharedMemorySize,
                         G_SMEM_BYTES);
    cudaFuncSetAttribute(outproj_kernel,
                         cudaFuncAttributeMaxDynamicSharedMemorySize,
                         G_SMEM_BYTES);

    proj_kernel<<<dim3(ROWS / 128, 12), 256, G_SMEM_BYTES>>>(x, Wq, bq, Wk, bk, Wv, bv);
    attn_kernel<<<dim3(NN / 128, BB * HH), 256, ATT_SMEM_BYTES>>>();
    rowtime_kernel<<<ROWS / 8, 256>>>(nullptr, 1);
    outproj_kernel<<<dim3(ROWS / 128, 4), 256, G_SMEM_BYTES>>>(Wo, bo, outp);
    rowtime_kernel<<<ROWS / 8, 256>>>(outp, 0);
}

// round 15
// speedup vs baseline: 2.1398x; 1.0145x over previous
#include <cuda_runtime.h>
#include <math.h>

// Problem dims
#define BB   4
#define NN   2048
#define DD   513
#define HH   8
#define DH   64
#define ROWS (BB*NN)       // 8192

#define INV_K   10.0f
#define K_CURV  0.1f
#define EPS_F   1e-9f
#define SCALE_F 0.125f     // 1/sqrt(64)
#define QSC     (0.125f * 1.44269504088896f)   // SCALE * log2(e)

// ---------------------------------------------------------------------------
// tf32 mma + cp.async helpers
// ---------------------------------------------------------------------------
__device__ __forceinline__ float tf32r(float x) {
    unsigned u; asm("cvt.rna.tf32.f32 %0, %1;" : "=r"(u) : "f"(x));
    return __uint_as_float(u);
}
__device__ __forceinline__ void mma_tf32(float c[4],
    unsigned a0, unsigned a1, unsigned a2, unsigned a3,
    unsigned b0, unsigned b1)
{
    asm("mma.sync.aligned.m16n8k8.row.col.f32.tf32.tf32.f32 "
        "{%0,%1,%2,%3},{%4,%5,%6,%7},{%8,%9},{%0,%1,%2,%3};"
        : "+f"(c[0]), "+f"(c[1]), "+f"(c[2]), "+f"(c[3])
        : "r"(a0), "r"(a1), "r"(a2), "r"(a3), "r"(b0), "r"(b1));
}
__device__ __forceinline__ unsigned fu(float x) { return __float_as_uint(x); }
__device__ __forceinline__ float ex2(float x) {
    float r; asm("ex2.approx.f32 %0, %1;" : "=f"(r) : "f"(x)); return r;
}
__device__ __forceinline__ void split2(float v, unsigned &hi, unsigned &lo) {
    float h = tf32r(v);
    hi = fu(h);
    lo = fu(tf32r(v - h));
}
__device__ __forceinline__ unsigned smaddr(const void* p) {
    return (unsigned)__cvta_generic_to_shared(p);
}
__device__ __forceinline__ void cpa4(unsigned dst, const void* src, int valid) {
    asm volatile("cp.async.ca.shared.global [%0], [%1], 4, %2;"
                 :: "r"(dst), "l"(src), "r"(valid ? 4 : 0));
}
__device__ __forceinline__ void cpa16(unsigned dst, const void* src, int valid) {
    asm volatile("cp.async.cg.shared.global [%0], [%1], 16, %2;"
                 :: "r"(dst), "l"(src), "r"(valid ? 16 : 0));
}
#define CP_COMMIT asm volatile("cp.async.commit_group;")
#define CP_WAIT0  asm volatile("cp.async.wait_group 0;")

// Scratch (device globals: allocation-free per harness rules)
__device__ float g_qs[BB*HH*NN*DH];
__device__ float g_qt[BB*HH*NN];      // q time, NEGATED
__device__ float g_ks[BB*HH*NN*DH];
__device__ float g_kt[BB*HH*NN];
__device__ float g_vs[BB*HH*NN*DH];
__device__ float g_vt[BB*HH*NN];
__device__ float g_cat[ROWS*DD];      // [B*N][513]

// ---------------------------------------------------------------------------
// GEMM raw-staging layout: A [128 rows][k16] stride 20, B [k16][128 cols]
// stride 136. Fragment loads split hi/lo in registers (identical arithmetic
// to pre-split staging). Double-buffered via cp.async.
// ---------------------------------------------------------------------------
#define RA_STRIDE 20
#define RB_STRIDE 136
#define R_A 0
#define R_B (128*RA_STRIDE)
#define R_BUF (128*RA_STRIDE + 16*RB_STRIDE)   // 4736 floats / buffer
#define R_SMEM_FLOATS (2*R_BUF)                // 9472 floats = 37888 B
#define PJ_SMEM_FLOATS (128*132)               // Cs reuse needs 16896 floats
#define PJ_SMEM_BYTES  (PJ_SMEM_FLOATS*4)      // 67584
#define OP_SMEM_BYTES  (R_SMEM_FLOATS*4)       // 37888

// ---------------------------------------------------------------------------
// Kernel 1: QKV projection, tensor-core 3-pass tf32 split (register split),
// cp.async double-buffered.
// ---------------------------------------------------------------------------
__global__ __launch_bounds__(256, 2) void proj_kernel(
    const float* __restrict__ x,
    const float* __restrict__ Wq, const float* __restrict__ bq,
    const float* __restrict__ Wk, const float* __restrict__ bk,
    const float* __restrict__ Wv, const float* __restrict__ bv)
{
    extern __shared__ float psm[];

    const int tid  = threadIdx.x;
    const int lane = tid & 31;
    const int wid  = tid >> 5;
    const int lg   = lane >> 2;
    const int lt   = lane & 3;
    const int row0 = blockIdx.x * 128;
    const int gy = blockIdx.y;
    const int mat = gy >> 2;
    const int h0 = (gy & 3) * 2;

    const float* W    = (mat == 0) ? Wq : ((mat == 1) ? Wk : Wv);
    const float* bias = (mat == 0) ? bq : ((mat == 1) ? bk : bv);
    float* outs       = (mat == 0) ? g_qs : ((mat == 1) ? g_ks : g_vs);
    float* outt       = (mat == 0) ? g_qt : ((mat == 1) ? g_kt : g_vt);

    const int mb = (wid >> 2) * 64;
    const int nb = (wid & 3) * 32;

    // staging coordinates
    const int sa_r = tid >> 4, sa_k = tid & 15;          // + it*16 rows
    const int sb_k0 = tid >> 5, sb_c = (tid & 31) * 4;   // + 8 for second
    const int sb_h = h0 + (sb_c >> 6), sb_m = sb_c & 63;

    float acc[4][4][4] = {};

    // stage one k-slice (16 wide) into buffer bs
    auto stage = [&](int k0, int bs) {
        float* Ar = psm + bs * R_BUF + R_A;
        float* Br = psm + bs * R_BUF + R_B;
        #pragma unroll
        for (int it = 0; it < 8; it++) {
            int r = sa_r + it * 16;
            int kg = k0 + sa_k;
            int v = (kg < DD);
            cpa4(smaddr(&Ar[r * RA_STRIDE + sa_k]),
                 &x[(size_t)(row0 + r) * DD + (v ? kg : 0)], v);
        }
        #pragma unroll
        for (int it = 0; it < 2; it++) {
            int kk = sb_k0 + it * 8;
            int kg = k0 + kk;
            int v = (kg < DD);
            cpa16(smaddr(&Br[kk * RB_STRIDE + sb_c]),
                  &W[((size_t)sb_h * DD + (v ? kg : 0)) * DH + sb_m], v);
        }
    };

    stage(0, 0); CP_COMMIT;

    int buf = 0;
    #pragma unroll 1
    for (int k0 = 0; k0 < DD; k0 += 16, buf ^= 1) {
        CP_WAIT0;
        __syncthreads();
        if (k0 + 16 < DD) { stage(k0 + 16, buf ^ 1); CP_COMMIT; }

        const float* Ar = psm + buf * R_BUF + R_A;
        const float* Br = psm + buf * R_BUF + R_B;

        #pragma unroll
        for (int ks = 0; ks < 2; ks++) {
            unsigned bh_[4][2], bl_[4][2];
            #pragma unroll
            for (int ni = 0; ni < 4; ni++) {
                const float* bp = &Br[(ks * 8 + lt) * RB_STRIDE + nb + 8 * ni + lg];
                split2(bp[0],             bh_[ni][0], bl_[ni][0]);
                split2(bp[4 * RB_STRIDE], bh_[ni][1], bl_[ni][1]);
            }
            #pragma unroll
            for (int mi = 0; mi < 4; mi++) {
                const float* ap = &Ar[(mb + 16 * mi + lg) * RA_STRIDE + ks * 8 + lt];
                unsigned ah0, ah1, ah2, ah3, al0, al1, al2, al3;
                split2(ap[0],                  ah0, al0);
                split2(ap[8 * RA_STRIDE],      ah1, al1);
                split2(ap[4],                  ah2, al2);
                split2(ap[8 * RA_STRIDE + 4],  ah3, al3);
                #pragma unroll
                for (int ni = 0; ni < 4; ni++) {
                    mma_tf32(acc[mi][ni], ah0, ah1, ah2, ah3, bh_[ni][0], bh_[ni][1]);
                    mma_tf32(acc[mi][ni], ah0, ah1, ah2, ah3, bl_[ni][0], bl_[ni][1]);
                    mma_tf32(acc[mi][ni], al0, al1, al2, al3, bh_[ni][0], bh_[ni][1]);
                }
            }
        }
        __syncthreads();
    }

    // stage C to Cs[128][132] (reuses smem; all cp.async drained)
    float* Cs = psm;
    #pragma unroll
    for (int mi = 0; mi < 4; mi++) {
        #pragma unroll
        for (int ni = 0; ni < 4; ni++) {
            int row = mb + 16 * mi + lg;
            int col = nb + 8 * ni + 2 * lt;
            *(float2*)&Cs[row * 132 + col]       = make_float2(acc[mi][ni][0], acc[mi][ni][1]);
            *(float2*)&Cs[(row + 8) * 132 + col] = make_float2(acc[mi][ni][2], acc[mi][ni][3]);
        }
    }
    __syncthreads();

    // epilogue: one thread per (row, head)
    {
        int r = tid >> 1, hh = tid & 1;
        int h = h0 + hh;
        const float tsign = (mat == 0) ? -1.0f : 1.0f;
        float c[64];
        float ss = 0.f;
        #pragma unroll
        for (int j4 = 0; j4 < 16; j4++) {
            float4 cv = *(const float4*)&Cs[r * 132 + hh * 64 + j4 * 4];
            float4 bb = *(const float4*)&bias[h * DH + j4 * 4];
            float v0 = cv.x + bb.x, v1 = cv.y + bb.y;
            float v2 = cv.z + bb.z, v3 = cv.w + bb.w;
            c[j4 * 4 + 0] = v0; c[j4 * 4 + 1] = v1;
            c[j4 * 4 + 2] = v2; c[j4 * 4 + 3] = v3;
            ss += v0 * v0 + v1 * v1 + v2 * v2 + v3 * v3;
        }
        int g = row0 + r;
        int b = g >> 11, n = g & 2047;
        size_t bhn = (size_t)(b * HH + h) * NN + n;
        float* dst = &outs[bhn * DH];
        #pragma unroll
        for (int j4 = 0; j4 < 16; j4++)
            *(float4*)&dst[j4 * 4] = make_float4(c[j4*4], c[j4*4+1], c[j4*4+2], c[j4*4+3]);
        outt[bhn] = tsign * sqrtf(fmaxf(INV_K + ss, EPS_F));
    }
}

// ---------------------------------------------------------------------------
// Kernel 2: flash attention, tensor cores, NO online softmax (logits <= -1.25
// on the hyperboloid); ex2 at S-fragment store. UNCHANGED from R14 passing.
// ---------------------------------------------------------------------------
#define AT_QS   0
#define AT_KS   (128*68)
#define AT_VS   (2*128*68)
#define AT_PT   (3*128*68)
#define AT_QT   (AT_PT + 128*132)
#define ATT_SMEM_FLOATS (AT_QT + 5*128)
#define ATT_SMEM_BYTES  (ATT_SMEM_FLOATS * 4)

__global__ __launch_bounds__(256, 1) void attn_kernel()
{
    extern __shared__ float sm[];
    float* Qs    = sm + AT_QS;
    float* Ks    = sm + AT_KS;
    float* Vs    = sm + AT_VS;
    float* Pt    = sm + AT_PT;
    float* qts   = sm + AT_QT;
    float* kts   = qts + 128;
    float* vtime = kts + 128;
    float* lrow  = vtime + 128;
    float* otc   = lrow + 128;

    const int tid  = threadIdx.x;
    const int lane = tid & 31;
    const int wid  = tid >> 5;
    const int lg   = lane >> 2;
    const int lt   = lane & 3;
    const int bh = blockIdx.y;
    const int q0 = blockIdx.x * 128;
    const int h = bh & 7, b = bh >> 3;

    const int s_qb = (wid >> 2) * 64;
    const int s_kb = (wid & 3) * 32;
    const int p_mb = (wid >> 2) * 32;
    const int p_qb = (wid & 3) * 32;

    const float* qsb = g_qs + ((size_t)bh * NN + q0) * DH;
    const float* qtb = g_qt + (size_t)bh * NN + q0;
    #pragma unroll
    for (int it = 0; it < 8; it++) {
        int lin = tid + it * 256;
        int r = lin >> 4, c4 = lin & 15;
        float4 v = *(const float4*)&qsb[r * DH + c4 * 4];
        float* d = &Qs[r * 68 + c4 * 4];
        d[0] = tf32r(v.x * QSC); d[1] = tf32r(v.y * QSC);
        d[2] = tf32r(v.z * QSC); d[3] = tf32r(v.w * QSC);
    }
    if (tid < 128) {
        qts[tid] = qtb[tid] * QSC;
        lrow[tid] = 0.0f; otc[tid] = 0.0f;
    }

    float o[2][4][4] = {};

    const float* ksb = g_ks + (size_t)bh * NN * DH;
    const float* ktb = g_kt + (size_t)bh * NN;
    const float* vsb = g_vs + (size_t)bh * NN * DH;
    const float* vtb = g_vt + (size_t)bh * NN;

    #pragma unroll 1
    for (int kt = 0; kt < NN / 128; kt++) {
        __syncthreads();
        const float* kp_ = ksb + (size_t)kt * 128 * DH;
        const float* vp_ = vsb + (size_t)kt * 128 * DH;
        #pragma unroll
        for (int it = 0; it < 8; it++) {
            int lin = tid + it * 256;
            int r = lin >> 4, c4 = lin & 15;
            float4 kv = *(const float4*)&kp_[r * DH + c4 * 4];
            float* kd = &Ks[r * 68 + c4 * 4];
            kd[0] = tf32r(kv.x); kd[1] = tf32r(kv.y);
            kd[2] = tf32r(kv.z); kd[3] = tf32r(kv.w);
            float4 vv = *(const float4*)&vp_[r * DH + c4 * 4];
            float* vd = &Vs[r * 68 + c4 * 4];
            vd[0] = tf32r(vv.x); vd[1] = tf32r(vv.y);
            vd[2] = tf32r(vv.z); vd[3] = tf32r(vv.w);
        }
        if (tid < 128) {
            kts[tid]   = ktb[kt * 128 + tid];
            vtime[tid] = vtb[kt * 128 + tid];
        }
        __syncthreads();

        // ---- S phase: mma (log2 domain) + exact time fold + exp2 at store ----
        {
            float sc[4][4][4];
            #pragma unroll
            for (int mi = 0; mi < 4; mi++)
                #pragma unroll
                for (int ni = 0; ni < 4; ni++)
                    #pragma unroll
                    for (int r = 0; r < 4; r++) sc[mi][ni][r] = 0.0f;

            #pragma unroll
            for (int ks = 0; ks < 8; ks++) {
                unsigned a[4][4];
                #pragma unroll
                for (int mi = 0; mi < 4; mi++) {
                    const float* ap = &Qs[(s_qb + 16 * mi + lg) * 68 + ks * 8 + lt];
                    a[mi][0] = fu(ap[0]);
                    a[mi][1] = fu(ap[8 * 68]);
                    a[mi][2] = fu(ap[4]);
                    a[mi][3] = fu(ap[8 * 68 + 4]);
                }
                unsigned bf[4][2];
                #pragma unroll
                for (int ni = 0; ni < 4; ni++) {
                    const float* bp = &Ks[(s_kb + 8 * ni + lg) * 68 + ks * 8 + lt];
                    bf[ni][0] = fu(bp[0]);
                    bf[ni][1] = fu(bp[4]);
                }
                #pragma unroll
                for (int mi = 0; mi < 4; mi++)
                    #pragma unroll
                    for (int ni = 0; ni < 4; ni++)
                        mma_tf32(sc[mi][ni], a[mi][0], a[mi][1], a[mi][2], a[mi][3],
                                 bf[ni][0], bf[ni][1]);
            }

            #pragma unroll
            for (int mi = 0; mi < 4; mi++) {
                int qr = s_qb + 16 * mi + lg;
                float qt0 = qts[qr], qt8 = qts[qr + 8];
                #pragma unroll
                for (int ni = 0; ni < 4; ni++) {
                    int kc = s_kb + 8 * ni + 2 * lt;
                    float kt0 = kts[kc], kt1 = kts[kc + 1];
                    float p0 = ex2(fmaf(qt0, kt0, sc[mi][ni][0]));
                    float p1 = ex2(fmaf(qt0, kt1, sc[mi][ni][1]));
                    float p2 = ex2(fmaf(qt8, kt0, sc[mi][ni][2]));
                    float p3 = ex2(fmaf(qt8, kt1, sc[mi][ni][3]));
                    *(float2*)&Pt[qr * 132 + kc]       = make_float2(p0, p1);
                    *(float2*)&Pt[(qr + 8) * 132 + kc] = make_float2(p2, p3);
                }
            }
        }
        __syncthreads();

        // ---- row sums (l, time-component) in exact fp32; 2 threads/row ----
        {
            int r = tid >> 1, part = tid & 1;
            const float* prow = &Pt[r * 132 + part * 64];
            float sum = 0.f, tsum = 0.f;
            #pragma unroll
            for (int jf = 0; jf < 16; jf++) {
                float4 p = *(const float4*)&prow[jf * 4];
                sum += (p.x + p.y) + (p.z + p.w);
                int kk = part * 64 + jf * 4;
                tsum += p.x * vtime[kk] + p.y * vtime[kk + 1]
                      + p.z * vtime[kk + 2] + p.w * vtime[kk + 3];
            }
            sum  += __shfl_xor_sync(0xffffffffu, sum, 1);
            tsum += __shfl_xor_sync(0xffffffffu, tsum, 1);
            if (part == 0) {
                lrow[r] += sum;
                otc[r]  += tsum;
            }
        }

        // ---- PV phase: O^T += V^T . P^T via mma ----
        {
            #pragma unroll
            for (int ks = 0; ks < 16; ks++) {
                unsigned a[2][4];
                #pragma unroll
                for (int fi = 0; fi < 2; fi++) {
                    const float* ap = &Vs[(ks * 8 + lt) * 68 + p_mb + 16 * fi + lg];
                    a[fi][0] = fu(ap[0]);
                    a[fi][1] = fu(ap[8]);
                    a[fi][2] = fu(ap[4 * 68]);
                    a[fi][3] = fu(ap[4 * 68 + 8]);
                }
                unsigned bf[4][2];
                #pragma unroll
                for (int ni = 0; ni < 4; ni++) {
                    const float* bp = &Pt[(p_qb + 8 * ni + lg) * 132 + ks * 8 + lt];
                    bf[ni][0] = fu(bp[0]);
                    bf[ni][1] = fu(bp[4]);
                }
                #pragma unroll
                for (int fi = 0; fi < 2; fi++)
                    #pragma unroll
                    for (int ni = 0; ni < 4; ni++)
                        mma_tf32(o[fi][ni], a[fi][0], a[fi][1], a[fi][2], a[fi][3],
                                 bf[ni][0], bf[ni][1]);
            }
        }
    }
    __syncthreads();

    // ---- stage O^T into Pt as [q][dim] ----
    #pragma unroll
    for (int fi = 0; fi < 2; fi++) {
        #pragma unroll
        for (int ni = 0; ni < 4; ni++) {
            int mr = p_mb + 16 * fi + lg;
            int qc = p_qb + 8 * ni + 2 * lt;
            Pt[qc * 132 + mr]           = o[fi][ni][0];
            Pt[(qc + 1) * 132 + mr]     = o[fi][ni][1];
            Pt[qc * 132 + mr + 8]       = o[fi][ni][2];
            Pt[(qc + 1) * 132 + mr + 8] = o[fi][ni][3];
        }
    }
    __syncthreads();

    // ---- epilogue: normalize, Lorentz midpoint, head-concat (scalar stores) ----
    {
        int q = tid >> 1, half = tid & 1;
        float invl = 1.0f / lrow[q];
        const float* orow = &Pt[q * 132 + half * 32];
        float c[32];
        float ss = 0.f;
        #pragma unroll
        for (int jf = 0; jf < 8; jf++) {
            float4 p = *(const float4*)&orow[jf * 4];
            c[jf * 4 + 0] = p.x * invl; c[jf * 4 + 1] = p.y * invl;
            c[jf * 4 + 2] = p.z * invl; c[jf * 4 + 3] = p.w * invl;
            ss += c[jf*4]*c[jf*4] + c[jf*4+1]*c[jf*4+1]
                + c[jf*4+2]*c[jf*4+2] + c[jf*4+3]*c[jf*4+3];
        }
        ss += __shfl_xor_sync(0xffffffffu, ss, 1);
        float t = otc[q] * invl;
        float fac = rsqrtf(fmaxf(-K_CURV * (ss - t * t), EPS_F));
        float* dst = &g_cat[(size_t)(b * NN + q0 + q) * DD + 1 + h * DH + half * 32];
        #pragma unroll
        for (int j = 0; j < 32; j++) dst[j] = c[j] * fac;
    }
}

// ---------------------------------------------------------------------------
// Kernel 3/5: per-row time attach
// ---------------------------------------------------------------------------
__global__ void rowtime_kernel(float* outp, int which)
{
    float* buf = which ? g_cat : outp;
    int warp = (blockIdx.x * blockDim.x + threadIdx.x) >> 5;
    int lane = threadIdx.x & 31;
    if (warp >= ROWS) return;
    const float* row = buf + (size_t)warp * DD + 1;
    float s = 0.0f;
    #pragma unroll
    for (int c = lane; c < 512; c += 32) {
        float v = row[c];
        s += v * v;
    }
    #pragma unroll
    for (int off = 16; off; off >>= 1)
        s += __shfl_xor_sync(0xffffffffu, s, off);
    if (lane == 0) buf[(size_t)warp * DD] = sqrtf(fmaxf(INV_K + s, EPS_F));
}

// ---------------------------------------------------------------------------
// Kernel 4: output GEMM, register hi/lo split, cp.async double-buffered.
// ---------------------------------------------------------------------------
__global__ __launch_bounds__(256, 2) void outproj_kernel(
    const float* __restrict__ Wo, const float* __restrict__ bo,
    float* __restrict__ outp)
{
    extern __shared__ float osm[];

    const int tid  = threadIdx.x;
    const int lane = tid & 31;
    const int wid  = tid >> 5;
    const int lg   = lane >> 2;
    const int lt   = lane & 3;
    const int row0 = blockIdx.x * 128;
    const int col0 = blockIdx.y * 128;

    const int mb = (wid >> 2) * 64;
    const int nb = (wid & 3) * 32;

    const int sa_r = tid >> 4, sa_k = tid & 15;
    const int sb_k0 = tid >> 5, sb_c = (tid & 31) * 4;

    float acc[4][4][4] = {};

    auto stage = [&](int k0, int bs) {
        float* Ar = osm + bs * R_BUF + R_A;
        float* Br = osm + bs * R_BUF + R_B;
        #pragma unroll
        for (int it = 0; it < 8; it++) {
            int r = sa_r + it * 16;
            int kg = k0 + sa_k;
            int v = (kg < DD);
            cpa4(smaddr(&Ar[r * RA_STRIDE + sa_k]),
                 &g_cat[(size_t)(row0 + r) * DD + (v ? kg : 0)], v);
        }
        #pragma unroll
        for (int it = 0; it < 2; it++) {
            int kk = sb_k0 + it * 8;
            int kg = k0 + kk;
            int v = (kg < DD);
            cpa16(smaddr(&Br[kk * RB_STRIDE + sb_c]),
                  &Wo[(size_t)(v ? kg : 0) * 512 + col0 + sb_c], v);
        }
    };

    stage(0, 0); CP_COMMIT;

    int buf = 0;
    #pragma unroll 1
    for (int k0 = 0; k0 < DD; k0 += 16, buf ^= 1) {
        CP_WAIT0;
        __syncthreads();
        if (k0 + 16 < DD) { stage(k0 + 16, buf ^ 1); CP_COMMIT; }

        const float* Ar = osm + buf * R_BUF + R_A;
        const float* Br = osm + buf * R_BUF + R_B;

        #pragma unroll
        for (int ks = 0; ks < 2; ks++) {
            unsigned bh_[4][2], bl_[4][2];
            #pragma unroll
            for (int ni = 0; ni < 4; ni++) {
                const float* bp = &Br[(ks * 8 + lt) * RB_STRIDE + nb + 8 * ni + lg];
                split2(bp[0],             bh_[ni][0], bl_[ni][0]);
                split2(bp[4 * RB_STRIDE], bh_[ni][1], bl_[ni][1]);
            }
            #pragma unroll
            for (int mi = 0; mi < 4; mi++) {
                const float* ap = &Ar[(mb + 16 * mi + lg) * RA_STRIDE + ks * 8 + lt];
                unsigned ah0, ah1, ah2, ah3, al0, al1, al2, al3;
                split2(ap[0],                  ah0, al0);
                split2(ap[8 * RA_STRIDE],      ah1, al1);
                split2(ap[4],                  ah2, al2);
                split2(ap[8 * RA_STRIDE + 4],  ah3, al3);
                #pragma unroll
                for (int ni = 0; ni < 4; ni++) {
                    mma_tf32(acc[mi][ni], ah0, ah1, ah2, ah3, bh_[ni][0], bh_[ni][1]);
                    mma_tf32(acc[mi][ni], ah0, ah1, ah2, ah3, bl_[ni][0], bl_[ni][1]);
                    mma_tf32(acc[mi][ni], al0, al1, al2, al3, bh_[ni][0], bh_[ni][1]);
                }
            }
        }
        __syncthreads();
    }

    // epilogue: bias + scalar stores (output row stride 513 floats is odd)
    #pragma unroll
    for (int ni = 0; ni < 4; ni++) {
        int col = col0 + nb + 8 * ni + 2 * lt;
        float b0_ = bo[col], b1_ = bo[col + 1];
        #pragma unroll
        for (int mi = 0; mi < 4; mi++) {
            int row = row0 + mb + 16 * mi + lg;
            float* d0 = &outp[(size_t)row * DD + 1 + col];
            d0[0] = acc[mi][ni][0] + b0_;
            d0[1] = acc[mi][ni][1] + b1_;
            float* d1 = &outp[(size_t)(row + 8) * DD + 1 + col];
            d1[0] = acc[mi][ni][2] + b0_;
            d1[1] = acc[mi][ni][3] + b1_;
        }
    }
}

// ---------------------------------------------------------------------------
extern "C" void kernel_launch(void* const* d_in, const int* in_sizes, int n_in,
                              void* d_out, int out_size)
{
    const float* x  = (const float*)d_in[0];
    const float* Wq = (const float*)d_in[1];
    const float* bq = (const float*)d_in[2];
    const float* Wk = (const float*)d_in[3];
    const float* bk = (const float*)d_in[4];
    const float* Wv = (const float*)d_in[5];
    const float* bv = (const float*)d_in[6];
    const float* Wo = (const float*)d_in[7];
    const float* bo = (const float*)d_in[8];
    float* outp = (float*)d_out;

    cudaFuncSetAttribute(attn_kernel,
                         cudaFuncAttributeMaxDynamicSharedMemorySize,
                         ATT_SMEM_BYTES);
    cudaFuncSetAttribute(proj_kernel,
                         cudaFuncAttributeMaxDynamicSharedMemorySize,
                         PJ_SMEM_BYTES);
    cudaFuncSetAttribute(outproj_kernel,
                         cudaFuncAttributeMaxDynamicSharedMemorySize,
                         OP_SMEM_BYTES);

    proj_kernel<<<dim3(ROWS / 128, 12), 256, PJ_SMEM_BYTES>>>(x, Wq, bq, Wk, bk, Wv, bv);
    attn_kernel<<<dim3(NN / 128, BB * HH), 256, ATT_SMEM_BYTES>>>();
    rowtime_kernel<<<ROWS / 8, 256>>>(nullptr, 1);
    outproj_kernel<<<dim3(ROWS / 128, 4), 256, OP_SMEM_BYTES>>>(Wo, bo, outp);
    rowtime_kernel<<<ROWS / 8, 256>>>(outp, 0);
}

// round 16
// speedup vs baseline: 2.3472x; 1.0969x over previous
#include <cuda_runtime.h>
#include <math.h>

// Problem dims
#define BB   4
#define NN   2048
#define DD   513
#define HH   8
#define DH   64
#define ROWS (BB*NN)       // 8192

#define INV_K   10.0f
#define K_CURV  0.1f
#define EPS_F   1e-9f
#define SCALE_F 0.125f     // 1/sqrt(64)
#define QSC     (0.125f * 1.44269504088896f)   // SCALE * log2(e)

// ---------------------------------------------------------------------------
// tf32 mma + cp.async helpers
// ---------------------------------------------------------------------------
__device__ __forceinline__ float tf32r(float x) {
    unsigned u; asm("cvt.rna.tf32.f32 %0, %1;" : "=r"(u) : "f"(x));
    return __uint_as_float(u);
}
__device__ __forceinline__ void mma_tf32(float c[4],
    unsigned a0, unsigned a1, unsigned a2, unsigned a3,
    unsigned b0, unsigned b1)
{
    asm("mma.sync.aligned.m16n8k8.row.col.f32.tf32.tf32.f32 "
        "{%0,%1,%2,%3},{%4,%5,%6,%7},{%8,%9},{%0,%1,%2,%3};"
        : "+f"(c[0]), "+f"(c[1]), "+f"(c[2]), "+f"(c[3])
        : "r"(a0), "r"(a1), "r"(a2), "r"(a3), "r"(b0), "r"(b1));
}
__device__ __forceinline__ unsigned fu(float x) { return __float_as_uint(x); }
__device__ __forceinline__ float ex2(float x) {
    float r; asm("ex2.approx.f32 %0, %1;" : "=f"(r) : "f"(x)); return r;
}
__device__ __forceinline__ void split2(float v, unsigned &hi, unsigned &lo) {
    float h = tf32r(v);
    hi = fu(h);
    lo = fu(tf32r(v - h));
}
__device__ __forceinline__ unsigned smaddr(const void* p) {
    return (unsigned)__cvta_generic_to_shared(p);
}
__device__ __forceinline__ void cpa4(unsigned dst, const void* src, int valid) {
    asm volatile("cp.async.ca.shared.global [%0], [%1], 4, %2;"
                 :: "r"(dst), "l"(src), "r"(valid ? 4 : 0));
}
__device__ __forceinline__ void cpa16(unsigned dst, const void* src, int valid) {
    asm volatile("cp.async.cg.shared.global [%0], [%1], 16, %2;"
                 :: "r"(dst), "l"(src), "r"(valid ? 16 : 0));
}
#define CP_COMMIT asm volatile("cp.async.commit_group;")
#define CP_WAIT0  asm volatile("cp.async.wait_group 0;")

// Scratch (device globals: allocation-free per harness rules)
__device__ float g_qs[BB*HH*NN*DH];
__device__ float g_qt[BB*HH*NN];      // q time, NEGATED
__device__ float g_ks[BB*HH*NN*DH];
__device__ float g_kt[BB*HH*NN];
__device__ float g_vs[BB*HH*NN*DH];
__device__ float g_vt[BB*HH*NN];
__device__ float g_cat[ROWS*DD];      // [B*N][513]

// ---------------------------------------------------------------------------
// GEMM raw-staging layout: A [128 rows][k16] stride 20, B [k16][128 cols]
// stride 136. Double-buffered via cp.async; hi/lo split at fragment load.
// ---------------------------------------------------------------------------
#define RA_STRIDE 20
#define RB_STRIDE 136
#define R_A 0
#define R_B (128*RA_STRIDE)
#define R_BUF (128*RA_STRIDE + 16*RB_STRIDE)   // 4736 floats / buffer
#define R_SMEM_FLOATS (2*R_BUF)                // 9472 floats = 37888 B
#define PJ_SMEM_FLOATS (128*132)               // Cs reuse needs 16896 floats
#define PJ_SMEM_BYTES  (PJ_SMEM_FLOATS*4)      // 67584
#define OP_SMEM_BYTES  (R_SMEM_FLOATS*4)       // 37888

// ---------------------------------------------------------------------------
// Kernel 1: QKV projection, tensor cores, 2-pass tf32 (A split hi/lo,
// B single-rounded: adds ~2.4e-4 rms, inside the 1e-3 budget), cp.async
// double-buffered.
// ---------------------------------------------------------------------------
__global__ __launch_bounds__(256, 2) void proj_kernel(
    const float* __restrict__ x,
    const float* __restrict__ Wq, const float* __restrict__ bq,
    const float* __restrict__ Wk, const float* __restrict__ bk,
    const float* __restrict__ Wv, const float* __restrict__ bv)
{
    extern __shared__ float psm[];

    const int tid  = threadIdx.x;
    const int lane = tid & 31;
    const int wid  = tid >> 5;
    const int lg   = lane >> 2;
    const int lt   = lane & 3;
    const int row0 = blockIdx.x * 128;
    const int gy = blockIdx.y;
    const int mat = gy >> 2;
    const int h0 = (gy & 3) * 2;

    const float* W    = (mat == 0) ? Wq : ((mat == 1) ? Wk : Wv);
    const float* bias = (mat == 0) ? bq : ((mat == 1) ? bk : bv);
    float* outs       = (mat == 0) ? g_qs : ((mat == 1) ? g_ks : g_vs);
    float* outt       = (mat == 0) ? g_qt : ((mat == 1) ? g_kt : g_vt);

    const int mb = (wid >> 2) * 64;
    const int nb = (wid & 3) * 32;

    const int sa_r = tid >> 4, sa_k = tid & 15;
    const int sb_k0 = tid >> 5, sb_c = (tid & 31) * 4;
    const int sb_h = h0 + (sb_c >> 6), sb_m = sb_c & 63;

    float acc[4][4][4] = {};

    auto stage = [&](int k0, int bs) {
        float* Ar = psm + bs * R_BUF + R_A;
        float* Br = psm + bs * R_BUF + R_B;
        #pragma unroll
        for (int it = 0; it < 8; it++) {
            int r = sa_r + it * 16;
            int kg = k0 + sa_k;
            int v = (kg < DD);
            cpa4(smaddr(&Ar[r * RA_STRIDE + sa_k]),
                 &x[(size_t)(row0 + r) * DD + (v ? kg : 0)], v);
        }
        #pragma unroll
        for (int it = 0; it < 2; it++) {
            int kk = sb_k0 + it * 8;
            int kg = k0 + kk;
            int v = (kg < DD);
            cpa16(smaddr(&Br[kk * RB_STRIDE + sb_c]),
                  &W[((size_t)sb_h * DD + (v ? kg : 0)) * DH + sb_m], v);
        }
    };

    stage(0, 0); CP_COMMIT;

    int buf = 0;
    #pragma unroll 1
    for (int k0 = 0; k0 < DD; k0 += 16, buf ^= 1) {
        CP_WAIT0;
        __syncthreads();
        if (k0 + 16 < DD) { stage(k0 + 16, buf ^ 1); CP_COMMIT; }

        const float* Ar = psm + buf * R_BUF + R_A;
        const float* Br = psm + buf * R_BUF + R_B;

        #pragma unroll
        for (int ks = 0; ks < 2; ks++) {
            unsigned bh_[4][2];
            #pragma unroll
            for (int ni = 0; ni < 4; ni++) {
                const float* bp = &Br[(ks * 8 + lt) * RB_STRIDE + nb + 8 * ni + lg];
                bh_[ni][0] = fu(tf32r(bp[0]));
                bh_[ni][1] = fu(tf32r(bp[4 * RB_STRIDE]));
            }
            #pragma unroll
            for (int mi = 0; mi < 4; mi++) {
                const float* ap = &Ar[(mb + 16 * mi + lg) * RA_STRIDE + ks * 8 + lt];
                unsigned ah0, ah1, ah2, ah3, al0, al1, al2, al3;
                split2(ap[0],                  ah0, al0);
                split2(ap[8 * RA_STRIDE],      ah1, al1);
                split2(ap[4],                  ah2, al2);
                split2(ap[8 * RA_STRIDE + 4],  ah3, al3);
                #pragma unroll
                for (int ni = 0; ni < 4; ni++) {
                    mma_tf32(acc[mi][ni], ah0, ah1, ah2, ah3, bh_[ni][0], bh_[ni][1]);
                    mma_tf32(acc[mi][ni], al0, al1, al2, al3, bh_[ni][0], bh_[ni][1]);
                }
            }
        }
        __syncthreads();
    }

    // stage C to Cs[128][132] (reuses smem; all cp.async drained)
    float* Cs = psm;
    #pragma unroll
    for (int mi = 0; mi < 4; mi++) {
        #pragma unroll
        for (int ni = 0; ni < 4; ni++) {
            int row = mb + 16 * mi + lg;
            int col = nb + 8 * ni + 2 * lt;
            *(float2*)&Cs[row * 132 + col]       = make_float2(acc[mi][ni][0], acc[mi][ni][1]);
            *(float2*)&Cs[(row + 8) * 132 + col] = make_float2(acc[mi][ni][2], acc[mi][ni][3]);
        }
    }
    __syncthreads();

    // epilogue: one thread per (row, head)
    {
        int r = tid >> 1, hh = tid & 1;
        int h = h0 + hh;
        const float tsign = (mat == 0) ? -1.0f : 1.0f;
        float c[64];
        float ss = 0.f;
        #pragma unroll
        for (int j4 = 0; j4 < 16; j4++) {
            float4 cv = *(const float4*)&Cs[r * 132 + hh * 64 + j4 * 4];
            float4 bb = *(const float4*)&bias[h * DH + j4 * 4];
            float v0 = cv.x + bb.x, v1 = cv.y + bb.y;
            float v2 = cv.z + bb.z, v3 = cv.w + bb.w;
            c[j4 * 4 + 0] = v0; c[j4 * 4 + 1] = v1;
            c[j4 * 4 + 2] = v2; c[j4 * 4 + 3] = v3;
            ss += v0 * v0 + v1 * v1 + v2 * v2 + v3 * v3;
        }
        int g = row0 + r;
        int b = g >> 11, n = g & 2047;
        size_t bhn = (size_t)(b * HH + h) * NN + n;
        float* dst = &outs[bhn * DH];
        #pragma unroll
        for (int j4 = 0; j4 < 16; j4++)
            *(float4*)&dst[j4 * 4] = make_float4(c[j4*4], c[j4*4+1], c[j4*4+2], c[j4*4+3]);
        outt[bhn] = tsign * sqrtf(fmaxf(INV_K + ss, EPS_F));
    }
}

// ---------------------------------------------------------------------------
// Kernel 2: flash attention, tensor cores, NO online softmax (logits <= -1.25
// on the hyperboloid); ex2 at S-fragment store. Staging now float4 STS.
// ---------------------------------------------------------------------------
#define AT_QS   0
#define AT_KS   (128*68)
#define AT_VS   (2*128*68)
#define AT_PT   (3*128*68)
#define AT_QT   (AT_PT + 128*132)
#define ATT_SMEM_FLOATS (AT_QT + 5*128)
#define ATT_SMEM_BYTES  (ATT_SMEM_FLOATS * 4)

__global__ __launch_bounds__(256, 1) void attn_kernel()
{
    extern __shared__ float sm[];
    float* Qs    = sm + AT_QS;
    float* Ks    = sm + AT_KS;
    float* Vs    = sm + AT_VS;
    float* Pt    = sm + AT_PT;
    float* qts   = sm + AT_QT;
    float* kts   = qts + 128;
    float* vtime = kts + 128;
    float* lrow  = vtime + 128;
    float* otc   = lrow + 128;

    const int tid  = threadIdx.x;
    const int lane = tid & 31;
    const int wid  = tid >> 5;
    const int lg   = lane >> 2;
    const int lt   = lane & 3;
    const int bh = blockIdx.y;
    const int q0 = blockIdx.x * 128;
    const int h = bh & 7, b = bh >> 3;

    const int s_qb = (wid >> 2) * 64;
    const int s_kb = (wid & 3) * 32;
    const int p_mb = (wid >> 2) * 32;
    const int p_qb = (wid & 3) * 32;

    const float* qsb = g_qs + ((size_t)bh * NN + q0) * DH;
    const float* qtb = g_qt + (size_t)bh * NN + q0;
    #pragma unroll
    for (int it = 0; it < 8; it++) {
        int lin = tid + it * 256;
        int r = lin >> 4, c4 = lin & 15;
        float4 v = *(const float4*)&qsb[r * DH + c4 * 4];
        *(float4*)&Qs[r * 68 + c4 * 4] = make_float4(
            tf32r(v.x * QSC), tf32r(v.y * QSC), tf32r(v.z * QSC), tf32r(v.w * QSC));
    }
    if (tid < 128) {
        qts[tid] = qtb[tid] * QSC;
        lrow[tid] = 0.0f; otc[tid] = 0.0f;
    }

    float o[2][4][4] = {};

    const float* ksb = g_ks + (size_t)bh * NN * DH;
    const float* ktb = g_kt + (size_t)bh * NN;
    const float* vsb = g_vs + (size_t)bh * NN * DH;
    const float* vtb = g_vt + (size_t)bh * NN;

    #pragma unroll 1
    for (int kt = 0; kt < NN / 128; kt++) {
        __syncthreads();
        const float* kp_ = ksb + (size_t)kt * 128 * DH;
        const float* vp_ = vsb + (size_t)kt * 128 * DH;
        #pragma unroll
        for (int it = 0; it < 8; it++) {
            int lin = tid + it * 256;
            int r = lin >> 4, c4 = lin & 15;
            float4 kv = *(const float4*)&kp_[r * DH + c4 * 4];
            *(float4*)&Ks[r * 68 + c4 * 4] = make_float4(
                tf32r(kv.x), tf32r(kv.y), tf32r(kv.z), tf32r(kv.w));
            float4 vv = *(const float4*)&vp_[r * DH + c4 * 4];
            *(float4*)&Vs[r * 68 + c4 * 4] = make_float4(
                tf32r(vv.x), tf32r(vv.y), tf32r(vv.z), tf32r(vv.w));
        }
        if (tid < 128) {
            kts[tid]   = ktb[kt * 128 + tid];
            vtime[tid] = vtb[kt * 128 + tid];
        }
        __syncthreads();

        // ---- S phase: mma (log2 domain) + exact time fold + exp2 at store ----
        {
            float sc[4][4][4];
            #pragma unroll
            for (int mi = 0; mi < 4; mi++)
                #pragma unroll
                for (int ni = 0; ni < 4; ni++)
                    #pragma unroll
                    for (int r = 0; r < 4; r++) sc[mi][ni][r] = 0.0f;

            #pragma unroll
            for (int ks = 0; ks < 8; ks++) {
                unsigned a[4][4];
                #pragma unroll
                for (int mi = 0; mi < 4; mi++) {
                    const float* ap = &Qs[(s_qb + 16 * mi + lg) * 68 + ks * 8 + lt];
                    a[mi][0] = fu(ap[0]);
                    a[mi][1] = fu(ap[8 * 68]);
                    a[mi][2] = fu(ap[4]);
                    a[mi][3] = fu(ap[8 * 68 + 4]);
                }
                unsigned bf[4][2];
                #pragma unroll
                for (int ni = 0; ni < 4; ni++) {
                    const float* bp = &Ks[(s_kb + 8 * ni + lg) * 68 + ks * 8 + lt];
                    bf[ni][0] = fu(bp[0]);
                    bf[ni][1] = fu(bp[4]);
                }
                #pragma unroll
                for (int mi = 0; mi < 4; mi++)
                    #pragma unroll
                    for (int ni = 0; ni < 4; ni++)
                        mma_tf32(sc[mi][ni], a[mi][0], a[mi][1], a[mi][2], a[mi][3],
                                 bf[ni][0], bf[ni][1]);
            }

            #pragma unroll
            for (int mi = 0; mi < 4; mi++) {
                int qr = s_qb + 16 * mi + lg;
                float qt0 = qts[qr], qt8 = qts[qr + 8];
                #pragma unroll
                for (int ni = 0; ni < 4; ni++) {
                    int kc = s_kb + 8 * ni + 2 * lt;
                    float kt0 = kts[kc], kt1 = kts[kc + 1];
                    float p0 = ex2(fmaf(qt0, kt0, sc[mi][ni][0]));
                    float p1 = ex2(fmaf(qt0, kt1, sc[mi][ni][1]));
                    float p2 = ex2(fmaf(qt8, kt0, sc[mi][ni][2]));
                    float p3 = ex2(fmaf(qt8, kt1, sc[mi][ni][3]));
                    *(float2*)&Pt[qr * 132 + kc]       = make_float2(p0, p1);
                    *(float2*)&Pt[(qr + 8) * 132 + kc] = make_float2(p2, p3);
                }
            }
        }
        __syncthreads();

        // ---- row sums (l, time-component) in exact fp32; 2 threads/row ----
        {
            int r = tid >> 1, part = tid & 1;
            const float* prow = &Pt[r * 132 + part * 64];
            float sum = 0.f, tsum = 0.f;
            #pragma unroll
            for (int jf = 0; jf < 16; jf++) {
                float4 p = *(const float4*)&prow[jf * 4];
                sum += (p.x + p.y) + (p.z + p.w);
                int kk = part * 64 + jf * 4;
                tsum += p.x * vtime[kk] + p.y * vtime[kk + 1]
                      + p.z * vtime[kk + 2] + p.w * vtime[kk + 3];
            }
            sum  += __shfl_xor_sync(0xffffffffu, sum, 1);
            tsum += __shfl_xor_sync(0xffffffffu, tsum, 1);
            if (part == 0) {
                lrow[r] += sum;
                otc[r]  += tsum;
            }
        }

        // ---- PV phase: O^T += V^T . P^T via mma ----
        {
            #pragma unroll
            for (int ks = 0; ks < 16; ks++) {
                unsigned a[2][4];
                #pragma unroll
                for (int fi = 0; fi < 2; fi++) {
                    const float* ap = &Vs[(ks * 8 + lt) * 68 + p_mb + 16 * fi + lg];
                    a[fi][0] = fu(ap[0]);
                    a[fi][1] = fu(ap[8]);
                    a[fi][2] = fu(ap[4 * 68]);
                    a[fi][3] = fu(ap[4 * 68 + 8]);
                }
                unsigned bf[4][2];
                #pragma unroll
                for (int ni = 0; ni < 4; ni++) {
                    const float* bp = &Pt[(p_qb + 8 * ni + lg) * 132 + ks * 8 + lt];
                    bf[ni][0] = fu(bp[0]);
                    bf[ni][1] = fu(bp[4]);
                }
                #pragma unroll
                for (int fi = 0; fi < 2; fi++)
                    #pragma unroll
                    for (int ni = 0; ni < 4; ni++)
                        mma_tf32(o[fi][ni], a[fi][0], a[fi][1], a[fi][2], a[fi][3],
                                 bf[ni][0], bf[ni][1]);
            }
        }
    }
    __syncthreads();

    // ---- stage O^T into Pt as [q][dim] ----
    #pragma unroll
    for (int fi = 0; fi < 2; fi++) {
        #pragma unroll
        for (int ni = 0; ni < 4; ni++) {
            int mr = p_mb + 16 * fi + lg;
            int qc = p_qb + 8 * ni + 2 * lt;
            Pt[qc * 132 + mr]           = o[fi][ni][0];
            Pt[(qc + 1) * 132 + mr]     = o[fi][ni][1];
            Pt[qc * 132 + mr + 8]       = o[fi][ni][2];
            Pt[(qc + 1) * 132 + mr + 8] = o[fi][ni][3];
        }
    }
    __syncthreads();

    // ---- epilogue: normalize, Lorentz midpoint, head-concat (scalar stores) ----
    {
        int q = tid >> 1, half = tid & 1;
        float invl = 1.0f / lrow[q];
        const float* orow = &Pt[q * 132 + half * 32];
        float c[32];
        float ss = 0.f;
        #pragma unroll
        for (int jf = 0; jf < 8; jf++) {
            float4 p = *(const float4*)&orow[jf * 4];
            c[jf * 4 + 0] = p.x * invl; c[jf * 4 + 1] = p.y * invl;
            c[jf * 4 + 2] = p.z * invl; c[jf * 4 + 3] = p.w * invl;
            ss += c[jf*4]*c[jf*4] + c[jf*4+1]*c[jf*4+1]
                + c[jf*4+2]*c[jf*4+2] + c[jf*4+3]*c[jf*4+3];
        }
        ss += __shfl_xor_sync(0xffffffffu, ss, 1);
        float t = otc[q] * invl;
        float fac = rsqrtf(fmaxf(-K_CURV * (ss - t * t), EPS_F));
        float* dst = &g_cat[(size_t)(b * NN + q0 + q) * DD + 1 + h * DH + half * 32];
        #pragma unroll
        for (int j = 0; j < 32; j++) dst[j] = c[j] * fac;
    }
}

// ---------------------------------------------------------------------------
// Kernel 3/5: per-row time attach
// ---------------------------------------------------------------------------
__global__ void rowtime_kernel(float* outp, int which)
{
    float* buf = which ? g_cat : outp;
    int warp = (blockIdx.x * blockDim.x + threadIdx.x) >> 5;
    int lane = threadIdx.x & 31;
    if (warp >= ROWS) return;
    const float* row = buf + (size_t)warp * DD + 1;
    float s = 0.0f;
    #pragma unroll
    for (int c = lane; c < 512; c += 32) {
        float v = row[c];
        s += v * v;
    }
    #pragma unroll
    for (int off = 16; off; off >>= 1)
        s += __shfl_xor_sync(0xffffffffu, s, off);
    if (lane == 0) buf[(size_t)warp * DD] = sqrtf(fmaxf(INV_K + s, EPS_F));
}

// ---------------------------------------------------------------------------
// Kernel 4: output GEMM, 3-pass exact split (register split), cp.async
// double-buffered. (Kept exact: it writes the final output directly.)
// ---------------------------------------------------------------------------
__global__ __launch_bounds__(256, 2) void outproj_kernel(
    const float* __restrict__ Wo, const float* __restrict__ bo,
    float* __restrict__ outp)
{
    extern __shared__ float osm[];

    const int tid  = threadIdx.x;
    const int lane = tid & 31;
    const int wid  = tid >> 5;
    const int lg   = lane >> 2;
    const int lt   = lane & 3;
    const int row0 = blockIdx.x * 128;
    const int col0 = blockIdx.y * 128;

    const int mb = (wid >> 2) * 64;
    const int nb = (wid & 3) * 32;

    const int sa_r = tid >> 4, sa_k = tid & 15;
    const int sb_k0 = tid >> 5, sb_c = (tid & 31) * 4;

    float acc[4][4][4] = {};

    auto stage = [&](int k0, int bs) {
        float* Ar = osm + bs * R_BUF + R_A;
        float* Br = osm + bs * R_BUF + R_B;
        #pragma unroll
        for (int it = 0; it < 8; it++) {
            int r = sa_r + it * 16;
            int kg = k0 + sa_k;
            int v = (kg < DD);
            cpa4(smaddr(&Ar[r * RA_STRIDE + sa_k]),
                 &g_cat[(size_t)(row0 + r) * DD + (v ? kg : 0)], v);
        }
        #pragma unroll
        for (int it = 0; it < 2; it++) {
            int kk = sb_k0 + it * 8;
            int kg = k0 + kk;
            int v = (kg < DD);
            cpa16(smaddr(&Br[kk * RB_STRIDE + sb_c]),
                  &Wo[(size_t)(v ? kg : 0) * 512 + col0 + sb_c], v);
        }
    };

    stage(0, 0); CP_COMMIT;

    int buf = 0;
    #pragma unroll 1
    for (int k0 = 0; k0 < DD; k0 += 16, buf ^= 1) {
        CP_WAIT0;
        __syncthreads();
        if (k0 + 16 < DD) { stage(k0 + 16, buf ^ 1); CP_COMMIT; }

        const float* Ar = osm + buf * R_BUF + R_A;
        const float* Br = osm + buf * R_BUF + R_B;

        #pragma unroll
        for (int ks = 0; ks < 2; ks++) {
            unsigned bh_[4][2], bl_[4][2];
            #pragma unroll
            for (int ni = 0; ni < 4; ni++) {
                const float* bp = &Br[(ks * 8 + lt) * RB_STRIDE + nb + 8 * ni + lg];
                split2(bp[0],             bh_[ni][0], bl_[ni][0]);
                split2(bp[4 * RB_STRIDE], bh_[ni][1], bl_[ni][1]);
            }
            #pragma unroll
            for (int mi = 0; mi < 4; mi++) {
                const float* ap = &Ar[(mb + 16 * mi + lg) * RA_STRIDE + ks * 8 + lt];
                unsigned ah0, ah1, ah2, ah3, al0, al1, al2, al3;
                split2(ap[0],                  ah0, al0);
                split2(ap[8 * RA_STRIDE],      ah1, al1);
                split2(ap[4],                  ah2, al2);
                split2(ap[8 * RA_STRIDE + 4],  ah3, al3);
                #pragma unroll
                for (int ni = 0; ni < 4; ni++) {
                    mma_tf32(acc[mi][ni], ah0, ah1, ah2, ah3, bh_[ni][0], bh_[ni][1]);
                    mma_tf32(acc[mi][ni], ah0, ah1, ah2, ah3, bl_[ni][0], bl_[ni][1]);
                    mma_tf32(acc[mi][ni], al0, al1, al2, al3, bh_[ni][0], bh_[ni][1]);
                }
            }
        }
        __syncthreads();
    }

    // epilogue: bias + scalar stores (output row stride 513 floats is odd)
    #pragma unroll
    for (int ni = 0; ni < 4; ni++) {
        int col = col0 + nb + 8 * ni + 2 * lt;
        float b0_ = bo[col], b1_ = bo[col + 1];
        #pragma unroll
        for (int mi = 0; mi < 4; mi++) {
            int row = row0 + mb + 16 * mi + lg;
            float* d0 = &outp[(size_t)row * DD + 1 + col];
            d0[0] = acc[mi][ni][0] + b0_;
            d0[1] = acc[mi][ni][1] + b1_;
            float* d1 = &outp[(size_t)(row + 8) * DD + 1 + col];
            d1[0] = acc[mi][ni][2] + b0_;
            d1[1] = acc[mi][ni][3] + b1_;
        }
    }
}

// ---------------------------------------------------------------------------
extern "C" void kernel_launch(void* const* d_in, const int* in_sizes, int n_in,
                              void* d_out, int out_size)
{
    const float* x  = (const float*)d_in[0];
    const float* Wq = (const float*)d_in[1];
    const float* bq = (const float*)d_in[2];
    const float* Wk = (const float*)d_in[3];
    const float* bk = (const float*)d_in[4];
    const float* Wv = (const float*)d_in[5];
    const float* bv = (const float*)d_in[6];
    const float* Wo = (const float*)d_in[7];
    const float* bo = (const float*)d_in[8];
    float* outp = (float*)d_out;

    cudaFuncSetAttribute(attn_kernel,
                         cudaFuncAttributeMaxDynamicSharedMemorySize,
                         ATT_SMEM_BYTES);
    cudaFuncSetAttribute(proj_kernel,
                         cudaFuncAttributeMaxDynamicSharedMemorySize,
                         PJ_SMEM_BYTES);
    cudaFuncSetAttribute(outproj_kernel,
                         cudaFuncAttributeMaxDynamicSharedMemorySize,
                         OP_SMEM_BYTES);

    proj_kernel<<<dim3(ROWS / 128, 12), 256, PJ_SMEM_BYTES>>>(x, Wq, bq, Wk, bk, Wv, bv);
    attn_kernel<<<dim3(NN / 128, BB * HH), 256, ATT_SMEM_BYTES>>>();
    rowtime_kernel<<<ROWS / 8, 256>>>(nullptr, 1);
    outproj_kernel<<<dim3(ROWS / 128, 4), 256, OP_SMEM_BYTES>>>(Wo, bo, outp);
    rowtime_kernel<<<ROWS / 8, 256>>>(outp, 0);
}

// round 17
// speedup vs baseline: 2.3767x; 1.0125x over previous
#include <cuda_runtime.h>
#include <math.h>

// Problem dims
#define BB   4
#define NN   2048
#define DD   513
#define HH   8
#define DH   64
#define ROWS (BB*NN)       // 8192

#define INV_K   10.0f
#define K_CURV  0.1f
#define EPS_F   1e-9f
#define SCALE_F 0.125f     // 1/sqrt(64)
#define QSC     (0.125f * 1.44269504088896f)   // SCALE * log2(e)

// ---------------------------------------------------------------------------
// tf32 mma + cp.async helpers
// ---------------------------------------------------------------------------
__device__ __forceinline__ float tf32r(float x) {
    unsigned u; asm("cvt.rna.tf32.f32 %0, %1;" : "=r"(u) : "f"(x));
    return __uint_as_float(u);
}
__device__ __forceinline__ void mma_tf32(float c[4],
    unsigned a0, unsigned a1, unsigned a2, unsigned a3,
    unsigned b0, unsigned b1)
{
    asm("mma.sync.aligned.m16n8k8.row.col.f32.tf32.tf32.f32 "
        "{%0,%1,%2,%3},{%4,%5,%6,%7},{%8,%9},{%0,%1,%2,%3};"
        : "+f"(c[0]), "+f"(c[1]), "+f"(c[2]), "+f"(c[3])
        : "r"(a0), "r"(a1), "r"(a2), "r"(a3), "r"(b0), "r"(b1));
}
__device__ __forceinline__ unsigned fu(float x) { return __float_as_uint(x); }
__device__ __forceinline__ float ex2(float x) {
    float r; asm("ex2.approx.f32 %0, %1;" : "=f"(r) : "f"(x)); return r;
}
__device__ __forceinline__ void split2(float v, unsigned &hi, unsigned &lo) {
    float h = tf32r(v);
    hi = fu(h);
    lo = fu(tf32r(v - h));
}
__device__ __forceinline__ unsigned smaddr(const void* p) {
    return (unsigned)__cvta_generic_to_shared(p);
}
__device__ __forceinline__ void cpa4(unsigned dst, const void* src, int valid) {
    asm volatile("cp.async.ca.shared.global [%0], [%1], 4, %2;"
                 :: "r"(dst), "l"(src), "r"(valid ? 4 : 0));
}
__device__ __forceinline__ void cpa16(unsigned dst, const void* src, int valid) {
    asm volatile("cp.async.cg.shared.global [%0], [%1], 16, %2;"
                 :: "r"(dst), "l"(src), "r"(valid ? 16 : 0));
}
#define CP_COMMIT asm volatile("cp.async.commit_group;")
#define CP_WAIT0  asm volatile("cp.async.wait_group 0;")

// Scratch (device globals: allocation-free per harness rules)
__device__ float g_qs[BB*HH*NN*DH];
__device__ float g_qt[BB*HH*NN];      // q time, NEGATED
__device__ float g_ks[BB*HH*NN*DH];
__device__ float g_kt[BB*HH*NN];
__device__ float g_vs[BB*HH*NN*DH];
__device__ float g_vt[BB*HH*NN];
__device__ float g_cat[ROWS*DD];      // [B*N][513]

// ---------------------------------------------------------------------------
// GEMM raw-staging layout: A [128 rows][k16] stride 20, B [k16][128 cols]
// stride 136. Double-buffered via cp.async; hi/lo split at fragment load.
// ---------------------------------------------------------------------------
#define RA_STRIDE 20
#define RB_STRIDE 136
#define R_A 0
#define R_B (128*RA_STRIDE)
#define R_BUF (128*RA_STRIDE + 16*RB_STRIDE)   // 4736 floats / buffer
#define R_SMEM_FLOATS (2*R_BUF)                // 9472 floats = 37888 B
#define PJ_SMEM_FLOATS (128*132)               // Cs reuse needs 16896 floats
#define PJ_SMEM_BYTES  (PJ_SMEM_FLOATS*4)      // 67584
#define OP_SMEM_BYTES  (R_SMEM_FLOATS*4)       // 37888

// ---------------------------------------------------------------------------
// Kernel 1: QKV projection, tensor cores, 2-pass tf32 (A split hi/lo, B
// single-rounded), cp.async double-buffered, PASS-MAJOR mma ordering so
// dependent mmas on an accumulator are 16 issues apart.
// ---------------------------------------------------------------------------
__global__ __launch_bounds__(256, 2) void proj_kernel(
    const float* __restrict__ x,
    const float* __restrict__ Wq, const float* __restrict__ bq,
    const float* __restrict__ Wk, const float* __restrict__ bk,
    const float* __restrict__ Wv, const float* __restrict__ bv)
{
    extern __shared__ float psm[];

    const int tid  = threadIdx.x;
    const int lane = tid & 31;
    const int wid  = tid >> 5;
    const int lg   = lane >> 2;
    const int lt   = lane & 3;
    const int row0 = blockIdx.x * 128;
    const int gy = blockIdx.y;
    const int mat = gy >> 2;
    const int h0 = (gy & 3) * 2;

    const float* W    = (mat == 0) ? Wq : ((mat == 1) ? Wk : Wv);
    const float* bias = (mat == 0) ? bq : ((mat == 1) ? bk : bv);
    float* outs       = (mat == 0) ? g_qs : ((mat == 1) ? g_ks : g_vs);
    float* outt       = (mat == 0) ? g_qt : ((mat == 1) ? g_kt : g_vt);

    const int mb = (wid >> 2) * 64;
    const int nb = (wid & 3) * 32;

    const int sa_r = tid >> 4, sa_k = tid & 15;
    const int sb_k0 = tid >> 5, sb_c = (tid & 31) * 4;
    const int sb_h = h0 + (sb_c >> 6), sb_m = sb_c & 63;

    float acc[4][4][4] = {};

    auto stage = [&](int k0, int bs) {
        float* Ar = psm + bs * R_BUF + R_A;
        float* Br = psm + bs * R_BUF + R_B;
        #pragma unroll
        for (int it = 0; it < 8; it++) {
            int r = sa_r + it * 16;
            int kg = k0 + sa_k;
            int v = (kg < DD);
            cpa4(smaddr(&Ar[r * RA_STRIDE + sa_k]),
                 &x[(size_t)(row0 + r) * DD + (v ? kg : 0)], v);
        }
        #pragma unroll
        for (int it = 0; it < 2; it++) {
            int kk = sb_k0 + it * 8;
            int kg = k0 + kk;
            int v = (kg < DD);
            cpa16(smaddr(&Br[kk * RB_STRIDE + sb_c]),
                  &W[((size_t)sb_h * DD + (v ? kg : 0)) * DH + sb_m], v);
        }
    };

    stage(0, 0); CP_COMMIT;

    int buf = 0;
    #pragma unroll 1
    for (int k0 = 0; k0 < DD; k0 += 16, buf ^= 1) {
        CP_WAIT0;
        __syncthreads();
        if (k0 + 16 < DD) { stage(k0 + 16, buf ^ 1); CP_COMMIT; }

        const float* Ar = psm + buf * R_BUF + R_A;
        const float* Br = psm + buf * R_BUF + R_B;

        #pragma unroll
        for (int ks = 0; ks < 2; ks++) {
            unsigned bh_[4][2];
            #pragma unroll
            for (int ni = 0; ni < 4; ni++) {
                const float* bp = &Br[(ks * 8 + lt) * RB_STRIDE + nb + 8 * ni + lg];
                bh_[ni][0] = fu(tf32r(bp[0]));
                bh_[ni][1] = fu(tf32r(bp[4 * RB_STRIDE]));
            }
            unsigned ah[4][4], al[4][4];
            #pragma unroll
            for (int mi = 0; mi < 4; mi++) {
                const float* ap = &Ar[(mb + 16 * mi + lg) * RA_STRIDE + ks * 8 + lt];
                split2(ap[0],                  ah[mi][0], al[mi][0]);
                split2(ap[8 * RA_STRIDE],      ah[mi][1], al[mi][1]);
                split2(ap[4],                  ah[mi][2], al[mi][2]);
                split2(ap[8 * RA_STRIDE + 4],  ah[mi][3], al[mi][3]);
            }
            // pass-major: dependent mmas on each acc are 16 issues apart
            #pragma unroll
            for (int mi = 0; mi < 4; mi++)
                #pragma unroll
                for (int ni = 0; ni < 4; ni++)
                    mma_tf32(acc[mi][ni], ah[mi][0], ah[mi][1], ah[mi][2], ah[mi][3],
                             bh_[ni][0], bh_[ni][1]);
            #pragma unroll
            for (int mi = 0; mi < 4; mi++)
                #pragma unroll
                for (int ni = 0; ni < 4; ni++)
                    mma_tf32(acc[mi][ni], al[mi][0], al[mi][1], al[mi][2], al[mi][3],
                             bh_[ni][0], bh_[ni][1]);
        }
        __syncthreads();
    }

    // stage C to Cs[128][132] (reuses smem; all cp.async drained)
    float* Cs = psm;
    #pragma unroll
    for (int mi = 0; mi < 4; mi++) {
        #pragma unroll
        for (int ni = 0; ni < 4; ni++) {
            int row = mb + 16 * mi + lg;
            int col = nb + 8 * ni + 2 * lt;
            *(float2*)&Cs[row * 132 + col]       = make_float2(acc[mi][ni][0], acc[mi][ni][1]);
            *(float2*)&Cs[(row + 8) * 132 + col] = make_float2(acc[mi][ni][2], acc[mi][ni][3]);
        }
    }
    __syncthreads();

    // epilogue: one thread per (row, head)
    {
        int r = tid >> 1, hh = tid & 1;
        int h = h0 + hh;
        const float tsign = (mat == 0) ? -1.0f : 1.0f;
        float c[64];
        float ss = 0.f;
        #pragma unroll
        for (int j4 = 0; j4 < 16; j4++) {
            float4 cv = *(const float4*)&Cs[r * 132 + hh * 64 + j4 * 4];
            float4 bb = *(const float4*)&bias[h * DH + j4 * 4];
            float v0 = cv.x + bb.x, v1 = cv.y + bb.y;
            float v2 = cv.z + bb.z, v3 = cv.w + bb.w;
            c[j4 * 4 + 0] = v0; c[j4 * 4 + 1] = v1;
            c[j4 * 4 + 2] = v2; c[j4 * 4 + 3] = v3;
            ss += v0 * v0 + v1 * v1 + v2 * v2 + v3 * v3;
        }
        int g = row0 + r;
        int b = g >> 11, n = g & 2047;
        size_t bhn = (size_t)(b * HH + h) * NN + n;
        float* dst = &outs[bhn * DH];
        #pragma unroll
        for (int j4 = 0; j4 < 16; j4++)
            *(float4*)&dst[j4 * 4] = make_float4(c[j4*4], c[j4*4+1], c[j4*4+2], c[j4*4+3]);
        outt[bhn] = tsign * sqrtf(fmaxf(INV_K + ss, EPS_F));
    }
}

// ---------------------------------------------------------------------------
// Kernel 2: flash attention, tensor cores, NO online softmax (logits <= -1.25
// on the hyperboloid); ex2 at S-fragment store. UNCHANGED from R16 passing.
// ---------------------------------------------------------------------------
#define AT_QS   0
#define AT_KS   (128*68)
#define AT_VS   (2*128*68)
#define AT_PT   (3*128*68)
#define AT_QT   (AT_PT + 128*132)
#define ATT_SMEM_FLOATS (AT_QT + 5*128)
#define ATT_SMEM_BYTES  (ATT_SMEM_FLOATS * 4)

__global__ __launch_bounds__(256, 1) void attn_kernel()
{
    extern __shared__ float sm[];
    float* Qs    = sm + AT_QS;
    float* Ks    = sm + AT_KS;
    float* Vs    = sm + AT_VS;
    float* Pt    = sm + AT_PT;
    float* qts   = sm + AT_QT;
    float* kts   = qts + 128;
    float* vtime = kts + 128;
    float* lrow  = vtime + 128;
    float* otc   = lrow + 128;

    const int tid  = threadIdx.x;
    const int lane = tid & 31;
    const int wid  = tid >> 5;
    const int lg   = lane >> 2;
    const int lt   = lane & 3;
    const int bh = blockIdx.y;
    const int q0 = blockIdx.x * 128;
    const int h = bh & 7, b = bh >> 3;

    const int s_qb = (wid >> 2) * 64;
    const int s_kb = (wid & 3) * 32;
    const int p_mb = (wid >> 2) * 32;
    const int p_qb = (wid & 3) * 32;

    const float* qsb = g_qs + ((size_t)bh * NN + q0) * DH;
    const float* qtb = g_qt + (size_t)bh * NN + q0;
    #pragma unroll
    for (int it = 0; it < 8; it++) {
        int lin = tid + it * 256;
        int r = lin >> 4, c4 = lin & 15;
        float4 v = *(const float4*)&qsb[r * DH + c4 * 4];
        *(float4*)&Qs[r * 68 + c4 * 4] = make_float4(
            tf32r(v.x * QSC), tf32r(v.y * QSC), tf32r(v.z * QSC), tf32r(v.w * QSC));
    }
    if (tid < 128) {
        qts[tid] = qtb[tid] * QSC;
        lrow[tid] = 0.0f; otc[tid] = 0.0f;
    }

    float o[2][4][4] = {};

    const float* ksb = g_ks + (size_t)bh * NN * DH;
    const float* ktb = g_kt + (size_t)bh * NN;
    const float* vsb = g_vs + (size_t)bh * NN * DH;
    const float* vtb = g_vt + (size_t)bh * NN;

    #pragma unroll 1
    for (int kt = 0; kt < NN / 128; kt++) {
        __syncthreads();
        const float* kp_ = ksb + (size_t)kt * 128 * DH;
        const float* vp_ = vsb + (size_t)kt * 128 * DH;
        #pragma unroll
        for (int it = 0; it < 8; it++) {
            int lin = tid + it * 256;
            int r = lin >> 4, c4 = lin & 15;
            float4 kv = *(const float4*)&kp_[r * DH + c4 * 4];
            *(float4*)&Ks[r * 68 + c4 * 4] = make_float4(
                tf32r(kv.x), tf32r(kv.y), tf32r(kv.z), tf32r(kv.w));
            float4 vv = *(const float4*)&vp_[r * DH + c4 * 4];
            *(float4*)&Vs[r * 68 + c4 * 4] = make_float4(
                tf32r(vv.x), tf32r(vv.y), tf32r(vv.z), tf32r(vv.w));
        }
        if (tid < 128) {
            kts[tid]   = ktb[kt * 128 + tid];
            vtime[tid] = vtb[kt * 128 + tid];
        }
        __syncthreads();

        // ---- S phase: mma (log2 domain) + exact time fold + exp2 at store ----
        {
            float sc[4][4][4];
            #pragma unroll
            for (int mi = 0; mi < 4; mi++)
                #pragma unroll
                for (int ni = 0; ni < 4; ni++)
                    #pragma unroll
                    for (int r = 0; r < 4; r++) sc[mi][ni][r] = 0.0f;

            #pragma unroll
            for (int ks = 0; ks < 8; ks++) {
                unsigned a[4][4];
                #pragma unroll
                for (int mi = 0; mi < 4; mi++) {
                    const float* ap = &Qs[(s_qb + 16 * mi + lg) * 68 + ks * 8 + lt];
                    a[mi][0] = fu(ap[0]);
                    a[mi][1] = fu(ap[8 * 68]);
                    a[mi][2] = fu(ap[4]);
                    a[mi][3] = fu(ap[8 * 68 + 4]);
                }
                unsigned bf[4][2];
                #pragma unroll
                for (int ni = 0; ni < 4; ni++) {
                    const float* bp = &Ks[(s_kb + 8 * ni + lg) * 68 + ks * 8 + lt];
                    bf[ni][0] = fu(bp[0]);
                    bf[ni][1] = fu(bp[4]);
                }
                #pragma unroll
                for (int mi = 0; mi < 4; mi++)
                    #pragma unroll
                    for (int ni = 0; ni < 4; ni++)
                        mma_tf32(sc[mi][ni], a[mi][0], a[mi][1], a[mi][2], a[mi][3],
                                 bf[ni][0], bf[ni][1]);
            }

            #pragma unroll
            for (int mi = 0; mi < 4; mi++) {
                int qr = s_qb + 16 * mi + lg;
                float qt0 = qts[qr], qt8 = qts[qr + 8];
                #pragma unroll
                for (int ni = 0; ni < 4; ni++) {
                    int kc = s_kb + 8 * ni + 2 * lt;
                    float kt0 = kts[kc], kt1 = kts[kc + 1];
                    float p0 = ex2(fmaf(qt0, kt0, sc[mi][ni][0]));
                    float p1 = ex2(fmaf(qt0, kt1, sc[mi][ni][1]));
                    float p2 = ex2(fmaf(qt8, kt0, sc[mi][ni][2]));
                    float p3 = ex2(fmaf(qt8, kt1, sc[mi][ni][3]));
                    *(float2*)&Pt[qr * 132 + kc]       = make_float2(p0, p1);
                    *(float2*)&Pt[(qr + 8) * 132 + kc] = make_float2(p2, p3);
                }
            }
        }
        __syncthreads();

        // ---- row sums (l, time-component) in exact fp32; 2 threads/row ----
        {
            int r = tid >> 1, part = tid & 1;
            const float* prow = &Pt[r * 132 + part * 64];
            float sum = 0.f, tsum = 0.f;
            #pragma unroll
            for (int jf = 0; jf < 16; jf++) {
                float4 p = *(const float4*)&prow[jf * 4];
                sum += (p.x + p.y) + (p.z + p.w);
                int kk = part * 64 + jf * 4;
                tsum += p.x * vtime[kk] + p.y * vtime[kk + 1]
                      + p.z * vtime[kk + 2] + p.w * vtime[kk + 3];
            }
            sum  += __shfl_xor_sync(0xffffffffu, sum, 1);
            tsum += __shfl_xor_sync(0xffffffffu, tsum, 1);
            if (part == 0) {
                lrow[r] += sum;
                otc[r]  += tsum;
            }
        }

        // ---- PV phase: O^T += V^T . P^T via mma ----
        {
            #pragma unroll
            for (int ks = 0; ks < 16; ks++) {
                unsigned a[2][4];
                #pragma unroll
                for (int fi = 0; fi < 2; fi++) {
                    const float* ap = &Vs[(ks * 8 + lt) * 68 + p_mb + 16 * fi + lg];
                    a[fi][0] = fu(ap[0]);
                    a[fi][1] = fu(ap[8]);
                    a[fi][2] = fu(ap[4 * 68]);
                    a[fi][3] = fu(ap[4 * 68 + 8]);
                }
                unsigned bf[4][2];
                #pragma unroll
                for (int ni = 0; ni < 4; ni++) {
                    const float* bp = &Pt[(p_qb + 8 * ni + lg) * 132 + ks * 8 + lt];
                    bf[ni][0] = fu(bp[0]);
                    bf[ni][1] = fu(bp[4]);
                }
                #pragma unroll
                for (int fi = 0; fi < 2; fi++)
                    #pragma unroll
                    for (int ni = 0; ni < 4; ni++)
                        mma_tf32(o[fi][ni], a[fi][0], a[fi][1], a[fi][2], a[fi][3],
                                 bf[ni][0], bf[ni][1]);
            }
        }
    }
    __syncthreads();

    // ---- stage O^T into Pt as [q][dim] ----
    #pragma unroll
    for (int fi = 0; fi < 2; fi++) {
        #pragma unroll
        for (int ni = 0; ni < 4; ni++) {
            int mr = p_mb + 16 * fi + lg;
            int qc = p_qb + 8 * ni + 2 * lt;
            Pt[qc * 132 + mr]           = o[fi][ni][0];
            Pt[(qc + 1) * 132 + mr]     = o[fi][ni][1];
            Pt[qc * 132 + mr + 8]       = o[fi][ni][2];
            Pt[(qc + 1) * 132 + mr + 8] = o[fi][ni][3];
        }
    }
    __syncthreads();

    // ---- epilogue: normalize, Lorentz midpoint, head-concat (scalar stores) ----
    {
        int q = tid >> 1, half = tid & 1;
        float invl = 1.0f / lrow[q];
        const float* orow = &Pt[q * 132 + half * 32];
        float c[32];
        float ss = 0.f;
        #pragma unroll
        for (int jf = 0; jf < 8; jf++) {
            float4 p = *(const float4*)&orow[jf * 4];
            c[jf * 4 + 0] = p.x * invl; c[jf * 4 + 1] = p.y * invl;
            c[jf * 4 + 2] = p.z * invl; c[jf * 4 + 3] = p.w * invl;
            ss += c[jf*4]*c[jf*4] + c[jf*4+1]*c[jf*4+1]
                + c[jf*4+2]*c[jf*4+2] + c[jf*4+3]*c[jf*4+3];
        }
        ss += __shfl_xor_sync(0xffffffffu, ss, 1);
        float t = otc[q] * invl;
        float fac = rsqrtf(fmaxf(-K_CURV * (ss - t * t), EPS_F));
        float* dst = &g_cat[(size_t)(b * NN + q0 + q) * DD + 1 + h * DH + half * 32];
        #pragma unroll
        for (int j = 0; j < 32; j++) dst[j] = c[j] * fac;
    }
}

// ---------------------------------------------------------------------------
// Kernel 3/5: per-row time attach
// ---------------------------------------------------------------------------
__global__ void rowtime_kernel(float* outp, int which)
{
    float* buf = which ? g_cat : outp;
    int warp = (blockIdx.x * blockDim.x + threadIdx.x) >> 5;
    int lane = threadIdx.x & 31;
    if (warp >= ROWS) return;
    const float* row = buf + (size_t)warp * DD + 1;
    float s = 0.0f;
    #pragma unroll
    for (int c = lane; c < 512; c += 32) {
        float v = row[c];
        s += v * v;
    }
    #pragma unroll
    for (int off = 16; off; off >>= 1)
        s += __shfl_xor_sync(0xffffffffu, s, off);
    if (lane == 0) buf[(size_t)warp * DD] = sqrtf(fmaxf(INV_K + s, EPS_F));
}

// ---------------------------------------------------------------------------
// Kernel 4: output GEMM, 2-pass tf32 (A split, B single-rounded), cp.async
// double-buffered, pass-major mma ordering.
// ---------------------------------------------------------------------------
__global__ __launch_bounds__(256, 2) void outproj_kernel(
    const float* __restrict__ Wo, const float* __restrict__ bo,
    float* __restrict__ outp)
{
    extern __shared__ float osm[];

    const int tid  = threadIdx.x;
    const int lane = tid & 31;
    const int wid  = tid >> 5;
    const int lg   = lane >> 2;
    const int lt   = lane & 3;
    const int row0 = blockIdx.x * 128;
    const int col0 = blockIdx.y * 128;

    const int mb = (wid >> 2) * 64;
    const int nb = (wid & 3) * 32;

    const int sa_r = tid >> 4, sa_k = tid & 15;
    const int sb_k0 = tid >> 5, sb_c = (tid & 31) * 4;

    float acc[4][4][4] = {};

    auto stage = [&](int k0, int bs) {
        float* Ar = osm + bs * R_BUF + R_A;
        float* Br = osm + bs * R_BUF + R_B;
        #pragma unroll
        for (int it = 0; it < 8; it++) {
            int r = sa_r + it * 16;
            int kg = k0 + sa_k;
            int v = (kg < DD);
            cpa4(smaddr(&Ar[r * RA_STRIDE + sa_k]),
                 &g_cat[(size_t)(row0 + r) * DD + (v ? kg : 0)], v);
        }
        #pragma unroll
        for (int it = 0; it < 2; it++) {
            int kk = sb_k0 + it * 8;
            int kg = k0 + kk;
            int v = (kg < DD);
            cpa16(smaddr(&Br[kk * RB_STRIDE + sb_c]),
                  &Wo[(size_t)(v ? kg : 0) * 512 + col0 + sb_c], v);
        }
    };

    stage(0, 0); CP_COMMIT;

    int buf = 0;
    #pragma unroll 1
    for (int k0 = 0; k0 < DD; k0 += 16, buf ^= 1) {
        CP_WAIT0;
        __syncthreads();
        if (k0 + 16 < DD) { stage(k0 + 16, buf ^ 1); CP_COMMIT; }

        const float* Ar = osm + buf * R_BUF + R_A;
        const float* Br = osm + buf * R_BUF + R_B;

        #pragma unroll
        for (int ks = 0; ks < 2; ks++) {
            unsigned bh_[4][2];
            #pragma unroll
            for (int ni = 0; ni < 4; ni++) {
                const float* bp = &Br[(ks * 8 + lt) * RB_STRIDE + nb + 8 * ni + lg];
                bh_[ni][0] = fu(tf32r(bp[0]));
                bh_[ni][1] = fu(tf32r(bp[4 * RB_STRIDE]));
            }
            unsigned ah[4][4], al[4][4];
            #pragma unroll
            for (int mi = 0; mi < 4; mi++) {
                const float* ap = &Ar[(mb + 16 * mi + lg) * RA_STRIDE + ks * 8 + lt];
                split2(ap[0],                  ah[mi][0], al[mi][0]);
                split2(ap[8 * RA_STRIDE],      ah[mi][1], al[mi][1]);
                split2(ap[4],                  ah[mi][2], al[mi][2]);
                split2(ap[8 * RA_STRIDE + 4],  ah[mi][3], al[mi][3]);
            }
            #pragma unroll
            for (int mi = 0; mi < 4; mi++)
                #pragma unroll
                for (int ni = 0; ni < 4; ni++)
                    mma_tf32(acc[mi][ni], ah[mi][0], ah[mi][1], ah[mi][2], ah[mi][3],
                             bh_[ni][0], bh_[ni][1]);
            #pragma unroll
            for (int mi = 0; mi < 4; mi++)
                #pragma unroll
                for (int ni = 0; ni < 4; ni++)
                    mma_tf32(acc[mi][ni], al[mi][0], al[mi][1], al[mi][2], al[mi][3],
                             bh_[ni][0], bh_[ni][1]);
        }
        __syncthreads();
    }

    // epilogue: bias + scalar stores (output row stride 513 floats is odd)
    #pragma unroll
    for (int ni = 0; ni < 4; ni++) {
        int col = col0 + nb + 8 * ni + 2 * lt;
        float b0_ = bo[col], b1_ = bo[col + 1];
        #pragma unroll
        for (int mi = 0; mi < 4; mi++) {
            int row = row0 + mb + 16 * mi + lg;
            float* d0 = &outp[(size_t)row * DD + 1 + col];
            d0[0] = acc[mi][ni][0] + b0_;
            d0[1] = acc[mi][ni][1] + b1_;
            float* d1 = &outp[(size_t)(row + 8) * DD + 1 + col];
            d1[0] = acc[mi][ni][2] + b0_;
            d1[1] = acc[mi][ni][3] + b1_;
        }
    }
}

// ---------------------------------------------------------------------------
extern "C" void kernel_launch(void* const* d_in, const int* in_sizes, int n_in,
                              void* d_out, int out_size)
{
    const float* x  = (const float*)d_in[0];
    const float* Wq = (const float*)d_in[1];
    const float* bq = (const float*)d_in[2];
    const float* Wk = (const float*)d_in[3];
    const float* bk = (const float*)d_in[4];
    const float* Wv = (const float*)d_in[5];
    const float* bv = (const float*)d_in[6];
    const float* Wo = (const float*)d_in[7];
    const float* bo = (const float*)d_in[8];
    float* outp = (float*)d_out;

    cudaFuncSetAttribute(attn_kernel,
                         cudaFuncAttributeMaxDynamicSharedMemorySize,
                         ATT_SMEM_BYTES);
    cudaFuncSetAttribute(proj_kernel,
                         cudaFuncAttributeMaxDynamicSharedMemorySize,
                         PJ_SMEM_BYTES);
    cudaFuncSetAttribute(outproj_kernel,
                         cudaFuncAttributeMaxDynamicSharedMemorySize,
                         OP_SMEM_BYTES);

    proj_kernel<<<dim3(ROWS / 128, 12), 256, PJ_SMEM_BYTES>>>(x, Wq, bq, Wk, bk, Wv, bv);
    attn_kernel<<<dim3(NN / 128, BB * HH), 256, ATT_SMEM_BYTES>>>();
    rowtime_kernel<<<ROWS / 8, 256>>>(nullptr, 1);
    outproj_kernel<<<dim3(ROWS / 128, 4), 256, OP_SMEM_BYTES>>>(Wo, bo, outp);
    rowtime_kernel<<<ROWS / 8, 256>>>(outp, 0);
}